// round 1
// baseline (speedup 1.0000x reference)
#include <cuda_runtime.h>
#include <cstdint>

#define BB 4
#define NN 2048
#define KK 32
#define CIN0 259
#define L0 128
#define L1C 128
#define L2C 256
#define PTOT (BB*NN*KK)   /* 262144 */
#define EPSV 1e-5f
#define SLOPE 0.01f

// ---------------- scratch (device globals; no allocation allowed) ----------------
__device__ float g_A[BB*NN*L0];      // 4 MB  : W0p@pos2 + W0f2@feature2, [b][j][c]
__device__ float g_D[BB*NN*L0];      // 4 MB  : W0f1@feature1 - W0p@pos1, [b][n][c]
__device__ float g_y1[(size_t)PTOT*L1C]; // 134 MB : layer1 pre-BN output, [p][c]
__device__ float g_mx[BB*NN*L2C];    // 8 MB  : max_k y2, [b][n][o]
__device__ float g_mn[BB*NN*L2C];    // 8 MB  : min_k y2
__device__ float g_s0[2*L0];         // per-channel sum / sumsq
__device__ float g_s1[2*L1C];
__device__ float g_s2[2*L2C];
__device__ float g_ab0[2*L0];        // per-channel affine a, c  (BN folded)
__device__ float g_ab1[2*L1C];
__device__ float g_ab2[2*L2C];

__global__ void k_zero() {
    int t = threadIdx.x;           // 512 threads
    if (t < 2*L0)  g_s0[t] = 0.f;
    if (t < 2*L1C) g_s1[t] = 0.f;
    g_s2[t] = 0.f;
}

// ---------------- layer-0 factorization: A and D ----------------
// A[b,j,o] = sum_{d<3} W0[o,d]*pos2[b,d,j] + sum_{c<128} W0[o,3+c]*f2[b,c,j]
// D[b,n,o] = sum_{c<128} W0[o,131+c]*f1[b,c,n] - sum_{d<3} W0[o,d]*pos1[b,d,n]
__global__ void __launch_bounds__(128) k_prep(
        const float* __restrict__ pos1, const float* __restrict__ pos2,
        const float* __restrict__ f1,   const float* __restrict__ f2,
        const float* __restrict__ W0) {
    __shared__ float s_in[131*16];
    int blk = blockIdx.x;
    int b  = blk / (NN/16);
    int j0 = (blk % (NN/16)) * 16;
    int tid = threadIdx.x;     // = output channel o
    const float* w = W0 + tid*CIN0;

    // ---- pass 1: A (inputs pos2 / feature2) ----
    for (int i = tid; i < 131*16; i += 128) {
        int c = i >> 4, jl = i & 15;
        float v = (c < 3) ? pos2[(b*3 + c)*NN + j0 + jl]
                          : f2[(b*128 + (c-3))*NN + j0 + jl];
        s_in[c*16 + jl] = v;
    }
    __syncthreads();
    {
        float4 acc[4];
        #pragma unroll
        for (int q = 0; q < 4; q++) acc[q] = make_float4(0.f,0.f,0.f,0.f);
        for (int c = 0; c < 131; c++) {
            float wv = w[c];
            const float4* r = (const float4*)&s_in[c*16];
            #pragma unroll
            for (int q = 0; q < 4; q++) {
                float4 rv = r[q];
                acc[q].x = fmaf(wv, rv.x, acc[q].x);
                acc[q].y = fmaf(wv, rv.y, acc[q].y);
                acc[q].z = fmaf(wv, rv.z, acc[q].z);
                acc[q].w = fmaf(wv, rv.w, acc[q].w);
            }
        }
        const float* af = (const float*)acc;
        #pragma unroll
        for (int pt = 0; pt < 16; pt++)
            g_A[((b*NN + j0 + pt) << 7) + tid] = af[pt];
    }
    __syncthreads();

    // ---- pass 2: D (inputs -pos1 / feature1) ----
    for (int i = tid; i < 131*16; i += 128) {
        int c = i >> 4, jl = i & 15;
        float v = (c < 3) ? -pos1[(b*3 + c)*NN + j0 + jl]
                          : f1[(b*128 + (c-3))*NN + j0 + jl];
        s_in[c*16 + jl] = v;
    }
    __syncthreads();
    {
        float4 acc[4];
        #pragma unroll
        for (int q = 0; q < 4; q++) acc[q] = make_float4(0.f,0.f,0.f,0.f);
        for (int c = 0; c < 131; c++) {
            float wv = (c < 3) ? w[c] : w[128 + c];   // 131+(c-3)
            const float4* r = (const float4*)&s_in[c*16];
            #pragma unroll
            for (int q = 0; q < 4; q++) {
                float4 rv = r[q];
                acc[q].x = fmaf(wv, rv.x, acc[q].x);
                acc[q].y = fmaf(wv, rv.y, acc[q].y);
                acc[q].z = fmaf(wv, rv.z, acc[q].z);
                acc[q].w = fmaf(wv, rv.w, acc[q].w);
            }
        }
        const float* af = (const float*)acc;
        #pragma unroll
        for (int pt = 0; pt < 16; pt++)
            g_D[((b*NN + j0 + pt) << 7) + tid] = af[pt];
    }
}

// ---------------- stats of y0 = A[idx] + D (y0 never stored) ----------------
__global__ void __launch_bounds__(128) k_stats0(const int* __restrict__ idxp) {
    __shared__ int s_idx[128];
    int tid = threadIdx.x;     // = channel c
    int pbase = blockIdx.x * 128;
    s_idx[tid] = idxp[pbase + tid];
    __syncthreads();
    float s = 0.f, ss = 0.f;
    #pragma unroll 4
    for (int i = 0; i < 128; i++) {
        int p = pbase + i;
        int arow = ((p >> 16) * NN + s_idx[i]) << 7;
        int drow = (p >> 5) << 7;
        float y = g_A[arow + tid] + g_D[drow + tid];
        s += y; ss = fmaf(y, y, ss);
    }
    atomicAdd(&g_s0[tid], s);
    atomicAdd(&g_s0[L0 + tid], ss);
}

// ---------------- finalize BN affine: a = g*rsqrt(var+eps), c = b - mean*a ----------------
__global__ void k_fin(int layer, const float* __restrict__ gamma,
                      const float* __restrict__ beta) {
    const float* sums; float* ab; int nc;
    if (layer == 0)      { sums = g_s0; ab = g_ab0; nc = L0;  }
    else if (layer == 1) { sums = g_s1; ab = g_ab1; nc = L1C; }
    else                 { sums = g_s2; ab = g_ab2; nc = L2C; }
    int t = threadIdx.x;
    if (t < nc) {
        const float invc = 1.0f / (float)PTOT;
        float mean = sums[t] * invc;
        float var  = sums[nc + t] * invc - mean*mean;
        float a = gamma[t] * rsqrtf(var + EPSV);
        ab[t]      = a;
        ab[nc + t] = beta[t] - mean * a;
    }
}

// ---------------- layer 1: y1 = W1 @ lrelu(a0*(A[idx]+D)+c0), + stats(y1) ----------------
static const int SMEM_L1 = (128*128 + 128*65 + 4*128) * 4 + 64*4;
__global__ void __launch_bounds__(256, 2) k_l1(const int* __restrict__ idxp,
                                               const float* __restrict__ W1) {
    extern __shared__ float sm[];
    float* sW    = sm;               // 128*128, transposed: sW[c*128+o]
    float* sU    = sW + 128*128;     // 128*65 : sU[c*65+p]
    float* s_sum = sU + 128*65;      // 128
    float* s_ss  = s_sum + 128;      // 128
    float* s_a   = s_ss + 128;       // 128
    float* s_c   = s_a + 128;        // 128
    int*   s_ar  = (int*)(s_c + 128);// 64 A-row bases

    int tid = threadIdx.x;
    int pbase = blockIdx.x * 64;

    for (int i = tid; i < 128*128; i += 256) {
        int o = i >> 7, c = i & 127;
        sW[c*128 + o] = W1[i];
    }
    if (tid < 128) {
        s_a[tid] = g_ab0[tid];  s_c[tid] = g_ab0[128 + tid];
        s_sum[tid] = 0.f;       s_ss[tid] = 0.f;
    }
    if (tid < 64) {
        int p = pbase + tid;
        s_ar[tid] = ((p >> 16) * NN + idxp[p]) << 7;
    }
    __syncthreads();

    int drow0 = (pbase >> 5) << 7;
    for (int i = tid; i < 64*128; i += 256) {
        int pl = i >> 7, c = i & 127;
        float av = g_A[s_ar[pl] + c];
        float dv = g_D[drow0 + ((pl >> 5) << 7) + c];
        float y = fmaf(s_a[c], av + dv, s_c[c]);
        sU[c*65 + pl] = (y > 0.f) ? y : SLOPE * y;
    }
    __syncthreads();

    int tx = tid & 15, ty = tid >> 4;
    int o0 = ty * 8;
    float acc[8][4];
    #pragma unroll
    for (int i = 0; i < 8; i++)
        #pragma unroll
        for (int q = 0; q < 4; q++) acc[i][q] = 0.f;

    #pragma unroll 4
    for (int c = 0; c < 128; c++) {
        float w[8];
        *(float4*)&w[0] = *(const float4*)&sW[c*128 + o0];
        *(float4*)&w[4] = *(const float4*)&sW[c*128 + o0 + 4];
        float u[4];
        #pragma unroll
        for (int q = 0; q < 4; q++) u[q] = sU[c*65 + tx + 16*q];
        #pragma unroll
        for (int i = 0; i < 8; i++)
            #pragma unroll
            for (int q = 0; q < 4; q++)
                acc[i][q] = fmaf(w[i], u[q], acc[i][q]);
    }

    // per-thread stats partials, reduce via smem atomics
    #pragma unroll
    for (int i = 0; i < 8; i++) {
        float sp = 0.f, ssp = 0.f;
        #pragma unroll
        for (int q = 0; q < 4; q++) { float v = acc[i][q]; sp += v; ssp = fmaf(v, v, ssp); }
        atomicAdd(&s_sum[o0 + i], sp);
        atomicAdd(&s_ss[o0 + i], ssp);
    }
    __syncthreads();   // stats done; sW free for reuse

    if (tid < 128) {
        atomicAdd(&g_s1[tid],       s_sum[tid]);
        atomicAdd(&g_s1[128 + tid], s_ss[tid]);
    }

    float* sOut = sW;  // 64*129 <= 128*128
    #pragma unroll
    for (int i = 0; i < 8; i++)
        #pragma unroll
        for (int q = 0; q < 4; q++)
            sOut[(tx + 16*q)*129 + o0 + i] = acc[i][q];
    __syncthreads();

    float* yg = g_y1 + (size_t)pbase * 128;
    for (int i = tid; i < 64*128; i += 256) {
        int pl = i >> 7, o = i & 127;
        yg[i] = sOut[pl*129 + o];
    }
}

// ---------------- layer 2: y2 = W2 @ lrelu(a1*y1+c1); stats + max/min over K ----------------
static const int SMEM_L2 = (128*256 + 128*65 + 2*128) * 4;
__global__ void __launch_bounds__(512, 1) k_l2(const float* __restrict__ W2) {
    extern __shared__ float sm[];
    float* sW  = sm;             // 128*256, transposed: sW[c*256+o]
    float* sV  = sW + 128*256;   // 128*65
    float* s_a = sV + 128*65;    // 128
    float* s_c = s_a + 128;      // 128

    int tid = threadIdx.x;
    int pbase = blockIdx.x * 64;

    for (int i = tid; i < 128*256; i += 512) {
        int o = i >> 7, c = i & 127;
        sW[c*256 + o] = W2[i];
    }
    if (tid < 128) { s_a[tid] = g_ab1[tid]; s_c[tid] = g_ab1[128 + tid]; }
    __syncthreads();

    const float* yg = g_y1 + (size_t)pbase * 128;
    for (int i = tid; i < 64*128; i += 512) {
        int pl = i >> 7, c = i & 127;
        float y = fmaf(s_a[c], yg[i], s_c[c]);
        sV[c*65 + pl] = (y > 0.f) ? y : SLOPE * y;
    }
    __syncthreads();

    int tx = tid & 31, ty = tid >> 5;
    int o0 = ty * 16;
    float acc[16][2];
    #pragma unroll
    for (int i = 0; i < 16; i++) { acc[i][0] = 0.f; acc[i][1] = 0.f; }

    #pragma unroll 4
    for (int c = 0; c < 128; c++) {
        float w[16];
        #pragma unroll
        for (int q = 0; q < 4; q++)
            *(float4*)&w[4*q] = *(const float4*)&sW[c*256 + o0 + 4*q];
        float u0 = sV[c*65 + tx];
        float u1 = sV[c*65 + tx + 32];
        #pragma unroll
        for (int i = 0; i < 16; i++) {
            acc[i][0] = fmaf(w[i], u0, acc[i][0]);
            acc[i][1] = fmaf(w[i], u1, acc[i][1]);
        }
    }
    __syncthreads();   // done reading sW/sV

    float* sOut = sW;  // 64*257 <= 128*256
    #pragma unroll
    for (int i = 0; i < 16; i++) {
        sOut[tx*257 + o0 + i]        = acc[i][0];
        sOut[(tx + 32)*257 + o0 + i] = acc[i][1];
    }
    __syncthreads();

    // stats + max/min per (n, channel): tile = 2 full n-groups of K=32
    int o = tid & 255, half = tid >> 8;
    float s = 0.f, ss = 0.f, mx = -3.4e38f, mn = 3.4e38f;
    #pragma unroll 4
    for (int k = 0; k < 32; k++) {
        float v = sOut[(half*32 + k)*257 + o];
        s += v; ss = fmaf(v, v, ss);
        mx = fmaxf(mx, v); mn = fminf(mn, v);
    }
    int bn = (pbase >> 5) + half;
    g_mx[bn*256 + o] = mx;
    g_mn[bn*256 + o] = mn;
    atomicAdd(&g_s2[o],       s);
    atomicAdd(&g_s2[256 + o], ss);
}

// ---------------- final: transpose [b][n][o] -> [b][o][n], apply BN2 + lrelu via max/min ----------------
static const int SMEM_OUT = 2 * 64 * 257 * 4;
__global__ void __launch_bounds__(256) k_out(float* __restrict__ out) {
    extern __shared__ float sm[];
    float* sMx = sm;             // [nl][o], pad 257
    float* sMn = sm + 64*257;
    int tid = threadIdx.x;
    int b  = blockIdx.x >> 5;          // N/64 = 32 tiles per batch
    int n0 = (blockIdx.x & 31) * 64;

    for (int i = tid; i < 64*256; i += 256) {
        int nl = i >> 8, o = i & 255;
        int g = (b*NN + n0 + nl)*256 + o;
        sMx[nl*257 + o] = g_mx[g];
        sMn[nl*257 + o] = g_mn[g];
    }
    __syncthreads();
    for (int i = tid; i < 64*256; i += 256) {
        int o = i >> 6, nl = i & 63;
        float a = g_ab2[o], c = g_ab2[256 + o];
        float z = (a >= 0.f) ? sMx[nl*257 + o] : sMn[nl*257 + o];
        float y = fmaf(a, z, c);
        out[(b*256 + o)*NN + n0 + nl] = (y > 0.f) ? y : SLOPE * y;
    }
}

// ---------------- launch ----------------
extern "C" void kernel_launch(void* const* d_in, const int* in_sizes, int n_in,
                              void* d_out, int out_size) {
    const float* pos1 = (const float*)d_in[0];
    const float* pos2 = (const float*)d_in[1];
    const float* f1   = (const float*)d_in[2];
    const float* f2   = (const float*)d_in[3];
    const int*   idxp = (const int*)d_in[4];
    const float* W0 = (const float*)d_in[5];
    const float* g0 = (const float*)d_in[6];
    const float* b0 = (const float*)d_in[7];
    const float* W1 = (const float*)d_in[8];
    const float* g1 = (const float*)d_in[9];
    const float* b1 = (const float*)d_in[10];
    const float* W2 = (const float*)d_in[11];
    const float* g2 = (const float*)d_in[12];
    const float* b2 = (const float*)d_in[13];

    cudaFuncSetAttribute(k_l1,  cudaFuncAttributeMaxDynamicSharedMemorySize, SMEM_L1);
    cudaFuncSetAttribute(k_l2,  cudaFuncAttributeMaxDynamicSharedMemorySize, SMEM_L2);
    cudaFuncSetAttribute(k_out, cudaFuncAttributeMaxDynamicSharedMemorySize, SMEM_OUT);

    float* outp = (float*)d_out;
    int featOff = out_size - BB*L2C*NN;   // expect 24576 (pos1) or 0
    if (featOff < 0) featOff = 0;

    k_zero<<<1, 512>>>();
    k_prep<<<BB*NN/16, 128>>>(pos1, pos2, f1, f2, W0);
    k_stats0<<<PTOT/128, 128>>>(idxp);
    k_fin<<<1, 256>>>(0, g0, b0);
    k_l1<<<PTOT/64, 256, SMEM_L1>>>(idxp, W1);
    k_fin<<<1, 256>>>(1, g1, b1);
    k_l2<<<PTOT/64, 512, SMEM_L2>>>(W2);
    k_fin<<<1, 256>>>(2, g2, b2);

    if (featOff > 0)
        cudaMemcpyAsync(d_out, pos1, (size_t)featOff * sizeof(float),
                        cudaMemcpyDeviceToDevice, 0);
    k_out<<<BB*(NN/64), 256, SMEM_OUT>>>(outp + featOff);
}

// round 4
// speedup vs baseline: 2.9575x; 2.9575x over previous
#include <cuda_runtime.h>
#include <cuda_fp16.h>
#include <cstdint>

#define BB 4
#define NN 2048
#define KK 32
#define L0 128
#define L1C 128
#define L2C 256
#define PTOT (BB*NN*KK)   /* 262144 */
#define EPSV 1e-5f
#define SLOPE 0.01f

// ---------------- scratch ----------------
__device__ float g_A[BB*NN*L0];          // 4 MB
__device__ float g_D[BB*NN*L0];          // 4 MB
__device__ float g_y1[(size_t)PTOT*L1C]; // 134 MB
__device__ float g_mx[BB*NN*L2C];        // 8 MB
__device__ float g_mn[BB*NN*L2C];        // 8 MB
__device__ float g_s0[2*L0];
__device__ float g_s1[2*L1C];
__device__ float g_s2[2*L2C];
__device__ uint32_t g_W1h2[128*64];      // W1 split, half2 packed
__device__ uint32_t g_W1l2[128*64];
__device__ uint32_t g_W2h2[256*64];
__device__ uint32_t g_W2l2[256*64];

// ---------------- helpers ----------------
__device__ __forceinline__ uint32_t smem_u32(const void* p) {
    uint32_t a;
    asm("{ .reg .u64 t; cvta.to.shared.u64 t, %1; cvt.u32.u64 %0, t; }" : "=r"(a) : "l"(p));
    return a;
}
__device__ __forceinline__ void ldmx4(uint32_t* r, uint32_t addr) {
    asm volatile("ldmatrix.sync.aligned.m8n8.x4.shared.b16 {%0,%1,%2,%3}, [%4];"
                 : "=r"(r[0]), "=r"(r[1]), "=r"(r[2]), "=r"(r[3]) : "r"(addr));
}
__device__ __forceinline__ void mma16816(float* d, const uint32_t* a, const uint32_t* b) {
    asm volatile(
        "mma.sync.aligned.m16n8k16.row.col.f32.f16.f16.f32 "
        "{%0,%1,%2,%3}, {%4,%5,%6,%7}, {%8,%9}, {%0,%1,%2,%3};"
        : "+f"(d[0]), "+f"(d[1]), "+f"(d[2]), "+f"(d[3])
        : "r"(a[0]), "r"(a[1]), "r"(a[2]), "r"(a[3]), "r"(b[0]), "r"(b[1]));
}
__device__ __forceinline__ void hsplit2(float x, float y, uint32_t& hi, uint32_t& lo) {
    __half hx = __float2half_rn(x), hy = __float2half_rn(y);
    __half lx = __float2half_rn(x - __half2float(hx));
    __half ly = __float2half_rn(y - __half2float(hy));
    __half2 h2 = __halves2half2(hx, hy), l2 = __halves2half2(lx, ly);
    hi = *(uint32_t*)&h2; lo = *(uint32_t*)&l2;
}
// tile rows are 256B (128 halves); XOR-swizzle 16B chunks within each 128B octant
__device__ __forceinline__ uint32_t sw_pair(int row, int c2) {   // c2 = half2 index 0..63
    return (uint32_t)row*256u + (uint32_t)(((c2 >> 2) ^ (row & 7)) << 4) + (uint32_t)((c2 & 3) << 2);
}
__device__ __forceinline__ uint32_t sw_chunk(int row, int cl) {  // cl = 16B chunk 0..15
    return (uint32_t)row*256u + (uint32_t)(((cl ^ (row & 7)) & 15) << 4);
}

// ---------------- k_zero ----------------
__global__ void k_zero() {
    int t = threadIdx.x;   // 512
    if (t < 2*L0)  g_s0[t] = 0.f;
    if (t < 2*L1C) g_s1[t] = 0.f;
    g_s2[t] = 0.f;
}

// ---------------- k_wsplit: W1/W2 -> half2 hi/lo ----------------
__global__ void k_wsplit(const float* __restrict__ W1, const float* __restrict__ W2) {
    int i = blockIdx.x * 256 + threadIdx.x;
    if (i < 8192) {
        float2 w = ((const float2*)W1)[i];
        hsplit2(w.x, w.y, g_W1h2[i], g_W1l2[i]);
    } else if (i < 24576) {
        int j = i - 8192;
        float2 w = ((const float2*)W2)[j];
        hsplit2(w.x, w.y, g_W2h2[j], g_W2l2[j]);
    }
}

// ---------------- k_prep: A/D factorization with smem-staged W0 ----------------
#define SW_PITCH 16900   /* 131*129=16899 rounded up so sI is 16B-aligned */
static const int SMEM_PREP = (SW_PITCH + 131*16) * 4;
__global__ void __launch_bounds__(128) k_prep(
        const float* __restrict__ pos1, const float* __restrict__ pos2,
        const float* __restrict__ f1,   const float* __restrict__ f2,
        const float* __restrict__ W0) {
    extern __shared__ float sp[];
    float* sW = sp;               // [131][129]
    float* sI = sp + SW_PITCH;    // [131][16], 16B-aligned
    int blk = blockIdx.x;
    int b  = blk / (NN/16);
    int j0 = (blk % (NN/16)) * 16;
    int tid = threadIdx.x;

    // ---- pass A ----
    for (int i = tid; i < 131*128; i += 128) {
        int o = i / 131, c = i - o*131;
        sW[c*129 + o] = W0[o*259 + c];
    }
    for (int i = tid; i < 131*16; i += 128) {
        int c = i >> 4, jl = i & 15;
        sI[c*16 + jl] = (c < 3) ? pos2[(b*3 + c)*NN + j0 + jl]
                                : f2[(b*128 + (c-3))*NN + j0 + jl];
    }
    __syncthreads();
    {
        float4 acc[4];
        #pragma unroll
        for (int q = 0; q < 4; q++) acc[q] = make_float4(0.f,0.f,0.f,0.f);
        for (int c = 0; c < 131; c++) {
            float wv = sW[c*129 + tid];
            const float4* r = (const float4*)&sI[c*16];
            #pragma unroll
            for (int q = 0; q < 4; q++) {
                float4 rv = r[q];
                acc[q].x = fmaf(wv, rv.x, acc[q].x);
                acc[q].y = fmaf(wv, rv.y, acc[q].y);
                acc[q].z = fmaf(wv, rv.z, acc[q].z);
                acc[q].w = fmaf(wv, rv.w, acc[q].w);
            }
        }
        const float* af = (const float*)acc;
        #pragma unroll
        for (int pt = 0; pt < 16; pt++)
            g_A[((b*NN + j0 + pt) << 7) + tid] = af[pt];
    }
    __syncthreads();

    // ---- pass D ----
    for (int i = tid; i < 131*128; i += 128) {
        int o = i / 131, c = i - o*131;
        int src = (c < 3) ? c : 128 + c;   // 131 + (c-3)
        sW[c*129 + o] = W0[o*259 + src];
    }
    for (int i = tid; i < 131*16; i += 128) {
        int c = i >> 4, jl = i & 15;
        sI[c*16 + jl] = (c < 3) ? -pos1[(b*3 + c)*NN + j0 + jl]
                                : f1[(b*128 + (c-3))*NN + j0 + jl];
    }
    __syncthreads();
    {
        float4 acc[4];
        #pragma unroll
        for (int q = 0; q < 4; q++) acc[q] = make_float4(0.f,0.f,0.f,0.f);
        for (int c = 0; c < 131; c++) {
            float wv = sW[c*129 + tid];
            const float4* r = (const float4*)&sI[c*16];
            #pragma unroll
            for (int q = 0; q < 4; q++) {
                float4 rv = r[q];
                acc[q].x = fmaf(wv, rv.x, acc[q].x);
                acc[q].y = fmaf(wv, rv.y, acc[q].y);
                acc[q].z = fmaf(wv, rv.z, acc[q].z);
                acc[q].w = fmaf(wv, rv.w, acc[q].w);
            }
        }
        const float* af = (const float*)acc;
        #pragma unroll
        for (int pt = 0; pt < 16; pt++)
            g_D[((b*NN + j0 + pt) << 7) + tid] = af[pt];
    }
}

// ---------------- k_stats0: stats of y0 = A[idx] + D ----------------
__global__ void __launch_bounds__(128) k_stats0(const int* __restrict__ idxp) {
    __shared__ int s_idx[128];
    int tid = threadIdx.x;
    int pbase = blockIdx.x * 128;
    s_idx[tid] = idxp[pbase + tid];
    __syncthreads();
    float s = 0.f, ss = 0.f;
    #pragma unroll 4
    for (int i = 0; i < 128; i++) {
        int p = pbase + i;
        int arow = ((p >> 16) * NN + s_idx[i]) << 7;
        int drow = (p >> 5) << 7;
        float y = g_A[arow + tid] + g_D[drow + tid];
        s += y; ss = fmaf(y, y, ss);
    }
    atomicAdd(&g_s0[tid], s);
    atomicAdd(&g_s0[L0 + tid], ss);
}

// ======================= layer 1 =======================
// block: 256 points x 128 out x K=128; 512 thr / 16 warps; warp tile 32x64
static const int L1HDR = 4096;
static const int L1_UH = L1HDR;               // 256*256B = 65536
static const int L1_UL = L1_UH + 65536;
static const int L1_WH = L1_UL + 65536;       // 128*256B = 32768
static const int L1_WL = L1_WH + 32768;
static const int SMEM_L1 = L1_WL + 32768;     // 200704

__global__ void __launch_bounds__(512, 1) k_l1(
        const int* __restrict__ idxp,
        const float* __restrict__ gam, const float* __restrict__ bet) {
    extern __shared__ char sm[];
    uint32_t sb = smem_u32(sm);
    float* sA   = (float*)(sm + 0);
    float* sC   = (float*)(sm + 512);
    int*   sAR  = (int*)(sm + 1024);     // 256 ints
    float* sSum = (float*)(sm + 2048);
    float* sSs  = (float*)(sm + 2560);
    int tid = threadIdx.x, wid = tid >> 5, lane = tid & 31;
    int pbase = blockIdx.x * 256;

    if (tid < 128) {
        const float inv = 1.0f / (float)PTOT;
        float mean = g_s0[tid] * inv;
        float var  = g_s0[128 + tid] * inv - mean * mean;
        float a = gam[tid] * rsqrtf(var + EPSV);
        sA[tid] = a; sC[tid] = bet[tid] - mean * a;
        sSum[tid] = 0.f; sSs[tid] = 0.f;
    }
    if (tid < 256) {
        int p = pbase + tid;
        sAR[tid] = ((p >> 16) * NN + idxp[p]) << 7;
    }
    __syncthreads();

    // W tiles (128 rows)
    for (int i = tid; i < 8192; i += 512) {
        int o = i >> 6, c2 = i & 63;
        uint32_t off = sw_pair(o, c2);
        *(uint32_t*)(sm + L1_WH + off) = g_W1h2[i];
        *(uint32_t*)(sm + L1_WL + off) = g_W1l2[i];
    }
    // U tiles (256 rows): lrelu(BN0(A[idx]+D)) split
    for (int i = tid; i < 16384; i += 512) {
        int p = i >> 6, c2 = i & 63;
        const float2* ar = (const float2*)(g_A + sAR[p]);
        const float2* dr = (const float2*)(g_D + (((pbase + p) >> 5) << 7));
        float2 av = ar[c2], dv = dr[c2];
        int c = c2 << 1;
        float u0 = fmaf(sA[c],     av.x + dv.x, sC[c]);
        float u1 = fmaf(sA[c + 1], av.y + dv.y, sC[c + 1]);
        u0 = (u0 > 0.f) ? u0 : SLOPE * u0;
        u1 = (u1 > 0.f) ? u1 : SLOPE * u1;
        uint32_t hi, lo; hsplit2(u0, u1, hi, lo);
        uint32_t off = sw_pair(p, c2);
        *(uint32_t*)(sm + L1_UH + off) = hi;
        *(uint32_t*)(sm + L1_UL + off) = lo;
    }
    __syncthreads();

    int mr = (wid & 7) * 32, nr = (wid >> 3) * 64;
    float acc[2][8][4];
    #pragma unroll
    for (int mt = 0; mt < 2; mt++)
        #pragma unroll
        for (int nt = 0; nt < 8; nt++)
            #pragma unroll
            for (int q = 0; q < 4; q++) acc[mt][nt][q] = 0.f;

    int aRow = lane & 15, aSel = lane >> 4;
    int bRow = (lane & 7) + ((lane >> 4) << 3), bSel = (lane >> 3) & 1;

    for (int ks = 0; ks < 8; ks++) {
        uint32_t ah[2][4], al[2][4];
        int clA = 2*ks + aSel;
        #pragma unroll
        for (int mt = 0; mt < 2; mt++) {
            int r = mr + mt*16 + aRow;
            uint32_t off = sw_chunk(r, clA);
            ldmx4(ah[mt], sb + L1_UH + off);
            ldmx4(al[mt], sb + L1_UL + off);
        }
        int clB = 2*ks + bSel;
        #pragma unroll
        for (int q = 0; q < 4; q++) {
            int n = nr + q*16 + bRow;
            uint32_t off = sw_chunk(n, clB);
            uint32_t bh[4], bl[4];
            ldmx4(bh, sb + L1_WH + off);
            ldmx4(bl, sb + L1_WL + off);
            #pragma unroll
            for (int mt = 0; mt < 2; mt++) {
                mma16816(acc[mt][2*q],     ah[mt], bh);
                mma16816(acc[mt][2*q + 1], ah[mt], bh + 2);
                mma16816(acc[mt][2*q],     ah[mt], bl);
                mma16816(acc[mt][2*q + 1], ah[mt], bl + 2);
                mma16816(acc[mt][2*q],     al[mt], bh);
                mma16816(acc[mt][2*q + 1], al[mt], bh + 2);
            }
        }
    }
    __syncthreads();   // sO reuses operand smem

    float* sO = (float*)(sm + L1HDR);   // [256][129]
    #pragma unroll
    for (int mt = 0; mt < 2; mt++) {
        int r = mr + mt*16 + (lane >> 2);
        #pragma unroll
        for (int nt = 0; nt < 8; nt++) {
            int c = nr + nt*8 + ((lane & 3) << 1);
            sO[r*129 + c]           = acc[mt][nt][0];
            sO[r*129 + c + 1]       = acc[mt][nt][1];
            sO[(r + 8)*129 + c]     = acc[mt][nt][2];
            sO[(r + 8)*129 + c + 1] = acc[mt][nt][3];
        }
    }
    __syncthreads();

    float s = 0.f, ssq = 0.f;
    int cch = tid & 127;
    for (int i = tid; i < 32768; i += 512) {
        int p = i >> 7;
        float v = sO[p*129 + cch];
        g_y1[(size_t)(pbase + p)*128 + cch] = v;
        s += v; ssq = fmaf(v, v, ssq);
    }
    atomicAdd(&sSum[cch], s);
    atomicAdd(&sSs[cch], ssq);
    __syncthreads();
    if (tid < 128) {
        atomicAdd(&g_s1[tid],       sSum[tid]);
        atomicAdd(&g_s1[128 + tid], sSs[tid]);
    }
}

// ======================= layer 2 =======================
// block: 128 points x 256 out x K=128; 512 thr / 16 warps; warp tile 32x64
static const int L2HDR = 4096;
static const int L2_UH = L2HDR;               // 128*256B = 32768
static const int L2_UL = L2_UH + 32768;
static const int L2_WH = L2_UL + 32768;       // 256*256B = 65536
static const int L2_WL = L2_WH + 65536;
static const int SMEM_L2 = L2_WL + 65536;     // 200704

__global__ void __launch_bounds__(512, 1) k_l2(
        const float* __restrict__ gam, const float* __restrict__ bet) {
    extern __shared__ char sm[];
    uint32_t sb = smem_u32(sm);
    float* sA   = (float*)(sm + 0);
    float* sC   = (float*)(sm + 512);
    float* sSum = (float*)(sm + 1024);   // 256
    float* sSs  = (float*)(sm + 2048);   // 256
    int tid = threadIdx.x, wid = tid >> 5, lane = tid & 31;
    int pbase = blockIdx.x * 128;

    if (tid < 128) {
        const float inv = 1.0f / (float)PTOT;
        float mean = g_s1[tid] * inv;
        float var  = g_s1[128 + tid] * inv - mean * mean;
        float a = gam[tid] * rsqrtf(var + EPSV);
        sA[tid] = a; sC[tid] = bet[tid] - mean * a;
    }
    if (tid < 256) { sSum[tid] = 0.f; sSs[tid] = 0.f; }
    __syncthreads();

    // W tiles (256 rows)
    for (int i = tid; i < 16384; i += 512) {
        int o = i >> 6, c2 = i & 63;
        uint32_t off = sw_pair(o, c2);
        *(uint32_t*)(sm + L2_WH + off) = g_W2h2[i];
        *(uint32_t*)(sm + L2_WL + off) = g_W2l2[i];
    }
    // U tiles (128 rows): lrelu(BN1(y1)) split
    for (int i = tid; i < 8192; i += 512) {
        int p = i >> 6, c2 = i & 63;
        float2 y = ((const float2*)(g_y1 + (size_t)(pbase + p)*128))[c2];
        int c = c2 << 1;
        float u0 = fmaf(sA[c],     y.x, sC[c]);
        float u1 = fmaf(sA[c + 1], y.y, sC[c + 1]);
        u0 = (u0 > 0.f) ? u0 : SLOPE * u0;
        u1 = (u1 > 0.f) ? u1 : SLOPE * u1;
        uint32_t hi, lo; hsplit2(u0, u1, hi, lo);
        uint32_t off = sw_pair(p, c2);
        *(uint32_t*)(sm + L2_UH + off) = hi;
        *(uint32_t*)(sm + L2_UL + off) = lo;
    }
    __syncthreads();

    int mr = (wid & 3) * 32, nr = (wid >> 2) * 64;
    float acc[2][8][4];
    #pragma unroll
    for (int mt = 0; mt < 2; mt++)
        #pragma unroll
        for (int nt = 0; nt < 8; nt++)
            #pragma unroll
            for (int q = 0; q < 4; q++) acc[mt][nt][q] = 0.f;

    int aRow = lane & 15, aSel = lane >> 4;
    int bRow = (lane & 7) + ((lane >> 4) << 3), bSel = (lane >> 3) & 1;

    for (int ks = 0; ks < 8; ks++) {
        uint32_t ah[2][4], al[2][4];
        int clA = 2*ks + aSel;
        #pragma unroll
        for (int mt = 0; mt < 2; mt++) {
            int r = mr + mt*16 + aRow;
            uint32_t off = sw_chunk(r, clA);
            ldmx4(ah[mt], sb + L2_UH + off);
            ldmx4(al[mt], sb + L2_UL + off);
        }
        int clB = 2*ks + bSel;
        #pragma unroll
        for (int q = 0; q < 4; q++) {
            int n = nr + q*16 + bRow;
            uint32_t off = sw_chunk(n, clB);
            uint32_t bh[4], bl[4];
            ldmx4(bh, sb + L2_WH + off);
            ldmx4(bl, sb + L2_WL + off);
            #pragma unroll
            for (int mt = 0; mt < 2; mt++) {
                mma16816(acc[mt][2*q],     ah[mt], bh);
                mma16816(acc[mt][2*q + 1], ah[mt], bh + 2);
                mma16816(acc[mt][2*q],     ah[mt], bl);
                mma16816(acc[mt][2*q + 1], ah[mt], bl + 2);
                mma16816(acc[mt][2*q],     al[mt], bh);
                mma16816(acc[mt][2*q + 1], al[mt], bh + 2);
            }
        }
    }
    __syncthreads();

    float* sO = (float*)(sm + L2HDR);   // [256 ch][129] (transposed)
    #pragma unroll
    for (int mt = 0; mt < 2; mt++) {
        int r = mr + mt*16 + (lane >> 2);
        #pragma unroll
        for (int nt = 0; nt < 8; nt++) {
            int c = nr + nt*8 + ((lane & 3) << 1);
            sO[c*129 + r]           = acc[mt][nt][0];
            sO[(c + 1)*129 + r]     = acc[mt][nt][1];
            sO[c*129 + r + 8]       = acc[mt][nt][2];
            sO[(c + 1)*129 + r + 8] = acc[mt][nt][3];
        }
    }
    __syncthreads();

    // K-reduction: c = tid&255; half = tid>>8 handles 2 of the 4 n-groups
    {
        int c = tid & 255, half = tid >> 8;
        int bn0 = blockIdx.x * 4;
        float s = 0.f, ssq = 0.f;
        #pragma unroll
        for (int gi = 0; gi < 2; gi++) {
            int g = half*2 + gi;
            float mx = -3.4e38f, mn = 3.4e38f;
            #pragma unroll 8
            for (int k = 0; k < 32; k++) {
                float v = sO[c*129 + g*32 + k];
                s += v; ssq = fmaf(v, v, ssq);
                mx = fmaxf(mx, v); mn = fminf(mn, v);
            }
            g_mx[(bn0 + g)*256 + c] = mx;
            g_mn[(bn0 + g)*256 + c] = mn;
        }
        atomicAdd(&sSum[c], s);
        atomicAdd(&sSs[c], ssq);
    }
    __syncthreads();
    if (tid < 256) {
        atomicAdd(&g_s2[tid],       sSum[tid]);
        atomicAdd(&g_s2[256 + tid], sSs[tid]);
    }
}

// ---------------- k_out ----------------
static const int SMEM_OUT = 2 * 64 * 257 * 4;
__global__ void __launch_bounds__(256) k_out(float* __restrict__ out,
        const float* __restrict__ gam, const float* __restrict__ bet) {
    extern __shared__ float smf[];
    float* sMx = smf;
    float* sMn = smf + 64*257;
    __shared__ float sA2[256], sC2[256];
    int tid = threadIdx.x;
    {
        const float inv = 1.0f / (float)PTOT;
        float mean = g_s2[tid] * inv;
        float var  = g_s2[256 + tid] * inv - mean * mean;
        float a = gam[tid] * rsqrtf(var + EPSV);
        sA2[tid] = a; sC2[tid] = bet[tid] - mean * a;
    }
    int b  = blockIdx.x >> 5;
    int n0 = (blockIdx.x & 31) * 64;
    for (int i = tid; i < 64*256; i += 256) {
        int nl = i >> 8, o = i & 255;
        int g = (b*NN + n0 + nl)*256 + o;
        sMx[nl*257 + o] = g_mx[g];
        sMn[nl*257 + o] = g_mn[g];
    }
    __syncthreads();
    for (int i = tid; i < 64*256; i += 256) {
        int o = i >> 6, nl = i & 63;
        float a = sA2[o], c = sC2[o];
        float z = (a >= 0.f) ? sMx[nl*257 + o] : sMn[nl*257 + o];
        float y = fmaf(a, z, c);
        out[(b*256 + o)*NN + n0 + nl] = (y > 0.f) ? y : SLOPE * y;
    }
}

// ---------------- launch ----------------
extern "C" void kernel_launch(void* const* d_in, const int* in_sizes, int n_in,
                              void* d_out, int out_size) {
    const float* pos1 = (const float*)d_in[0];
    const float* pos2 = (const float*)d_in[1];
    const float* f1   = (const float*)d_in[2];
    const float* f2   = (const float*)d_in[3];
    const int*   idxp = (const int*)d_in[4];
    const float* W0 = (const float*)d_in[5];
    const float* g0 = (const float*)d_in[6];
    const float* b0 = (const float*)d_in[7];
    const float* W1 = (const float*)d_in[8];
    const float* g1 = (const float*)d_in[9];
    const float* b1 = (const float*)d_in[10];
    const float* W2 = (const float*)d_in[11];
    const float* g2 = (const float*)d_in[12];
    const float* b2 = (const float*)d_in[13];

    cudaFuncSetAttribute(k_prep, cudaFuncAttributeMaxDynamicSharedMemorySize, SMEM_PREP);
    cudaFuncSetAttribute(k_l1,   cudaFuncAttributeMaxDynamicSharedMemorySize, SMEM_L1);
    cudaFuncSetAttribute(k_l2,   cudaFuncAttributeMaxDynamicSharedMemorySize, SMEM_L2);
    cudaFuncSetAttribute(k_out,  cudaFuncAttributeMaxDynamicSharedMemorySize, SMEM_OUT);

    float* outp = (float*)d_out;
    int featOff = out_size - BB*L2C*NN;
    if (featOff < 0) featOff = 0;

    k_zero<<<1, 512>>>();                                            // 0
    k_prep<<<BB*(NN/16), 128, SMEM_PREP>>>(pos1, pos2, f1, f2, W0);  // 1
    k_stats0<<<PTOT/128, 128>>>(idxp);                               // 2
    k_wsplit<<<96, 256>>>(W1, W2);                                   // 3
    k_l1<<<PTOT/256, 512, SMEM_L1>>>(idxp, g0, b0);                  // 4
    k_l2<<<PTOT/128, 512, SMEM_L2>>>(g1, b1);                        // 5 (profiled)
    if (featOff > 0)
        cudaMemcpyAsync(d_out, pos1, (size_t)featOff * sizeof(float),
                        cudaMemcpyDeviceToDevice, 0);
    k_out<<<BB*(NN/64), 256, SMEM_OUT>>>(outp + featOff, g2, b2);    // 6
}

// round 5
// speedup vs baseline: 3.3691x; 1.1392x over previous
#include <cuda_runtime.h>
#include <cuda_fp16.h>
#include <cstdint>

#define BB 4
#define NN 2048
#define KK 32
#define L0 128
#define L1C 128
#define L2C 256
#define PTOT (BB*NN*KK)   /* 262144 */
#define EPSV 1e-5f
#define SLOPE 0.01f

// ---------------- scratch ----------------
__device__ float g_A[BB*NN*L0];          // 4 MB
__device__ float g_D[BB*NN*L0];          // 4 MB
__device__ float g_y1[(size_t)PTOT*L1C]; // 134 MB
__device__ float g_mx[BB*NN*L2C];        // 8 MB
__device__ float g_mn[BB*NN*L2C];        // 8 MB
__device__ float g_s0[2*L0];
__device__ float g_s1[2*L1C];
__device__ float g_s2[2*L2C];
__device__ uint32_t g_W1h2[128*64];      // W1 split, half2 packed
__device__ uint32_t g_W1l2[128*64];
__device__ uint32_t g_W2h2[256*64];
__device__ uint32_t g_W2l2[256*64];

// ---------------- helpers ----------------
__device__ __forceinline__ uint32_t smem_u32(const void* p) {
    uint32_t a;
    asm("{ .reg .u64 t; cvta.to.shared.u64 t, %1; cvt.u32.u64 %0, t; }" : "=r"(a) : "l"(p));
    return a;
}
__device__ __forceinline__ void ldmx4(uint32_t* r, uint32_t addr) {
    asm volatile("ldmatrix.sync.aligned.m8n8.x4.shared.b16 {%0,%1,%2,%3}, [%4];"
                 : "=r"(r[0]), "=r"(r[1]), "=r"(r[2]), "=r"(r[3]) : "r"(addr));
}
__device__ __forceinline__ void mma16816(float* d, const uint32_t* a, const uint32_t* b) {
    asm volatile(
        "mma.sync.aligned.m16n8k16.row.col.f32.f16.f16.f32 "
        "{%0,%1,%2,%3}, {%4,%5,%6,%7}, {%8,%9}, {%0,%1,%2,%3};"
        : "+f"(d[0]), "+f"(d[1]), "+f"(d[2]), "+f"(d[3])
        : "r"(a[0]), "r"(a[1]), "r"(a[2]), "r"(a[3]), "r"(b[0]), "r"(b[1]));
}
__device__ __forceinline__ void hsplit2(float x, float y, uint32_t& hi, uint32_t& lo) {
    __half hx = __float2half_rn(x), hy = __float2half_rn(y);
    __half lx = __float2half_rn(x - __half2float(hx));
    __half ly = __float2half_rn(y - __half2float(hy));
    __half2 h2 = __halves2half2(hx, hy), l2 = __halves2half2(lx, ly);
    hi = *(uint32_t*)&h2; lo = *(uint32_t*)&l2;
}
// tile rows are 256B (128 halves); XOR-swizzle 16B chunks within each 128B octant
__device__ __forceinline__ uint32_t sw_pair(int row, int c2) {   // c2 = half2 index 0..63
    return (uint32_t)row*256u + (uint32_t)(((c2 >> 2) ^ (row & 7)) << 4) + (uint32_t)((c2 & 3) << 2);
}
__device__ __forceinline__ uint32_t sw_chunk(int row, int cl) {  // cl = 16B chunk 0..15
    return (uint32_t)row*256u + (uint32_t)(((cl ^ (row & 7)) & 15) << 4);
}

// ---------------- k_zero ----------------
__global__ void k_zero() {
    int t = threadIdx.x;   // 512
    if (t < 2*L0)  g_s0[t] = 0.f;
    if (t < 2*L1C) g_s1[t] = 0.f;
    g_s2[t] = 0.f;
}

// ---------------- k_wsplit: W1/W2 -> half2 hi/lo ----------------
__global__ void k_wsplit(const float* __restrict__ W1, const float* __restrict__ W2) {
    int i = blockIdx.x * 256 + threadIdx.x;
    if (i < 8192) {
        float2 w = ((const float2*)W1)[i];
        hsplit2(w.x, w.y, g_W1h2[i], g_W1l2[i]);
    } else if (i < 24576) {
        int j = i - 8192;
        float2 w = ((const float2*)W2)[j];
        hsplit2(w.x, w.y, g_W2h2[j], g_W2l2[j]);
    }
}

// ---------------- k_prep: A/D factorization with smem-staged W0 ----------------
#define SW_PITCH 16900   /* 131*129=16899 rounded up so sI is 16B-aligned */
static const int SMEM_PREP = (SW_PITCH + 131*16) * 4;
__global__ void __launch_bounds__(128) k_prep(
        const float* __restrict__ pos1, const float* __restrict__ pos2,
        const float* __restrict__ f1,   const float* __restrict__ f2,
        const float* __restrict__ W0) {
    extern __shared__ float sp[];
    float* sW = sp;               // [131][129]
    float* sI = sp + SW_PITCH;    // [131][16], 16B-aligned
    int blk = blockIdx.x;
    int b  = blk / (NN/16);
    int j0 = (blk % (NN/16)) * 16;
    int tid = threadIdx.x;

    // ---- pass A ----
    for (int i = tid; i < 131*128; i += 128) {
        int o = i / 131, c = i - o*131;
        sW[c*129 + o] = W0[o*259 + c];
    }
    for (int i = tid; i < 131*16; i += 128) {
        int c = i >> 4, jl = i & 15;
        sI[c*16 + jl] = (c < 3) ? pos2[(b*3 + c)*NN + j0 + jl]
                                : f2[(b*128 + (c-3))*NN + j0 + jl];
    }
    __syncthreads();
    {
        float4 acc[4];
        #pragma unroll
        for (int q = 0; q < 4; q++) acc[q] = make_float4(0.f,0.f,0.f,0.f);
        for (int c = 0; c < 131; c++) {
            float wv = sW[c*129 + tid];
            const float4* r = (const float4*)&sI[c*16];
            #pragma unroll
            for (int q = 0; q < 4; q++) {
                float4 rv = r[q];
                acc[q].x = fmaf(wv, rv.x, acc[q].x);
                acc[q].y = fmaf(wv, rv.y, acc[q].y);
                acc[q].z = fmaf(wv, rv.z, acc[q].z);
                acc[q].w = fmaf(wv, rv.w, acc[q].w);
            }
        }
        const float* af = (const float*)acc;
        #pragma unroll
        for (int pt = 0; pt < 16; pt++)
            g_A[((b*NN + j0 + pt) << 7) + tid] = af[pt];
    }
    __syncthreads();

    // ---- pass D ----
    for (int i = tid; i < 131*128; i += 128) {
        int o = i / 131, c = i - o*131;
        int src = (c < 3) ? c : 128 + c;   // 131 + (c-3)
        sW[c*129 + o] = W0[o*259 + src];
    }
    for (int i = tid; i < 131*16; i += 128) {
        int c = i >> 4, jl = i & 15;
        sI[c*16 + jl] = (c < 3) ? -pos1[(b*3 + c)*NN + j0 + jl]
                                : f1[(b*128 + (c-3))*NN + j0 + jl];
    }
    __syncthreads();
    {
        float4 acc[4];
        #pragma unroll
        for (int q = 0; q < 4; q++) acc[q] = make_float4(0.f,0.f,0.f,0.f);
        for (int c = 0; c < 131; c++) {
            float wv = sW[c*129 + tid];
            const float4* r = (const float4*)&sI[c*16];
            #pragma unroll
            for (int q = 0; q < 4; q++) {
                float4 rv = r[q];
                acc[q].x = fmaf(wv, rv.x, acc[q].x);
                acc[q].y = fmaf(wv, rv.y, acc[q].y);
                acc[q].z = fmaf(wv, rv.z, acc[q].z);
                acc[q].w = fmaf(wv, rv.w, acc[q].w);
            }
        }
        const float* af = (const float*)acc;
        #pragma unroll
        for (int pt = 0; pt < 16; pt++)
            g_D[((b*NN + j0 + pt) << 7) + tid] = af[pt];
    }
}

// ---------------- k_stats0: stats of y0 = A[idx] + D ----------------
__global__ void __launch_bounds__(128) k_stats0(const int* __restrict__ idxp) {
    __shared__ int s_idx[128];
    int tid = threadIdx.x;
    int pbase = blockIdx.x * 128;
    s_idx[tid] = idxp[pbase + tid];
    __syncthreads();
    float s = 0.f, ss = 0.f;
    #pragma unroll 4
    for (int i = 0; i < 128; i++) {
        int p = pbase + i;
        int arow = ((p >> 16) * NN + s_idx[i]) << 7;
        int drow = (p >> 5) << 7;
        float y = g_A[arow + tid] + g_D[drow + tid];
        s += y; ss = fmaf(y, y, ss);
    }
    atomicAdd(&g_s0[tid], s);
    atomicAdd(&g_s0[L0 + tid], ss);
}

// ======================= layer 1 =======================
// block: 2 tiles x (256 pts x 128 out) x K=128; 512 thr / 16 warps; warp tile 32x64
static const int L1_UH = 4096;                // 256*256B = 65536
static const int L1_UL = L1_UH + 65536;
static const int L1_WH = L1_UL + 65536;       // 128*256B = 32768
static const int L1_WL = L1_WH + 32768;
static const int SMEM_L1 = L1_WL + 32768;     // 200704

__global__ void __launch_bounds__(512, 1) k_l1(
        const int* __restrict__ idxp,
        const float* __restrict__ gam, const float* __restrict__ bet) {
    extern __shared__ char sm[];
    uint32_t sb = smem_u32(sm);
    float* sA   = (float*)(sm + 0);      // 128
    float* sC   = (float*)(sm + 512);    // 128
    int*   sAR  = (int*)(sm + 1024);     // 512 ints -> 1024..3071
    float* sSum = (float*)(sm + 3072);   // 128
    float* sSs  = (float*)(sm + 3584);   // 128
    int tid = threadIdx.x, wid = tid >> 5, lane = tid & 31;
    int pblk = blockIdx.x * 512;

    if (tid < 128) {
        const float inv = 1.0f / (float)PTOT;
        float mean = g_s0[tid] * inv;
        float var  = g_s0[128 + tid] * inv - mean * mean;
        float a = gam[tid] * rsqrtf(var + EPSV);
        sA[tid] = a; sC[tid] = bet[tid] - mean * a;
        sSum[tid] = 0.f; sSs[tid] = 0.f;
    }
    {
        int p = pblk + tid;
        sAR[tid] = ((p >> 16) * NN + idxp[p]) << 7;
    }
    __syncthreads();

    // W tiles (128 rows), loaded once
    for (int i = tid; i < 8192; i += 512) {
        int o = i >> 6, c2 = i & 63;
        uint32_t off = sw_pair(o, c2);
        *(uint32_t*)(sm + L1_WH + off) = g_W1h2[i];
        *(uint32_t*)(sm + L1_WL + off) = g_W1l2[i];
    }

    int mr = (wid & 7) * 32, nr = (wid >> 3) * 64;
    int aRow = lane & 15, aSel = lane >> 4;
    int bRow = (lane & 7) + ((lane >> 4) << 3), bSel = (lane >> 3) & 1;

    #pragma unroll 1
    for (int t = 0; t < 2; t++) {
        int pbase = pblk + t * 256;
        if (t) __syncthreads();   // all warps done reading U of prev tile

        // U tiles (256 rows): lrelu(BN0(A[idx]+D)) split hi/lo
        for (int i = tid; i < 16384; i += 512) {
            int pl = i >> 6, c2 = i & 63;
            const float2* ar = (const float2*)(g_A + sAR[t*256 + pl]);
            const float2* dr = (const float2*)(g_D + (((pbase + pl) >> 5) << 7));
            float2 av = ar[c2], dv = dr[c2];
            int c = c2 << 1;
            float u0 = fmaf(sA[c],     av.x + dv.x, sC[c]);
            float u1 = fmaf(sA[c + 1], av.y + dv.y, sC[c + 1]);
            u0 = (u0 > 0.f) ? u0 : SLOPE * u0;
            u1 = (u1 > 0.f) ? u1 : SLOPE * u1;
            uint32_t hi, lo; hsplit2(u0, u1, hi, lo);
            uint32_t off = sw_pair(pl, c2);
            *(uint32_t*)(sm + L1_UH + off) = hi;
            *(uint32_t*)(sm + L1_UL + off) = lo;
        }
        __syncthreads();

        float acc[2][8][4];
        #pragma unroll
        for (int mt = 0; mt < 2; mt++)
            #pragma unroll
            for (int nt = 0; nt < 8; nt++)
                #pragma unroll
                for (int q = 0; q < 4; q++) acc[mt][nt][q] = 0.f;

        for (int ks = 0; ks < 8; ks++) {
            uint32_t ah[2][4], al[2][4];
            int clA = 2*ks + aSel;
            #pragma unroll
            for (int mt = 0; mt < 2; mt++) {
                int r = mr + mt*16 + aRow;
                uint32_t off = sw_chunk(r, clA);
                ldmx4(ah[mt], sb + L1_UH + off);
                ldmx4(al[mt], sb + L1_UL + off);
            }
            int clB = 2*ks + bSel;
            #pragma unroll
            for (int q = 0; q < 4; q++) {
                int n = nr + q*16 + bRow;
                uint32_t off = sw_chunk(n, clB);
                uint32_t bh[4], bl[4];
                ldmx4(bh, sb + L1_WH + off);
                ldmx4(bl, sb + L1_WL + off);
                #pragma unroll
                for (int mt = 0; mt < 2; mt++) {
                    mma16816(acc[mt][2*q],     ah[mt], bh);
                    mma16816(acc[mt][2*q + 1], ah[mt], bh + 2);
                    mma16816(acc[mt][2*q],     ah[mt], bl);
                    mma16816(acc[mt][2*q + 1], ah[mt], bl + 2);
                    mma16816(acc[mt][2*q],     al[mt], bh);
                    mma16816(acc[mt][2*q + 1], al[mt], bh + 2);
                }
            }
        }

        // ---- register epilogue: direct y1 stores + channel sums via shuffles ----
        #pragma unroll
        for (int mt = 0; mt < 2; mt++) {
            int r = mr + mt*16 + (lane >> 2);
            #pragma unroll
            for (int nt = 0; nt < 8; nt++) {
                int c = nr + nt*8 + ((lane & 3) << 1);
                *(float2*)&g_y1[(size_t)(pbase + r)*128 + c] =
                    make_float2(acc[mt][nt][0], acc[mt][nt][1]);
                *(float2*)&g_y1[(size_t)(pbase + r + 8)*128 + c] =
                    make_float2(acc[mt][nt][2], acc[mt][nt][3]);
            }
        }
        #pragma unroll
        for (int nt = 0; nt < 8; nt++) {
            float s0 = acc[0][nt][0] + acc[0][nt][2] + acc[1][nt][0] + acc[1][nt][2];
            float s1 = acc[0][nt][1] + acc[0][nt][3] + acc[1][nt][1] + acc[1][nt][3];
            float q0 = acc[0][nt][0]*acc[0][nt][0] + acc[0][nt][2]*acc[0][nt][2]
                     + acc[1][nt][0]*acc[1][nt][0] + acc[1][nt][2]*acc[1][nt][2];
            float q1 = acc[0][nt][1]*acc[0][nt][1] + acc[0][nt][3]*acc[0][nt][3]
                     + acc[1][nt][1]*acc[1][nt][1] + acc[1][nt][3]*acc[1][nt][3];
            #pragma unroll
            for (int d = 4; d < 32; d <<= 1) {
                s0 += __shfl_xor_sync(0xFFFFFFFF, s0, d);
                s1 += __shfl_xor_sync(0xFFFFFFFF, s1, d);
                q0 += __shfl_xor_sync(0xFFFFFFFF, q0, d);
                q1 += __shfl_xor_sync(0xFFFFFFFF, q1, d);
            }
            if (lane < 4) {
                int c = nr + nt*8 + (lane << 1);
                atomicAdd(&sSum[c], s0);  atomicAdd(&sSum[c + 1], s1);
                atomicAdd(&sSs[c],  q0);  atomicAdd(&sSs[c + 1],  q1);
            }
        }
    }
    __syncthreads();
    if (tid < 128) {
        atomicAdd(&g_s1[tid],       sSum[tid]);
        atomicAdd(&g_s1[128 + tid], sSs[tid]);
    }
}

// ======================= layer 2 =======================
// block: 2 tiles x (128 pts x 256 out) x K=128; 512 thr / 16 warps; warp tile 32x64
static const int L2_UH = 4096;                // 128*256B = 32768
static const int L2_UL = L2_UH + 32768;
static const int L2_WH = L2_UL + 32768;       // 256*256B = 65536
static const int L2_WL = L2_WH + 65536;
static const int SMEM_L2 = L2_WL + 65536;     // 200704

__global__ void __launch_bounds__(512, 1) k_l2(
        const float* __restrict__ gam, const float* __restrict__ bet) {
    extern __shared__ char sm[];
    uint32_t sb = smem_u32(sm);
    float* sA   = (float*)(sm + 0);      // 128
    float* sC   = (float*)(sm + 512);    // 128
    float* sSum = (float*)(sm + 1024);   // 256
    float* sSs  = (float*)(sm + 2048);   // 256
    int tid = threadIdx.x, wid = tid >> 5, lane = tid & 31;
    int pblk = blockIdx.x * 256;

    if (tid < 128) {
        const float inv = 1.0f / (float)PTOT;
        float mean = g_s1[tid] * inv;
        float var  = g_s1[128 + tid] * inv - mean * mean;
        float a = gam[tid] * rsqrtf(var + EPSV);
        sA[tid] = a; sC[tid] = bet[tid] - mean * a;
    }
    if (tid < 256) { sSum[tid] = 0.f; sSs[tid] = 0.f; }
    __syncthreads();

    // W tiles (256 rows), loaded once
    for (int i = tid; i < 16384; i += 512) {
        int o = i >> 6, c2 = i & 63;
        uint32_t off = sw_pair(o, c2);
        *(uint32_t*)(sm + L2_WH + off) = g_W2h2[i];
        *(uint32_t*)(sm + L2_WL + off) = g_W2l2[i];
    }

    int mr = (wid & 3) * 32, nr = (wid >> 2) * 64;
    int aRow = lane & 15, aSel = lane >> 4;
    int bRow = (lane & 7) + ((lane >> 4) << 3), bSel = (lane >> 3) & 1;

    #pragma unroll 1
    for (int t = 0; t < 2; t++) {
        int pbase = pblk + t * 128;
        if (t) __syncthreads();

        // U tiles (128 rows): lrelu(BN1(y1)) split hi/lo
        for (int i = tid; i < 8192; i += 512) {
            int pl = i >> 6, c2 = i & 63;
            float2 y = ((const float2*)(g_y1 + (size_t)(pbase + pl)*128))[c2];
            int c = c2 << 1;
            float u0 = fmaf(sA[c],     y.x, sC[c]);
            float u1 = fmaf(sA[c + 1], y.y, sC[c + 1]);
            u0 = (u0 > 0.f) ? u0 : SLOPE * u0;
            u1 = (u1 > 0.f) ? u1 : SLOPE * u1;
            uint32_t hi, lo; hsplit2(u0, u1, hi, lo);
            uint32_t off = sw_pair(pl, c2);
            *(uint32_t*)(sm + L2_UH + off) = hi;
            *(uint32_t*)(sm + L2_UL + off) = lo;
        }
        __syncthreads();

        float acc[2][8][4];
        #pragma unroll
        for (int mt = 0; mt < 2; mt++)
            #pragma unroll
            for (int nt = 0; nt < 8; nt++)
                #pragma unroll
                for (int q = 0; q < 4; q++) acc[mt][nt][q] = 0.f;

        for (int ks = 0; ks < 8; ks++) {
            uint32_t ah[2][4], al[2][4];
            int clA = 2*ks + aSel;
            #pragma unroll
            for (int mt = 0; mt < 2; mt++) {
                int r = mr + mt*16 + aRow;
                uint32_t off = sw_chunk(r, clA);
                ldmx4(ah[mt], sb + L2_UH + off);
                ldmx4(al[mt], sb + L2_UL + off);
            }
            int clB = 2*ks + bSel;
            #pragma unroll
            for (int q = 0; q < 4; q++) {
                int n = nr + q*16 + bRow;
                uint32_t off = sw_chunk(n, clB);
                uint32_t bh[4], bl[4];
                ldmx4(bh, sb + L2_WH + off);
                ldmx4(bl, sb + L2_WL + off);
                #pragma unroll
                for (int mt = 0; mt < 2; mt++) {
                    mma16816(acc[mt][2*q],     ah[mt], bh);
                    mma16816(acc[mt][2*q + 1], ah[mt], bh + 2);
                    mma16816(acc[mt][2*q],     ah[mt], bl);
                    mma16816(acc[mt][2*q + 1], ah[mt], bl + 2);
                    mma16816(acc[mt][2*q],     al[mt], bh);
                    mma16816(acc[mt][2*q + 1], al[mt], bh + 2);
                }
            }
        }

        // ---- register epilogue: warp owns one K-group (32 pts) x 64 ch ----
        int bn = (pbase >> 5) + (wid & 3);
        #pragma unroll
        for (int nt = 0; nt < 8; nt++) {
            float mx0 = fmaxf(fmaxf(acc[0][nt][0], acc[0][nt][2]),
                              fmaxf(acc[1][nt][0], acc[1][nt][2]));
            float mx1 = fmaxf(fmaxf(acc[0][nt][1], acc[0][nt][3]),
                              fmaxf(acc[1][nt][1], acc[1][nt][3]));
            float mn0 = fminf(fminf(acc[0][nt][0], acc[0][nt][2]),
                              fminf(acc[1][nt][0], acc[1][nt][2]));
            float mn1 = fminf(fminf(acc[0][nt][1], acc[0][nt][3]),
                              fminf(acc[1][nt][1], acc[1][nt][3]));
            float s0 = acc[0][nt][0] + acc[0][nt][2] + acc[1][nt][0] + acc[1][nt][2];
            float s1 = acc[0][nt][1] + acc[0][nt][3] + acc[1][nt][1] + acc[1][nt][3];
            float q0 = acc[0][nt][0]*acc[0][nt][0] + acc[0][nt][2]*acc[0][nt][2]
                     + acc[1][nt][0]*acc[1][nt][0] + acc[1][nt][2]*acc[1][nt][2];
            float q1 = acc[0][nt][1]*acc[0][nt][1] + acc[0][nt][3]*acc[0][nt][3]
                     + acc[1][nt][1]*acc[1][nt][1] + acc[1][nt][3]*acc[1][nt][3];
            #pragma unroll
            for (int d = 4; d < 32; d <<= 1) {
                mx0 = fmaxf(mx0, __shfl_xor_sync(0xFFFFFFFF, mx0, d));
                mx1 = fmaxf(mx1, __shfl_xor_sync(0xFFFFFFFF, mx1, d));
                mn0 = fminf(mn0, __shfl_xor_sync(0xFFFFFFFF, mn0, d));
                mn1 = fminf(mn1, __shfl_xor_sync(0xFFFFFFFF, mn1, d));
                s0 += __shfl_xor_sync(0xFFFFFFFF, s0, d);
                s1 += __shfl_xor_sync(0xFFFFFFFF, s1, d);
                q0 += __shfl_xor_sync(0xFFFFFFFF, q0, d);
                q1 += __shfl_xor_sync(0xFFFFFFFF, q1, d);
            }
            if (lane < 4) {
                int c = nr + nt*8 + (lane << 1);
                *(float2*)&g_mx[bn*256 + c] = make_float2(mx0, mx1);
                *(float2*)&g_mn[bn*256 + c] = make_float2(mn0, mn1);
                atomicAdd(&sSum[c], s0);  atomicAdd(&sSum[c + 1], s1);
                atomicAdd(&sSs[c],  q0);  atomicAdd(&sSs[c + 1],  q1);
            }
        }
    }
    __syncthreads();
    if (tid < 256) {
        atomicAdd(&g_s2[tid],       sSum[tid]);
        atomicAdd(&g_s2[256 + tid], sSs[tid]);
    }
}

// ---------------- k_out ----------------
static const int SMEM_OUT = 2 * 64 * 257 * 4;
__global__ void __launch_bounds__(256) k_out(float* __restrict__ out,
        const float* __restrict__ gam, const float* __restrict__ bet) {
    extern __shared__ float smf[];
    float* sMx = smf;
    float* sMn = smf + 64*257;
    __shared__ float sA2[256], sC2[256];
    int tid = threadIdx.x;
    {
        const float inv = 1.0f / (float)PTOT;
        float mean = g_s2[tid] * inv;
        float var  = g_s2[256 + tid] * inv - mean * mean;
        float a = gam[tid] * rsqrtf(var + EPSV);
        sA2[tid] = a; sC2[tid] = bet[tid] - mean * a;
    }
    int b  = blockIdx.x >> 5;
    int n0 = (blockIdx.x & 31) * 64;
    for (int i = tid; i < 64*256; i += 256) {
        int nl = i >> 8, o = i & 255;
        int g = (b*NN + n0 + nl)*256 + o;
        sMx[nl*257 + o] = g_mx[g];
        sMn[nl*257 + o] = g_mn[g];
    }
    __syncthreads();
    for (int i = tid; i < 64*256; i += 256) {
        int o = i >> 6, nl = i & 63;
        float a = sA2[o], c = sC2[o];
        float z = (a >= 0.f) ? sMx[nl*257 + o] : sMn[nl*257 + o];
        float y = fmaf(a, z, c);
        out[(b*256 + o)*NN + n0 + nl] = (y > 0.f) ? y : SLOPE * y;
    }
}

// ---------------- launch ----------------
extern "C" void kernel_launch(void* const* d_in, const int* in_sizes, int n_in,
                              void* d_out, int out_size) {
    const float* pos1 = (const float*)d_in[0];
    const float* pos2 = (const float*)d_in[1];
    const float* f1   = (const float*)d_in[2];
    const float* f2   = (const float*)d_in[3];
    const int*   idxp = (const int*)d_in[4];
    const float* W0 = (const float*)d_in[5];
    const float* g0 = (const float*)d_in[6];
    const float* b0 = (const float*)d_in[7];
    const float* W1 = (const float*)d_in[8];
    const float* g1 = (const float*)d_in[9];
    const float* b1 = (const float*)d_in[10];
    const float* W2 = (const float*)d_in[11];
    const float* g2 = (const float*)d_in[12];
    const float* b2 = (const float*)d_in[13];

    cudaFuncSetAttribute(k_prep, cudaFuncAttributeMaxDynamicSharedMemorySize, SMEM_PREP);
    cudaFuncSetAttribute(k_l1,   cudaFuncAttributeMaxDynamicSharedMemorySize, SMEM_L1);
    cudaFuncSetAttribute(k_l2,   cudaFuncAttributeMaxDynamicSharedMemorySize, SMEM_L2);
    cudaFuncSetAttribute(k_out,  cudaFuncAttributeMaxDynamicSharedMemorySize, SMEM_OUT);

    float* outp = (float*)d_out;
    int featOff = out_size - BB*L2C*NN;
    if (featOff < 0) featOff = 0;

    k_wsplit<<<96, 256>>>(W1, W2);                                   // 0
    k_zero<<<1, 512>>>();                                            // 1
    k_prep<<<BB*(NN/16), 128, SMEM_PREP>>>(pos1, pos2, f1, f2, W0);  // 2
    k_stats0<<<PTOT/128, 128>>>(idxp);                               // 3
    k_l1<<<PTOT/512, 512, SMEM_L1>>>(idxp, g0, b0);                  // 4
    k_l2<<<PTOT/256, 512, SMEM_L2>>>(g1, b1);                        // 5
    if (featOff > 0)
        cudaMemcpyAsync(d_out, pos1, (size_t)featOff * sizeof(float),
                        cudaMemcpyDeviceToDevice, 0);
    k_out<<<BB*(NN/64), 256, SMEM_OUT>>>(outp + featOff, g2, b2);    // 6
}

// round 6
// speedup vs baseline: 3.6995x; 1.0981x over previous
#include <cuda_runtime.h>
#include <cuda_fp16.h>
#include <cstdint>

#define BB 4
#define NN 2048
#define KK 32
#define L0 128
#define L1C 128
#define L2C 256
#define PTOT (BB*NN*KK)   /* 262144 */
#define EPSV 1e-5f
#define SLOPE 0.01f

// ---------------- scratch ----------------
__device__ float g_A[BB*NN*L0];          // 4 MB
__device__ float g_D[BB*NN*L0];          // 4 MB
__device__ float g_y1[(size_t)PTOT*L1C]; // 134 MB
__device__ float g_mx[BB*NN*L2C];        // 8 MB
__device__ float g_mn[BB*NN*L2C];        // 8 MB
__device__ float g_s0[2*L0];
__device__ float g_s1[2*L1C];
__device__ float g_s2[2*L2C];
__device__ uint32_t g_W1h2[128*64];      // W1 fp16 half2 packed
__device__ uint32_t g_W2h2[256*64];      // W2 fp16 half2 packed

// ---------------- helpers ----------------
__device__ __forceinline__ uint32_t smem_u32(const void* p) {
    uint32_t a;
    asm("{ .reg .u64 t; cvta.to.shared.u64 t, %1; cvt.u32.u64 %0, t; }" : "=r"(a) : "l"(p));
    return a;
}
__device__ __forceinline__ void ldmx4(uint32_t* r, uint32_t addr) {
    asm volatile("ldmatrix.sync.aligned.m8n8.x4.shared.b16 {%0,%1,%2,%3}, [%4];"
                 : "=r"(r[0]), "=r"(r[1]), "=r"(r[2]), "=r"(r[3]) : "r"(addr));
}
__device__ __forceinline__ void mma16816(float* d, const uint32_t* a, const uint32_t* b) {
    asm volatile(
        "mma.sync.aligned.m16n8k16.row.col.f32.f16.f16.f32 "
        "{%0,%1,%2,%3}, {%4,%5,%6,%7}, {%8,%9}, {%0,%1,%2,%3};"
        : "+f"(d[0]), "+f"(d[1]), "+f"(d[2]), "+f"(d[3])
        : "r"(a[0]), "r"(a[1]), "r"(a[2]), "r"(a[3]), "r"(b[0]), "r"(b[1]));
}
__device__ __forceinline__ void hsplit2(float x, float y, uint32_t& hi, uint32_t& lo) {
    __half hx = __float2half_rn(x), hy = __float2half_rn(y);
    __half lx = __float2half_rn(x - __half2float(hx));
    __half ly = __float2half_rn(y - __half2float(hy));
    __half2 h2 = __halves2half2(hx, hy), l2 = __halves2half2(lx, ly);
    hi = *(uint32_t*)&h2; lo = *(uint32_t*)&l2;
}
// tile rows are 256B (128 halves); XOR-swizzle 16B chunks within each 128B octant
__device__ __forceinline__ uint32_t sw_pair(int row, int c2) {   // c2 = half2 index 0..63
    return (uint32_t)row*256u + (uint32_t)(((c2 >> 2) ^ (row & 7)) << 4) + (uint32_t)((c2 & 3) << 2);
}
__device__ __forceinline__ uint32_t sw_chunk(int row, int cl) {  // cl = 16B chunk 0..15
    return (uint32_t)row*256u + (uint32_t)(((cl ^ (row & 7)) & 15) << 4);
}

// ---------------- k_zw: zero stats + W1/W2 -> fp16 half2 ----------------
__global__ void k_zw(const float* __restrict__ W1, const float* __restrict__ W2) {
    if (blockIdx.x == 0) {
        for (int j = threadIdx.x; j < 1024; j += 256) {
            if (j < 256)      g_s0[j] = 0.f;
            else if (j < 512) g_s1[j - 256] = 0.f;
            else              g_s2[j - 512] = 0.f;
        }
    }
    int i = blockIdx.x * 256 + threadIdx.x;
    if (i < 8192) {
        float2 w = ((const float2*)W1)[i];
        __half2 h = __floats2half2_rn(w.x, w.y);
        g_W1h2[i] = *(uint32_t*)&h;
    } else if (i < 24576) {
        int j = i - 8192;
        float2 w = ((const float2*)W2)[j];
        __half2 h = __floats2half2_rn(w.x, w.y);
        g_W2h2[j] = *(uint32_t*)&h;
    }
}

// ---------------- k_prep: A/D factorization with smem-staged W0 ----------------
#define SW_PITCH 16900   /* 131*129=16899 rounded up so sI is 16B-aligned */
static const int SMEM_PREP = (SW_PITCH + 131*16) * 4;
__global__ void __launch_bounds__(128) k_prep(
        const float* __restrict__ pos1, const float* __restrict__ pos2,
        const float* __restrict__ f1,   const float* __restrict__ f2,
        const float* __restrict__ W0) {
    extern __shared__ float sp[];
    float* sW = sp;               // [131][129]
    float* sI = sp + SW_PITCH;    // [131][16], 16B-aligned
    int blk = blockIdx.x;
    int b  = blk / (NN/16);
    int j0 = (blk % (NN/16)) * 16;
    int tid = threadIdx.x;

    // ---- pass A ----
    for (int i = tid; i < 131*128; i += 128) {
        int o = i / 131, c = i - o*131;
        sW[c*129 + o] = W0[o*259 + c];
    }
    for (int i = tid; i < 131*16; i += 128) {
        int c = i >> 4, jl = i & 15;
        sI[c*16 + jl] = (c < 3) ? pos2[(b*3 + c)*NN + j0 + jl]
                                : f2[(b*128 + (c-3))*NN + j0 + jl];
    }
    __syncthreads();
    {
        float4 acc[4];
        #pragma unroll
        for (int q = 0; q < 4; q++) acc[q] = make_float4(0.f,0.f,0.f,0.f);
        for (int c = 0; c < 131; c++) {
            float wv = sW[c*129 + tid];
            const float4* r = (const float4*)&sI[c*16];
            #pragma unroll
            for (int q = 0; q < 4; q++) {
                float4 rv = r[q];
                acc[q].x = fmaf(wv, rv.x, acc[q].x);
                acc[q].y = fmaf(wv, rv.y, acc[q].y);
                acc[q].z = fmaf(wv, rv.z, acc[q].z);
                acc[q].w = fmaf(wv, rv.w, acc[q].w);
            }
        }
        const float* af = (const float*)acc;
        #pragma unroll
        for (int pt = 0; pt < 16; pt++)
            g_A[((b*NN + j0 + pt) << 7) + tid] = af[pt];
    }
    __syncthreads();

    // ---- pass D ----
    for (int i = tid; i < 131*128; i += 128) {
        int o = i / 131, c = i - o*131;
        int src = (c < 3) ? c : 128 + c;   // 131 + (c-3)
        sW[c*129 + o] = W0[o*259 + src];
    }
    for (int i = tid; i < 131*16; i += 128) {
        int c = i >> 4, jl = i & 15;
        sI[c*16 + jl] = (c < 3) ? -pos1[(b*3 + c)*NN + j0 + jl]
                                : f1[(b*128 + (c-3))*NN + j0 + jl];
    }
    __syncthreads();
    {
        float4 acc[4];
        #pragma unroll
        for (int q = 0; q < 4; q++) acc[q] = make_float4(0.f,0.f,0.f,0.f);
        for (int c = 0; c < 131; c++) {
            float wv = sW[c*129 + tid];
            const float4* r = (const float4*)&sI[c*16];
            #pragma unroll
            for (int q = 0; q < 4; q++) {
                float4 rv = r[q];
                acc[q].x = fmaf(wv, rv.x, acc[q].x);
                acc[q].y = fmaf(wv, rv.y, acc[q].y);
                acc[q].z = fmaf(wv, rv.z, acc[q].z);
                acc[q].w = fmaf(wv, rv.w, acc[q].w);
            }
        }
        const float* af = (const float*)acc;
        #pragma unroll
        for (int pt = 0; pt < 16; pt++)
            g_D[((b*NN + j0 + pt) << 7) + tid] = af[pt];
    }
}

// ---------------- k_stats0: stats of y0 = A[idx] + D ----------------
__global__ void __launch_bounds__(128) k_stats0(const int* __restrict__ idxp) {
    __shared__ int s_idx[128];
    int tid = threadIdx.x;
    int pbase = blockIdx.x * 128;
    s_idx[tid] = idxp[pbase + tid];
    __syncthreads();
    float s = 0.f, ss = 0.f;
    #pragma unroll 4
    for (int i = 0; i < 128; i++) {
        int p = pbase + i;
        int arow = ((p >> 16) * NN + s_idx[i]) << 7;
        int drow = (p >> 5) << 7;
        float y = g_A[arow + tid] + g_D[drow + tid];
        s += y; ss = fmaf(y, y, ss);
    }
    atomicAdd(&g_s0[tid], s);
    atomicAdd(&g_s0[L0 + tid], ss);
}

// ======================= layer 1 =======================
// block: 2 tiles x (256 pts x 128 out) x K=128; 512 thr / 16 warps; warp tile 32x64
// 2-pass: acc = Uh*Wh + Ul*Wh
static const int L1_UH = 4096;                // 256*256B = 65536
static const int L1_UL = L1_UH + 65536;
static const int L1_WH = L1_UL + 65536;       // 128*256B = 32768
static const int SMEM_L1 = L1_WH + 32768;     // 167936

__global__ void __launch_bounds__(512, 1) k_l1(
        const int* __restrict__ idxp,
        const float* __restrict__ gam, const float* __restrict__ bet) {
    extern __shared__ char sm[];
    uint32_t sb = smem_u32(sm);
    float* sA   = (float*)(sm + 0);      // 128
    float* sC   = (float*)(sm + 512);    // 128
    int*   sAR  = (int*)(sm + 1024);     // 512 ints
    float* sSum = (float*)(sm + 3072);   // 128
    float* sSs  = (float*)(sm + 3584);   // 128
    int tid = threadIdx.x, wid = tid >> 5, lane = tid & 31;
    int pblk = blockIdx.x * 512;

    if (tid < 128) {
        const float inv = 1.0f / (float)PTOT;
        float mean = g_s0[tid] * inv;
        float var  = g_s0[128 + tid] * inv - mean * mean;
        float a = gam[tid] * rsqrtf(var + EPSV);
        sA[tid] = a; sC[tid] = bet[tid] - mean * a;
        sSum[tid] = 0.f; sSs[tid] = 0.f;
    }
    {
        int p = pblk + tid;
        sAR[tid] = ((p >> 16) * NN + idxp[p]) << 7;
    }
    __syncthreads();

    // W tile (128 rows, hi only), loaded once
    for (int i = tid; i < 8192; i += 512) {
        int o = i >> 6, c2 = i & 63;
        *(uint32_t*)(sm + L1_WH + sw_pair(o, c2)) = g_W1h2[i];
    }

    int mr = (wid & 7) * 32, nr = (wid >> 3) * 64;
    int aRow = lane & 15, aSel = lane >> 4;
    int bRow = (lane & 7) + ((lane >> 4) << 3), bSel = (lane >> 3) & 1;

    #pragma unroll 1
    for (int t = 0; t < 2; t++) {
        int pbase = pblk + t * 256;
        if (t) __syncthreads();

        // U tiles (256 rows): lrelu(BN0(A[idx]+D)) split hi/lo
        for (int i = tid; i < 16384; i += 512) {
            int pl = i >> 6, c2 = i & 63;
            const float2* ar = (const float2*)(g_A + sAR[t*256 + pl]);
            const float2* dr = (const float2*)(g_D + (((pbase + pl) >> 5) << 7));
            float2 av = ar[c2], dv = dr[c2];
            int c = c2 << 1;
            float u0 = fmaf(sA[c],     av.x + dv.x, sC[c]);
            float u1 = fmaf(sA[c + 1], av.y + dv.y, sC[c + 1]);
            u0 = (u0 > 0.f) ? u0 : SLOPE * u0;
            u1 = (u1 > 0.f) ? u1 : SLOPE * u1;
            uint32_t hi, lo; hsplit2(u0, u1, hi, lo);
            uint32_t off = sw_pair(pl, c2);
            *(uint32_t*)(sm + L1_UH + off) = hi;
            *(uint32_t*)(sm + L1_UL + off) = lo;
        }
        __syncthreads();

        float acc[2][8][4];
        #pragma unroll
        for (int mt = 0; mt < 2; mt++)
            #pragma unroll
            for (int nt = 0; nt < 8; nt++)
                #pragma unroll
                for (int q = 0; q < 4; q++) acc[mt][nt][q] = 0.f;

        for (int ks = 0; ks < 8; ks++) {
            uint32_t ah[2][4], al[2][4];
            int clA = 2*ks + aSel;
            #pragma unroll
            for (int mt = 0; mt < 2; mt++) {
                int r = mr + mt*16 + aRow;
                uint32_t off = sw_chunk(r, clA);
                ldmx4(ah[mt], sb + L1_UH + off);
                ldmx4(al[mt], sb + L1_UL + off);
            }
            int clB = 2*ks + bSel;
            #pragma unroll
            for (int q = 0; q < 4; q++) {
                int n = nr + q*16 + bRow;
                uint32_t bh[4];
                ldmx4(bh, sb + L1_WH + sw_chunk(n, clB));
                #pragma unroll
                for (int mt = 0; mt < 2; mt++) {
                    mma16816(acc[mt][2*q],     ah[mt], bh);
                    mma16816(acc[mt][2*q + 1], ah[mt], bh + 2);
                    mma16816(acc[mt][2*q],     al[mt], bh);
                    mma16816(acc[mt][2*q + 1], al[mt], bh + 2);
                }
            }
        }

        // ---- register epilogue: direct y1 stores + channel sums via shuffles ----
        #pragma unroll
        for (int mt = 0; mt < 2; mt++) {
            int r = mr + mt*16 + (lane >> 2);
            #pragma unroll
            for (int nt = 0; nt < 8; nt++) {
                int c = nr + nt*8 + ((lane & 3) << 1);
                *(float2*)&g_y1[(size_t)(pbase + r)*128 + c] =
                    make_float2(acc[mt][nt][0], acc[mt][nt][1]);
                *(float2*)&g_y1[(size_t)(pbase + r + 8)*128 + c] =
                    make_float2(acc[mt][nt][2], acc[mt][nt][3]);
            }
        }
        #pragma unroll
        for (int nt = 0; nt < 8; nt++) {
            float s0 = acc[0][nt][0] + acc[0][nt][2] + acc[1][nt][0] + acc[1][nt][2];
            float s1 = acc[0][nt][1] + acc[0][nt][3] + acc[1][nt][1] + acc[1][nt][3];
            float q0 = acc[0][nt][0]*acc[0][nt][0] + acc[0][nt][2]*acc[0][nt][2]
                     + acc[1][nt][0]*acc[1][nt][0] + acc[1][nt][2]*acc[1][nt][2];
            float q1 = acc[0][nt][1]*acc[0][nt][1] + acc[0][nt][3]*acc[0][nt][3]
                     + acc[1][nt][1]*acc[1][nt][1] + acc[1][nt][3]*acc[1][nt][3];
            #pragma unroll
            for (int d = 4; d < 32; d <<= 1) {
                s0 += __shfl_xor_sync(0xFFFFFFFF, s0, d);
                s1 += __shfl_xor_sync(0xFFFFFFFF, s1, d);
                q0 += __shfl_xor_sync(0xFFFFFFFF, q0, d);
                q1 += __shfl_xor_sync(0xFFFFFFFF, q1, d);
            }
            if (lane < 4) {
                int c = nr + nt*8 + (lane << 1);
                atomicAdd(&sSum[c], s0);  atomicAdd(&sSum[c + 1], s1);
                atomicAdd(&sSs[c],  q0);  atomicAdd(&sSs[c + 1],  q1);
            }
        }
    }
    __syncthreads();
    if (tid < 128) {
        atomicAdd(&g_s1[tid],       sSum[tid]);
        atomicAdd(&g_s1[128 + tid], sSs[tid]);
    }
}

// ======================= layer 2 =======================
// block: 2 tiles x (128 pts x 256 out) x K=128; 512 thr / 16 warps; warp tile 32x64
// 2-pass: acc = Uh*Wh + Ul*Wh
static const int L2_UH = 4096;                // 128*256B = 32768
static const int L2_UL = L2_UH + 32768;
static const int L2_WH = L2_UL + 32768;       // 256*256B = 65536
static const int SMEM_L2 = L2_WH + 65536;     // 135168

__global__ void __launch_bounds__(512, 1) k_l2(
        const float* __restrict__ gam, const float* __restrict__ bet) {
    extern __shared__ char sm[];
    uint32_t sb = smem_u32(sm);
    float* sA   = (float*)(sm + 0);      // 128
    float* sC   = (float*)(sm + 512);    // 128
    float* sSum = (float*)(sm + 1024);   // 256
    float* sSs  = (float*)(sm + 2048);   // 256
    int tid = threadIdx.x, wid = tid >> 5, lane = tid & 31;
    int pblk = blockIdx.x * 256;

    if (tid < 128) {
        const float inv = 1.0f / (float)PTOT;
        float mean = g_s1[tid] * inv;
        float var  = g_s1[128 + tid] * inv - mean * mean;
        float a = gam[tid] * rsqrtf(var + EPSV);
        sA[tid] = a; sC[tid] = bet[tid] - mean * a;
    }
    if (tid < 256) { sSum[tid] = 0.f; sSs[tid] = 0.f; }
    __syncthreads();

    // W tile (256 rows, hi only), loaded once
    for (int i = tid; i < 16384; i += 512) {
        int o = i >> 6, c2 = i & 63;
        *(uint32_t*)(sm + L2_WH + sw_pair(o, c2)) = g_W2h2[i];
    }

    int mr = (wid & 3) * 32, nr = (wid >> 2) * 64;
    int aRow = lane & 15, aSel = lane >> 4;
    int bRow = (lane & 7) + ((lane >> 4) << 3), bSel = (lane >> 3) & 1;

    #pragma unroll 1
    for (int t = 0; t < 2; t++) {
        int pbase = pblk + t * 128;
        if (t) __syncthreads();

        // U tiles (128 rows): lrelu(BN1(y1)) split hi/lo
        for (int i = tid; i < 8192; i += 512) {
            int pl = i >> 6, c2 = i & 63;
            float2 y = ((const float2*)(g_y1 + (size_t)(pbase + pl)*128))[c2];
            int c = c2 << 1;
            float u0 = fmaf(sA[c],     y.x, sC[c]);
            float u1 = fmaf(sA[c + 1], y.y, sC[c + 1]);
            u0 = (u0 > 0.f) ? u0 : SLOPE * u0;
            u1 = (u1 > 0.f) ? u1 : SLOPE * u1;
            uint32_t hi, lo; hsplit2(u0, u1, hi, lo);
            uint32_t off = sw_pair(pl, c2);
            *(uint32_t*)(sm + L2_UH + off) = hi;
            *(uint32_t*)(sm + L2_UL + off) = lo;
        }
        __syncthreads();

        float acc[2][8][4];
        #pragma unroll
        for (int mt = 0; mt < 2; mt++)
            #pragma unroll
            for (int nt = 0; nt < 8; nt++)
                #pragma unroll
                for (int q = 0; q < 4; q++) acc[mt][nt][q] = 0.f;

        for (int ks = 0; ks < 8; ks++) {
            uint32_t ah[2][4], al[2][4];
            int clA = 2*ks + aSel;
            #pragma unroll
            for (int mt = 0; mt < 2; mt++) {
                int r = mr + mt*16 + aRow;
                uint32_t off = sw_chunk(r, clA);
                ldmx4(ah[mt], sb + L2_UH + off);
                ldmx4(al[mt], sb + L2_UL + off);
            }
            int clB = 2*ks + bSel;
            #pragma unroll
            for (int q = 0; q < 4; q++) {
                int n = nr + q*16 + bRow;
                uint32_t bh[4];
                ldmx4(bh, sb + L2_WH + sw_chunk(n, clB));
                #pragma unroll
                for (int mt = 0; mt < 2; mt++) {
                    mma16816(acc[mt][2*q],     ah[mt], bh);
                    mma16816(acc[mt][2*q + 1], ah[mt], bh + 2);
                    mma16816(acc[mt][2*q],     al[mt], bh);
                    mma16816(acc[mt][2*q + 1], al[mt], bh + 2);
                }
            }
        }

        // ---- register epilogue: warp owns one K-group (32 pts) x 64 ch ----
        int bn = (pbase >> 5) + (wid & 3);
        #pragma unroll
        for (int nt = 0; nt < 8; nt++) {
            float mx0 = fmaxf(fmaxf(acc[0][nt][0], acc[0][nt][2]),
                              fmaxf(acc[1][nt][0], acc[1][nt][2]));
            float mx1 = fmaxf(fmaxf(acc[0][nt][1], acc[0][nt][3]),
                              fmaxf(acc[1][nt][1], acc[1][nt][3]));
            float mn0 = fminf(fminf(acc[0][nt][0], acc[0][nt][2]),
                              fminf(acc[1][nt][0], acc[1][nt][2]));
            float mn1 = fminf(fminf(acc[0][nt][1], acc[0][nt][3]),
                              fminf(acc[1][nt][1], acc[1][nt][3]));
            float s0 = acc[0][nt][0] + acc[0][nt][2] + acc[1][nt][0] + acc[1][nt][2];
            float s1 = acc[0][nt][1] + acc[0][nt][3] + acc[1][nt][1] + acc[1][nt][3];
            float q0 = acc[0][nt][0]*acc[0][nt][0] + acc[0][nt][2]*acc[0][nt][2]
                     + acc[1][nt][0]*acc[1][nt][0] + acc[1][nt][2]*acc[1][nt][2];
            float q1 = acc[0][nt][1]*acc[0][nt][1] + acc[0][nt][3]*acc[0][nt][3]
                     + acc[1][nt][1]*acc[1][nt][1] + acc[1][nt][3]*acc[1][nt][3];
            #pragma unroll
            for (int d = 4; d < 32; d <<= 1) {
                mx0 = fmaxf(mx0, __shfl_xor_sync(0xFFFFFFFF, mx0, d));
                mx1 = fmaxf(mx1, __shfl_xor_sync(0xFFFFFFFF, mx1, d));
                mn0 = fminf(mn0, __shfl_xor_sync(0xFFFFFFFF, mn0, d));
                mn1 = fminf(mn1, __shfl_xor_sync(0xFFFFFFFF, mn1, d));
                s0 += __shfl_xor_sync(0xFFFFFFFF, s0, d);
                s1 += __shfl_xor_sync(0xFFFFFFFF, s1, d);
                q0 += __shfl_xor_sync(0xFFFFFFFF, q0, d);
                q1 += __shfl_xor_sync(0xFFFFFFFF, q1, d);
            }
            if (lane < 4) {
                int c = nr + nt*8 + (lane << 1);
                *(float2*)&g_mx[bn*256 + c] = make_float2(mx0, mx1);
                *(float2*)&g_mn[bn*256 + c] = make_float2(mn0, mn1);
                atomicAdd(&sSum[c], s0);  atomicAdd(&sSum[c + 1], s1);
                atomicAdd(&sSs[c],  q0);  atomicAdd(&sSs[c + 1],  q1);
            }
        }
    }
    __syncthreads();
    if (tid < 256) {
        atomicAdd(&g_s2[tid],       sSum[tid]);
        atomicAdd(&g_s2[256 + tid], sSs[tid]);
    }
}

// ---------------- k_out ----------------
static const int SMEM_OUT = 2 * 64 * 257 * 4;
__global__ void __launch_bounds__(256) k_out(float* __restrict__ out,
        const float* __restrict__ gam, const float* __restrict__ bet) {
    extern __shared__ float smf[];
    float* sMx = smf;
    float* sMn = smf + 64*257;
    __shared__ float sA2[256], sC2[256];
    int tid = threadIdx.x;
    {
        const float inv = 1.0f / (float)PTOT;
        float mean = g_s2[tid] * inv;
        float var  = g_s2[256 + tid] * inv - mean * mean;
        float a = gam[tid] * rsqrtf(var + EPSV);
        sA2[tid] = a; sC2[tid] = bet[tid] - mean * a;
    }
    int b  = blockIdx.x >> 5;
    int n0 = (blockIdx.x & 31) * 64;
    for (int i = tid; i < 64*256; i += 256) {
        int nl = i >> 8, o = i & 255;
        int g = (b*NN + n0 + nl)*256 + o;
        sMx[nl*257 + o] = g_mx[g];
        sMn[nl*257 + o] = g_mn[g];
    }
    __syncthreads();
    for (int i = tid; i < 64*256; i += 256) {
        int o = i >> 6, nl = i & 63;
        float a = sA2[o], c = sC2[o];
        float z = (a >= 0.f) ? sMx[nl*257 + o] : sMn[nl*257 + o];
        float y = fmaf(a, z, c);
        out[(b*256 + o)*NN + n0 + nl] = (y > 0.f) ? y : SLOPE * y;
    }
}

// ---------------- launch ----------------
extern "C" void kernel_launch(void* const* d_in, const int* in_sizes, int n_in,
                              void* d_out, int out_size) {
    const float* pos1 = (const float*)d_in[0];
    const float* pos2 = (const float*)d_in[1];
    const float* f1   = (const float*)d_in[2];
    const float* f2   = (const float*)d_in[3];
    const int*   idxp = (const int*)d_in[4];
    const float* W0 = (const float*)d_in[5];
    const float* g0 = (const float*)d_in[6];
    const float* b0 = (const float*)d_in[7];
    const float* W1 = (const float*)d_in[8];
    const float* g1 = (const float*)d_in[9];
    const float* b1 = (const float*)d_in[10];
    const float* W2 = (const float*)d_in[11];
    const float* g2 = (const float*)d_in[12];
    const float* b2 = (const float*)d_in[13];

    cudaFuncSetAttribute(k_prep, cudaFuncAttributeMaxDynamicSharedMemorySize, SMEM_PREP);
    cudaFuncSetAttribute(k_l1,   cudaFuncAttributeMaxDynamicSharedMemorySize, SMEM_L1);
    cudaFuncSetAttribute(k_l2,   cudaFuncAttributeMaxDynamicSharedMemorySize, SMEM_L2);
    cudaFuncSetAttribute(k_out,  cudaFuncAttributeMaxDynamicSharedMemorySize, SMEM_OUT);

    float* outp = (float*)d_out;
    int featOff = out_size - BB*L2C*NN;
    if (featOff < 0) featOff = 0;

    k_zw<<<96, 256>>>(W1, W2);                                       // 0
    k_prep<<<BB*(NN/16), 128, SMEM_PREP>>>(pos1, pos2, f1, f2, W0);  // 1
    k_stats0<<<PTOT/128, 128>>>(idxp);                               // 2
    k_l1<<<PTOT/512, 512, SMEM_L1>>>(idxp, g0, b0);                  // 3 (profiled)
    k_l2<<<PTOT/256, 512, SMEM_L2>>>(g1, b1);                        // 4
    if (featOff > 0)
        cudaMemcpyAsync(d_out, pos1, (size_t)featOff * sizeof(float),
                        cudaMemcpyDeviceToDevice, 0);
    k_out<<<BB*(NN/64), 256, SMEM_OUT>>>(outp + featOff, g2, b2);    // 5
}

// round 7
// speedup vs baseline: 3.8977x; 1.0536x over previous
#include <cuda_runtime.h>
#include <cuda_fp16.h>
#include <cstdint>

#define BB 4
#define NN 2048
#define KK 32
#define L0 128
#define L1C 128
#define L2C 256
#define PTOT (BB*NN*KK)   /* 262144 */
#define EPSV 1e-5f
#define SLOPE 0.01f

// ---------------- scratch ----------------
__device__ float g_A[BB*NN*L0];              // 4 MB
__device__ float g_D[BB*NN*L0];              // 4 MB
__device__ uint32_t g_y1h[(size_t)PTOT*64];  // 67 MB : y1 as half2 pairs [pt][c/2]
__device__ float g_mx[BB*NN*L2C];            // 8 MB
__device__ float g_mn[BB*NN*L2C];            // 8 MB
__device__ float g_s0[2*L0];
__device__ float g_s1[2*L1C];
__device__ float g_s2[2*L2C];
__device__ uint32_t g_W1h2[128*64];          // W1 fp16 half2 packed
__device__ uint32_t g_W2h2[256*64];          // W2 fp16 half2 packed

// ---------------- helpers ----------------
__device__ __forceinline__ uint32_t smem_u32(const void* p) {
    uint32_t a;
    asm("{ .reg .u64 t; cvta.to.shared.u64 t, %1; cvt.u32.u64 %0, t; }" : "=r"(a) : "l"(p));
    return a;
}
__device__ __forceinline__ void ldmx4(uint32_t* r, uint32_t addr) {
    asm volatile("ldmatrix.sync.aligned.m8n8.x4.shared.b16 {%0,%1,%2,%3}, [%4];"
                 : "=r"(r[0]), "=r"(r[1]), "=r"(r[2]), "=r"(r[3]) : "r"(addr));
}
__device__ __forceinline__ void mma16816(float* d, const uint32_t* a, const uint32_t* b) {
    asm volatile(
        "mma.sync.aligned.m16n8k16.row.col.f32.f16.f16.f32 "
        "{%0,%1,%2,%3}, {%4,%5,%6,%7}, {%8,%9}, {%0,%1,%2,%3};"
        : "+f"(d[0]), "+f"(d[1]), "+f"(d[2]), "+f"(d[3])
        : "r"(a[0]), "r"(a[1]), "r"(a[2]), "r"(a[3]), "r"(b[0]), "r"(b[1]));
}
__device__ __forceinline__ void hsplit2(float x, float y, uint32_t& hi, uint32_t& lo) {
    __half hx = __float2half_rn(x), hy = __float2half_rn(y);
    __half lx = __float2half_rn(x - __half2float(hx));
    __half ly = __float2half_rn(y - __half2float(hy));
    __half2 h2 = __halves2half2(hx, hy), l2 = __halves2half2(lx, ly);
    hi = *(uint32_t*)&h2; lo = *(uint32_t*)&l2;
}
// tile rows are 256B (128 halves); XOR-swizzle 16B chunks within each 128B octant
__device__ __forceinline__ uint32_t sw_pair(int row, int c2) {   // c2 = half2 index 0..63
    return (uint32_t)row*256u + (uint32_t)(((c2 >> 2) ^ (row & 7)) << 4) + (uint32_t)((c2 & 3) << 2);
}
__device__ __forceinline__ uint32_t sw_chunk(int row, int cl) {  // cl = 16B chunk 0..15
    return (uint32_t)row*256u + (uint32_t)(((cl ^ (row & 7)) & 15) << 4);
}

// ---------------- k_zw: zero stats + W1/W2 -> fp16 half2 ----------------
__global__ void k_zw(const float* __restrict__ W1, const float* __restrict__ W2) {
    if (blockIdx.x == 0) {
        for (int j = threadIdx.x; j < 1024; j += 256) {
            if (j < 256)      g_s0[j] = 0.f;
            else if (j < 512) g_s1[j - 256] = 0.f;
            else              g_s2[j - 512] = 0.f;
        }
    }
    int i = blockIdx.x * 256 + threadIdx.x;
    if (i < 8192) {
        float2 w = ((const float2*)W1)[i];
        __half2 h = __floats2half2_rn(w.x, w.y);
        g_W1h2[i] = *(uint32_t*)&h;
    } else if (i < 24576) {
        int j = i - 8192;
        float2 w = ((const float2*)W2)[j];
        __half2 h = __floats2half2_rn(w.x, w.y);
        g_W2h2[j] = *(uint32_t*)&h;
    }
}

// ---------------- k_prep: A/D factorization with smem-staged W0 ----------------
#define SW_PITCH 16900   /* 131*129=16899 rounded up so sI is 16B-aligned */
static const int SMEM_PREP = (SW_PITCH + 131*16) * 4;
__global__ void __launch_bounds__(128) k_prep(
        const float* __restrict__ pos1, const float* __restrict__ pos2,
        const float* __restrict__ f1,   const float* __restrict__ f2,
        const float* __restrict__ W0) {
    extern __shared__ float sp[];
    float* sW = sp;               // [131][129]
    float* sI = sp + SW_PITCH;    // [131][16], 16B-aligned
    int blk = blockIdx.x;
    int b  = blk / (NN/16);
    int j0 = (blk % (NN/16)) * 16;
    int tid = threadIdx.x;

    // ---- pass A ----
    for (int i = tid; i < 131*128; i += 128) {
        int o = i / 131, c = i - o*131;
        sW[c*129 + o] = W0[o*259 + c];
    }
    for (int i = tid; i < 131*16; i += 128) {
        int c = i >> 4, jl = i & 15;
        sI[c*16 + jl] = (c < 3) ? pos2[(b*3 + c)*NN + j0 + jl]
                                : f2[(b*128 + (c-3))*NN + j0 + jl];
    }
    __syncthreads();
    {
        float4 acc[4];
        #pragma unroll
        for (int q = 0; q < 4; q++) acc[q] = make_float4(0.f,0.f,0.f,0.f);
        for (int c = 0; c < 131; c++) {
            float wv = sW[c*129 + tid];
            const float4* r = (const float4*)&sI[c*16];
            #pragma unroll
            for (int q = 0; q < 4; q++) {
                float4 rv = r[q];
                acc[q].x = fmaf(wv, rv.x, acc[q].x);
                acc[q].y = fmaf(wv, rv.y, acc[q].y);
                acc[q].z = fmaf(wv, rv.z, acc[q].z);
                acc[q].w = fmaf(wv, rv.w, acc[q].w);
            }
        }
        const float* af = (const float*)acc;
        #pragma unroll
        for (int pt = 0; pt < 16; pt++)
            g_A[((b*NN + j0 + pt) << 7) + tid] = af[pt];
    }
    __syncthreads();

    // ---- pass D ----
    for (int i = tid; i < 131*128; i += 128) {
        int o = i / 131, c = i - o*131;
        int src = (c < 3) ? c : 128 + c;   // 131 + (c-3)
        sW[c*129 + o] = W0[o*259 + src];
    }
    for (int i = tid; i < 131*16; i += 128) {
        int c = i >> 4, jl = i & 15;
        sI[c*16 + jl] = (c < 3) ? -pos1[(b*3 + c)*NN + j0 + jl]
                                : f1[(b*128 + (c-3))*NN + j0 + jl];
    }
    __syncthreads();
    {
        float4 acc[4];
        #pragma unroll
        for (int q = 0; q < 4; q++) acc[q] = make_float4(0.f,0.f,0.f,0.f);
        for (int c = 0; c < 131; c++) {
            float wv = sW[c*129 + tid];
            const float4* r = (const float4*)&sI[c*16];
            #pragma unroll
            for (int q = 0; q < 4; q++) {
                float4 rv = r[q];
                acc[q].x = fmaf(wv, rv.x, acc[q].x);
                acc[q].y = fmaf(wv, rv.y, acc[q].y);
                acc[q].z = fmaf(wv, rv.z, acc[q].z);
                acc[q].w = fmaf(wv, rv.w, acc[q].w);
            }
        }
        const float* af = (const float*)acc;
        #pragma unroll
        for (int pt = 0; pt < 16; pt++)
            g_D[((b*NN + j0 + pt) << 7) + tid] = af[pt];
    }
}

// ---------------- k_stats0: stats of y0 = A[idx] + D ----------------
__global__ void __launch_bounds__(128) k_stats0(const int* __restrict__ idxp) {
    __shared__ int s_idx[128];
    int tid = threadIdx.x;
    int pbase = blockIdx.x * 128;
    s_idx[tid] = idxp[pbase + tid];
    __syncthreads();
    float s = 0.f, ss = 0.f;
    #pragma unroll 4
    for (int i = 0; i < 128; i++) {
        int p = pbase + i;
        int arow = ((p >> 16) * NN + s_idx[i]) << 7;
        int drow = (p >> 5) << 7;
        float y = g_A[arow + tid] + g_D[drow + tid];
        s += y; ss = fmaf(y, y, ss);
    }
    atomicAdd(&g_s0[tid], s);
    atomicAdd(&g_s0[L0 + tid], ss);
}

// ======================= layer 1 =======================
// block: 4 tiles x (128 pts x 128 out) x K=128; 256 thr / 8 warps; 2 CTAs/SM
// warp tile 32x64; 2-pass: acc = Uh*Wh + Ul*Wh
static const int L1_UH = 4096;                // 128*256B = 32768
static const int L1_UL = L1_UH + 32768;
static const int L1_WH = L1_UL + 32768;
static const int SMEM_L1 = L1_WH + 32768;     // 102400

__global__ void __launch_bounds__(256, 2) k_l1(
        const int* __restrict__ idxp,
        const float* __restrict__ gam, const float* __restrict__ bet) {
    extern __shared__ char sm[];
    uint32_t sb = smem_u32(sm);
    float* sA   = (float*)(sm + 0);      // 128
    float* sC   = (float*)(sm + 512);    // 128
    int*   sAR  = (int*)(sm + 1024);     // 512 ints
    float* sSum = (float*)(sm + 3072);   // 128
    float* sSs  = (float*)(sm + 3584);   // 128
    int tid = threadIdx.x, wid = tid >> 5, lane = tid & 31;
    int pblk = blockIdx.x * 512;

    if (tid < 128) {
        const float inv = 1.0f / (float)PTOT;
        float mean = g_s0[tid] * inv;
        float var  = g_s0[128 + tid] * inv - mean * mean;
        float a = gam[tid] * rsqrtf(var + EPSV);
        sA[tid] = a; sC[tid] = bet[tid] - mean * a;
        sSum[tid] = 0.f; sSs[tid] = 0.f;
    }
    for (int j = tid; j < 512; j += 256) {
        int p = pblk + j;
        sAR[j] = ((p >> 16) * NN + idxp[p]) << 7;
    }
    __syncthreads();

    // W tile (128 rows, hi only), loaded once
    for (int i = tid; i < 8192; i += 256) {
        int o = i >> 6, c2 = i & 63;
        *(uint32_t*)(sm + L1_WH + sw_pair(o, c2)) = g_W1h2[i];
    }

    int mr = (wid & 3) * 32, nr = (wid >> 2) * 64;
    int aRow = lane & 15, aSel = lane >> 4;
    int bRow = (lane & 7) + ((lane >> 4) << 3), bSel = (lane >> 3) & 1;

    #pragma unroll 1
    for (int t = 0; t < 4; t++) {
        int pbase = pblk + t * 128;
        if (t) __syncthreads();

        // U tile (128 rows): lrelu(BN0(A[idx]+D)) split hi/lo
        for (int i = tid; i < 8192; i += 256) {
            int pl = i >> 6, c2 = i & 63;
            const float2* ar = (const float2*)(g_A + sAR[t*128 + pl]);
            const float2* dr = (const float2*)(g_D + (((pbase + pl) >> 5) << 7));
            float2 av = ar[c2], dv = dr[c2];
            int c = c2 << 1;
            float u0 = fmaf(sA[c],     av.x + dv.x, sC[c]);
            float u1 = fmaf(sA[c + 1], av.y + dv.y, sC[c + 1]);
            u0 = (u0 > 0.f) ? u0 : SLOPE * u0;
            u1 = (u1 > 0.f) ? u1 : SLOPE * u1;
            uint32_t hi, lo; hsplit2(u0, u1, hi, lo);
            uint32_t off = sw_pair(pl, c2);
            *(uint32_t*)(sm + L1_UH + off) = hi;
            *(uint32_t*)(sm + L1_UL + off) = lo;
        }
        __syncthreads();

        float acc[2][8][4];
        #pragma unroll
        for (int mt = 0; mt < 2; mt++)
            #pragma unroll
            for (int nt = 0; nt < 8; nt++)
                #pragma unroll
                for (int q = 0; q < 4; q++) acc[mt][nt][q] = 0.f;

        for (int ks = 0; ks < 8; ks++) {
            uint32_t ah[2][4], al[2][4];
            int clA = 2*ks + aSel;
            #pragma unroll
            for (int mt = 0; mt < 2; mt++) {
                int r = mr + mt*16 + aRow;
                uint32_t off = sw_chunk(r, clA);
                ldmx4(ah[mt], sb + L1_UH + off);
                ldmx4(al[mt], sb + L1_UL + off);
            }
            int clB = 2*ks + bSel;
            #pragma unroll
            for (int q = 0; q < 4; q++) {
                int n = nr + q*16 + bRow;
                uint32_t bh[4];
                ldmx4(bh, sb + L1_WH + sw_chunk(n, clB));
                #pragma unroll
                for (int mt = 0; mt < 2; mt++) {
                    mma16816(acc[mt][2*q],     ah[mt], bh);
                    mma16816(acc[mt][2*q + 1], ah[mt], bh + 2);
                    mma16816(acc[mt][2*q],     al[mt], bh);
                    mma16816(acc[mt][2*q + 1], al[mt], bh + 2);
                }
            }
        }

        // ---- register epilogue: y1 -> half2 pairs + channel sums via shuffles ----
        #pragma unroll
        for (int mt = 0; mt < 2; mt++) {
            int r = mr + mt*16 + (lane >> 2);
            #pragma unroll
            for (int nt = 0; nt < 8; nt++) {
                int c2 = (nr >> 1) + nt*4 + (lane & 3);
                __half2 h0 = __floats2half2_rn(acc[mt][nt][0], acc[mt][nt][1]);
                __half2 h1 = __floats2half2_rn(acc[mt][nt][2], acc[mt][nt][3]);
                g_y1h[(size_t)(pbase + r)*64 + c2]     = *(uint32_t*)&h0;
                g_y1h[(size_t)(pbase + r + 8)*64 + c2] = *(uint32_t*)&h1;
            }
        }
        #pragma unroll
        for (int nt = 0; nt < 8; nt++) {
            float s0 = acc[0][nt][0] + acc[0][nt][2] + acc[1][nt][0] + acc[1][nt][2];
            float s1 = acc[0][nt][1] + acc[0][nt][3] + acc[1][nt][1] + acc[1][nt][3];
            float q0 = acc[0][nt][0]*acc[0][nt][0] + acc[0][nt][2]*acc[0][nt][2]
                     + acc[1][nt][0]*acc[1][nt][0] + acc[1][nt][2]*acc[1][nt][2];
            float q1 = acc[0][nt][1]*acc[0][nt][1] + acc[0][nt][3]*acc[0][nt][3]
                     + acc[1][nt][1]*acc[1][nt][1] + acc[1][nt][3]*acc[1][nt][3];
            #pragma unroll
            for (int d = 4; d < 32; d <<= 1) {
                s0 += __shfl_xor_sync(0xFFFFFFFF, s0, d);
                s1 += __shfl_xor_sync(0xFFFFFFFF, s1, d);
                q0 += __shfl_xor_sync(0xFFFFFFFF, q0, d);
                q1 += __shfl_xor_sync(0xFFFFFFFF, q1, d);
            }
            if (lane < 4) {
                int c = nr + nt*8 + (lane << 1);
                atomicAdd(&sSum[c], s0);  atomicAdd(&sSum[c + 1], s1);
                atomicAdd(&sSs[c],  q0);  atomicAdd(&sSs[c + 1],  q1);
            }
        }
    }
    __syncthreads();
    if (tid < 128) {
        atomicAdd(&g_s1[tid],       sSum[tid]);
        atomicAdd(&g_s1[128 + tid], sSs[tid]);
    }
}

// ======================= layer 2 =======================
// block: 4 tiles x (128 pts x 128 out-half) x K=128; 256 thr / 8 warps; 2 CTAs/SM
// grid = 2 * PTOT/512; even/odd block handles channel half
static const int L2_UH = 4096;
static const int L2_UL = L2_UH + 32768;
static const int L2_WH = L2_UL + 32768;
static const int SMEM_L2 = L2_WH + 32768;     // 102400

__global__ void __launch_bounds__(256, 2) k_l2(
        const float* __restrict__ gam, const float* __restrict__ bet) {
    extern __shared__ char sm[];
    uint32_t sb = smem_u32(sm);
    float* sA   = (float*)(sm + 0);      // 128
    float* sC   = (float*)(sm + 512);    // 128
    float* sSum = (float*)(sm + 1024);   // 128 (local channel half)
    float* sSs  = (float*)(sm + 1536);   // 128
    int tid = threadIdx.x, wid = tid >> 5, lane = tid & 31;
    int pblk = (blockIdx.x >> 1) * 512;
    int nh   = (blockIdx.x & 1) * 128;   // channel-half offset

    if (tid < 128) {
        const float inv = 1.0f / (float)PTOT;
        float mean = g_s1[tid] * inv;
        float var  = g_s1[128 + tid] * inv - mean * mean;
        float a = gam[tid] * rsqrtf(var + EPSV);
        sA[tid] = a; sC[tid] = bet[tid] - mean * a;
        sSum[tid] = 0.f; sSs[tid] = 0.f;
    }
    __syncthreads();

    // W tile: rows nh..nh+127 of W2
    for (int i = tid; i < 8192; i += 256) {
        int o = i >> 6, c2 = i & 63;
        *(uint32_t*)(sm + L2_WH + sw_pair(o, c2)) = g_W2h2[(nh + o)*64 + c2];
    }

    int mr = (wid & 3) * 32, nr = (wid >> 2) * 64;
    int aRow = lane & 15, aSel = lane >> 4;
    int bRow = (lane & 7) + ((lane >> 4) << 3), bSel = (lane >> 3) & 1;

    #pragma unroll 1
    for (int t = 0; t < 4; t++) {
        int pbase = pblk + t * 128;
        if (t) __syncthreads();

        // U tile: lrelu(BN1(y1)) from half2-packed y1
        for (int i = tid; i < 8192; i += 256) {
            int pl = i >> 6, c2 = i & 63;
            uint32_t yy = g_y1h[(size_t)(pbase + pl)*64 + c2];
            float2 y = __half22float2(*(__half2*)&yy);
            int c = c2 << 1;
            float u0 = fmaf(sA[c],     y.x, sC[c]);
            float u1 = fmaf(sA[c + 1], y.y, sC[c + 1]);
            u0 = (u0 > 0.f) ? u0 : SLOPE * u0;
            u1 = (u1 > 0.f) ? u1 : SLOPE * u1;
            uint32_t hi, lo; hsplit2(u0, u1, hi, lo);
            uint32_t off = sw_pair(pl, c2);
            *(uint32_t*)(sm + L2_UH + off) = hi;
            *(uint32_t*)(sm + L2_UL + off) = lo;
        }
        __syncthreads();

        float acc[2][8][4];
        #pragma unroll
        for (int mt = 0; mt < 2; mt++)
            #pragma unroll
            for (int nt = 0; nt < 8; nt++)
                #pragma unroll
                for (int q = 0; q < 4; q++) acc[mt][nt][q] = 0.f;

        for (int ks = 0; ks < 8; ks++) {
            uint32_t ah[2][4], al[2][4];
            int clA = 2*ks + aSel;
            #pragma unroll
            for (int mt = 0; mt < 2; mt++) {
                int r = mr + mt*16 + aRow;
                uint32_t off = sw_chunk(r, clA);
                ldmx4(ah[mt], sb + L2_UH + off);
                ldmx4(al[mt], sb + L2_UL + off);
            }
            int clB = 2*ks + bSel;
            #pragma unroll
            for (int q = 0; q < 4; q++) {
                int n = nr + q*16 + bRow;
                uint32_t bh[4];
                ldmx4(bh, sb + L2_WH + sw_chunk(n, clB));
                #pragma unroll
                for (int mt = 0; mt < 2; mt++) {
                    mma16816(acc[mt][2*q],     ah[mt], bh);
                    mma16816(acc[mt][2*q + 1], ah[mt], bh + 2);
                    mma16816(acc[mt][2*q],     al[mt], bh);
                    mma16816(acc[mt][2*q + 1], al[mt], bh + 2);
                }
            }
        }

        // ---- register epilogue: warp owns one K-group (32 pts) x 64 ch ----
        int bn = (pbase >> 5) + (wid & 3);
        #pragma unroll
        for (int nt = 0; nt < 8; nt++) {
            float mx0 = fmaxf(fmaxf(acc[0][nt][0], acc[0][nt][2]),
                              fmaxf(acc[1][nt][0], acc[1][nt][2]));
            float mx1 = fmaxf(fmaxf(acc[0][nt][1], acc[0][nt][3]),
                              fmaxf(acc[1][nt][1], acc[1][nt][3]));
            float mn0 = fminf(fminf(acc[0][nt][0], acc[0][nt][2]),
                              fminf(acc[1][nt][0], acc[1][nt][2]));
            float mn1 = fminf(fminf(acc[0][nt][1], acc[0][nt][3]),
                              fminf(acc[1][nt][1], acc[1][nt][3]));
            float s0 = acc[0][nt][0] + acc[0][nt][2] + acc[1][nt][0] + acc[1][nt][2];
            float s1 = acc[0][nt][1] + acc[0][nt][3] + acc[1][nt][1] + acc[1][nt][3];
            float q0 = acc[0][nt][0]*acc[0][nt][0] + acc[0][nt][2]*acc[0][nt][2]
                     + acc[1][nt][0]*acc[1][nt][0] + acc[1][nt][2]*acc[1][nt][2];
            float q1 = acc[0][nt][1]*acc[0][nt][1] + acc[0][nt][3]*acc[0][nt][3]
                     + acc[1][nt][1]*acc[1][nt][1] + acc[1][nt][3]*acc[1][nt][3];
            #pragma unroll
            for (int d = 4; d < 32; d <<= 1) {
                mx0 = fmaxf(mx0, __shfl_xor_sync(0xFFFFFFFF, mx0, d));
                mx1 = fmaxf(mx1, __shfl_xor_sync(0xFFFFFFFF, mx1, d));
                mn0 = fminf(mn0, __shfl_xor_sync(0xFFFFFFFF, mn0, d));
                mn1 = fminf(mn1, __shfl_xor_sync(0xFFFFFFFF, mn1, d));
                s0 += __shfl_xor_sync(0xFFFFFFFF, s0, d);
                s1 += __shfl_xor_sync(0xFFFFFFFF, s1, d);
                q0 += __shfl_xor_sync(0xFFFFFFFF, q0, d);
                q1 += __shfl_xor_sync(0xFFFFFFFF, q1, d);
            }
            if (lane < 4) {
                int cl = nr + nt*8 + (lane << 1);
                int c  = nh + cl;
                *(float2*)&g_mx[bn*256 + c] = make_float2(mx0, mx1);
                *(float2*)&g_mn[bn*256 + c] = make_float2(mn0, mn1);
                atomicAdd(&sSum[cl], s0);  atomicAdd(&sSum[cl + 1], s1);
                atomicAdd(&sSs[cl],  q0);  atomicAdd(&sSs[cl + 1],  q1);
            }
        }
    }
    __syncthreads();
    if (tid < 128) {
        atomicAdd(&g_s2[nh + tid],       sSum[tid]);
        atomicAdd(&g_s2[256 + nh + tid], sSs[tid]);
    }
}

// ---------------- k_out ----------------
static const int SMEM_OUT = 2 * 64 * 257 * 4;
__global__ void __launch_bounds__(256) k_out(float* __restrict__ out,
        const float* __restrict__ gam, const float* __restrict__ bet) {
    extern __shared__ float smf[];
    float* sMx = smf;
    float* sMn = smf + 64*257;
    __shared__ float sA2[256], sC2[256];
    int tid = threadIdx.x;
    {
        const float inv = 1.0f / (float)PTOT;
        float mean = g_s2[tid] * inv;
        float var  = g_s2[256 + tid] * inv - mean * mean;
        float a = gam[tid] * rsqrtf(var + EPSV);
        sA2[tid] = a; sC2[tid] = bet[tid] - mean * a;
    }
    int b  = blockIdx.x >> 5;
    int n0 = (blockIdx.x & 31) * 64;
    for (int i = tid; i < 64*256; i += 256) {
        int nl = i >> 8, o = i & 255;
        int g = (b*NN + n0 + nl)*256 + o;
        sMx[nl*257 + o] = g_mx[g];
        sMn[nl*257 + o] = g_mn[g];
    }
    __syncthreads();
    for (int i = tid; i < 64*256; i += 256) {
        int o = i >> 6, nl = i & 63;
        float a = sA2[o], c = sC2[o];
        float z = (a >= 0.f) ? sMx[nl*257 + o] : sMn[nl*257 + o];
        float y = fmaf(a, z, c);
        out[(b*256 + o)*NN + n0 + nl] = (y > 0.f) ? y : SLOPE * y;
    }
}

// ---------------- launch ----------------
extern "C" void kernel_launch(void* const* d_in, const int* in_sizes, int n_in,
                              void* d_out, int out_size) {
    const float* pos1 = (const float*)d_in[0];
    const float* pos2 = (const float*)d_in[1];
    const float* f1   = (const float*)d_in[2];
    const float* f2   = (const float*)d_in[3];
    const int*   idxp = (const int*)d_in[4];
    const float* W0 = (const float*)d_in[5];
    const float* g0 = (const float*)d_in[6];
    const float* b0 = (const float*)d_in[7];
    const float* W1 = (const float*)d_in[8];
    const float* g1 = (const float*)d_in[9];
    const float* b1 = (const float*)d_in[10];
    const float* W2 = (const float*)d_in[11];
    const float* g2 = (const float*)d_in[12];
    const float* b2 = (const float*)d_in[13];

    cudaFuncSetAttribute(k_prep, cudaFuncAttributeMaxDynamicSharedMemorySize, SMEM_PREP);
    cudaFuncSetAttribute(k_l1,   cudaFuncAttributeMaxDynamicSharedMemorySize, SMEM_L1);
    cudaFuncSetAttribute(k_l2,   cudaFuncAttributeMaxDynamicSharedMemorySize, SMEM_L2);
    cudaFuncSetAttribute(k_out,  cudaFuncAttributeMaxDynamicSharedMemorySize, SMEM_OUT);

    float* outp = (float*)d_out;
    int featOff = out_size - BB*L2C*NN;
    if (featOff < 0) featOff = 0;

    k_zw<<<96, 256>>>(W1, W2);                                       // 0
    k_prep<<<BB*(NN/16), 128, SMEM_PREP>>>(pos1, pos2, f1, f2, W0);  // 1
    k_stats0<<<PTOT/128, 128>>>(idxp);                               // 2
    k_l1<<<PTOT/512, 256, SMEM_L1>>>(idxp, g0, b0);                  // 3 (profiled)
    k_l2<<<2*(PTOT/512), 256, SMEM_L2>>>(g1, b1);                    // 4
    if (featOff > 0)
        cudaMemcpyAsync(d_out, pos1, (size_t)featOff * sizeof(float),
                        cudaMemcpyDeviceToDevice, 0);
    k_out<<<BB*(NN/64), 256, SMEM_OUT>>>(outp + featOff, g2, b2);    // 5
}

// round 8
// speedup vs baseline: 4.1634x; 1.0682x over previous
#include <cuda_runtime.h>
#include <cuda_fp16.h>
#include <cstdint>

#define BB 4
#define NN 2048
#define KK 32
#define L0 128
#define L1C 128
#define L2C 256
#define PTOT (BB*NN*KK)   /* 262144 */
#define EPSV 1e-5f
#define SLOPE 0.01f

// ---------------- scratch ----------------
__device__ float g_A[BB*NN*L0];              // 4 MB
__device__ float g_D[BB*NN*L0];              // 4 MB
__device__ uint32_t g_y1h[(size_t)PTOT*64];  // 67 MB : y1 as half2 pairs [pt][c/2]
__device__ float g_mx[BB*NN*L2C];            // 8 MB
__device__ float g_mn[BB*NN*L2C];            // 8 MB
__device__ float g_s0[2*L0];
__device__ float g_s1[2*L1C];
__device__ float g_s2[2*L2C];
__device__ uint32_t g_W1h2[128*64];          // W1 fp16 half2 packed
__device__ uint32_t g_W2h2[256*64];          // W2 fp16 half2 packed

// ---------------- helpers ----------------
__device__ __forceinline__ uint32_t smem_u32(const void* p) {
    uint32_t a;
    asm("{ .reg .u64 t; cvta.to.shared.u64 t, %1; cvt.u32.u64 %0, t; }" : "=r"(a) : "l"(p));
    return a;
}
__device__ __forceinline__ void ldmx4(uint32_t* r, uint32_t addr) {
    asm volatile("ldmatrix.sync.aligned.m8n8.x4.shared.b16 {%0,%1,%2,%3}, [%4];"
                 : "=r"(r[0]), "=r"(r[1]), "=r"(r[2]), "=r"(r[3]) : "r"(addr));
}
__device__ __forceinline__ void mma16816(float* d, const uint32_t* a, const uint32_t* b) {
    asm volatile(
        "mma.sync.aligned.m16n8k16.row.col.f32.f16.f16.f32 "
        "{%0,%1,%2,%3}, {%4,%5,%6,%7}, {%8,%9}, {%0,%1,%2,%3};"
        : "+f"(d[0]), "+f"(d[1]), "+f"(d[2]), "+f"(d[3])
        : "r"(a[0]), "r"(a[1]), "r"(a[2]), "r"(a[3]), "r"(b[0]), "r"(b[1]));
}
__device__ __forceinline__ void hsplit2(float x, float y, uint32_t& hi, uint32_t& lo) {
    __half hx = __float2half_rn(x), hy = __float2half_rn(y);
    __half lx = __float2half_rn(x - __half2float(hx));
    __half ly = __float2half_rn(y - __half2float(hy));
    __half2 h2 = __halves2half2(hx, hy), l2 = __halves2half2(lx, ly);
    hi = *(uint32_t*)&h2; lo = *(uint32_t*)&l2;
}
// tile rows are 256B (128 halves); XOR-swizzle 16B chunks within each 128B octant
__device__ __forceinline__ uint32_t sw_pair(int row, int c2) {   // c2 = half2 index 0..63
    return (uint32_t)row*256u + (uint32_t)(((c2 >> 2) ^ (row & 7)) << 4) + (uint32_t)((c2 & 3) << 2);
}
__device__ __forceinline__ uint32_t sw_chunk(int row, int cl) {  // cl = 16B chunk 0..15
    return (uint32_t)row*256u + (uint32_t)(((cl ^ (row & 7)) & 15) << 4);
}

// ---------------- k_zw: zero stats + W1/W2 -> fp16 half2 ----------------
__global__ void k_zw(const float* __restrict__ W1, const float* __restrict__ W2) {
    if (blockIdx.x == 0) {
        for (int j = threadIdx.x; j < 1024; j += 256) {
            if (j < 256)      g_s0[j] = 0.f;
            else if (j < 512) g_s1[j - 256] = 0.f;
            else              g_s2[j - 512] = 0.f;
        }
    }
    int i = blockIdx.x * 256 + threadIdx.x;
    if (i < 8192) {
        float2 w = ((const float2*)W1)[i];
        __half2 h = __floats2half2_rn(w.x, w.y);
        g_W1h2[i] = *(uint32_t*)&h;
    } else if (i < 24576) {
        int j = i - 8192;
        float2 w = ((const float2*)W2)[j];
        __half2 h = __floats2half2_rn(w.x, w.y);
        g_W2h2[j] = *(uint32_t*)&h;
    }
}

// ---------------- k_prep: A/D factorization with smem-staged W0 ----------------
#define SW_PITCH 16900   /* 131*129=16899 rounded up so sI is 16B-aligned */
static const int SMEM_PREP = (SW_PITCH + 131*16) * 4;
__global__ void __launch_bounds__(128) k_prep(
        const float* __restrict__ pos1, const float* __restrict__ pos2,
        const float* __restrict__ f1,   const float* __restrict__ f2,
        const float* __restrict__ W0) {
    extern __shared__ float sp[];
    float* sW = sp;               // [131][129]
    float* sI = sp + SW_PITCH;    // [131][16], 16B-aligned
    int blk = blockIdx.x;
    int b  = blk / (NN/16);
    int j0 = (blk % (NN/16)) * 16;
    int tid = threadIdx.x;

    // ---- pass A ----
    for (int i = tid; i < 131*128; i += 128) {
        int o = i / 131, c = i - o*131;
        sW[c*129 + o] = W0[o*259 + c];
    }
    for (int i = tid; i < 131*16; i += 128) {
        int c = i >> 4, jl = i & 15;
        sI[c*16 + jl] = (c < 3) ? pos2[(b*3 + c)*NN + j0 + jl]
                                : f2[(b*128 + (c-3))*NN + j0 + jl];
    }
    __syncthreads();
    {
        float4 acc[4];
        #pragma unroll
        for (int q = 0; q < 4; q++) acc[q] = make_float4(0.f,0.f,0.f,0.f);
        for (int c = 0; c < 131; c++) {
            float wv = sW[c*129 + tid];
            const float4* r = (const float4*)&sI[c*16];
            #pragma unroll
            for (int q = 0; q < 4; q++) {
                float4 rv = r[q];
                acc[q].x = fmaf(wv, rv.x, acc[q].x);
                acc[q].y = fmaf(wv, rv.y, acc[q].y);
                acc[q].z = fmaf(wv, rv.z, acc[q].z);
                acc[q].w = fmaf(wv, rv.w, acc[q].w);
            }
        }
        const float* af = (const float*)acc;
        #pragma unroll
        for (int pt = 0; pt < 16; pt++)
            g_A[((b*NN + j0 + pt) << 7) + tid] = af[pt];
    }
    __syncthreads();

    // ---- pass D ----
    for (int i = tid; i < 131*128; i += 128) {
        int o = i / 131, c = i - o*131;
        int src = (c < 3) ? c : 128 + c;   // 131 + (c-3)
        sW[c*129 + o] = W0[o*259 + src];
    }
    for (int i = tid; i < 131*16; i += 128) {
        int c = i >> 4, jl = i & 15;
        sI[c*16 + jl] = (c < 3) ? -pos1[(b*3 + c)*NN + j0 + jl]
                                : f1[(b*128 + (c-3))*NN + j0 + jl];
    }
    __syncthreads();
    {
        float4 acc[4];
        #pragma unroll
        for (int q = 0; q < 4; q++) acc[q] = make_float4(0.f,0.f,0.f,0.f);
        for (int c = 0; c < 131; c++) {
            float wv = sW[c*129 + tid];
            const float4* r = (const float4*)&sI[c*16];
            #pragma unroll
            for (int q = 0; q < 4; q++) {
                float4 rv = r[q];
                acc[q].x = fmaf(wv, rv.x, acc[q].x);
                acc[q].y = fmaf(wv, rv.y, acc[q].y);
                acc[q].z = fmaf(wv, rv.z, acc[q].z);
                acc[q].w = fmaf(wv, rv.w, acc[q].w);
            }
        }
        const float* af = (const float*)acc;
        #pragma unroll
        for (int pt = 0; pt < 16; pt++)
            g_D[((b*NN + j0 + pt) << 7) + tid] = af[pt];
    }
}

// ---------------- k_stats0: stats of y0 = A[idx] + D ----------------
__global__ void __launch_bounds__(128) k_stats0(const int* __restrict__ idxp) {
    __shared__ int s_idx[128];
    int tid = threadIdx.x;
    int pbase = blockIdx.x * 128;
    s_idx[tid] = idxp[pbase + tid];
    __syncthreads();
    float s = 0.f, ss = 0.f;
    #pragma unroll 4
    for (int i = 0; i < 128; i++) {
        int p = pbase + i;
        int arow = ((p >> 16) * NN + s_idx[i]) << 7;
        int drow = (p >> 5) << 7;
        float y = g_A[arow + tid] + g_D[drow + tid];
        s += y; ss = fmaf(y, y, ss);
    }
    atomicAdd(&g_s0[tid], s);
    atomicAdd(&g_s0[L0 + tid], ss);
}

// ======================= layer 1 =======================
// block: 4 tiles x (64 pts x 128 out) x K=128; 256 thr / 8 warps; 3 CTAs/SM
// warp tile 16x64; 2-pass: acc = Uh*Wh + Ul*Wh
static const int L1_UH = 4096;                // 64*256B = 16384
static const int L1_UL = L1_UH + 16384;
static const int L1_WH = L1_UL + 16384;       // 32768
static const int SMEM_L1 = L1_WH + 32768;     // 69632

__global__ void __launch_bounds__(256, 3) k_l1(
        const int* __restrict__ idxp,
        const float* __restrict__ gam, const float* __restrict__ bet) {
    extern __shared__ char sm[];
    uint32_t sb = smem_u32(sm);
    float* sA   = (float*)(sm + 0);      // 128
    float* sC   = (float*)(sm + 512);    // 128
    int*   sAR  = (int*)(sm + 1024);     // 256 ints
    float* sSum = (float*)(sm + 2048);   // 128
    float* sSs  = (float*)(sm + 2560);   // 128
    int tid = threadIdx.x, wid = tid >> 5, lane = tid & 31;
    int pblk = blockIdx.x * 256;

    if (tid < 128) {
        const float inv = 1.0f / (float)PTOT;
        float mean = g_s0[tid] * inv;
        float var  = g_s0[128 + tid] * inv - mean * mean;
        float a = gam[tid] * rsqrtf(var + EPSV);
        sA[tid] = a; sC[tid] = bet[tid] - mean * a;
        sSum[tid] = 0.f; sSs[tid] = 0.f;
    }
    {
        int p = pblk + tid;
        sAR[tid] = ((p >> 16) * NN + idxp[p]) << 7;
    }
    __syncthreads();

    // W tile (128 rows, hi only), loaded once
    for (int i = tid; i < 8192; i += 256) {
        int o = i >> 6, c2 = i & 63;
        *(uint32_t*)(sm + L1_WH + sw_pair(o, c2)) = g_W1h2[i];
    }

    int mr = (wid & 3) * 16, nr = (wid >> 2) * 64;
    int aRow = lane & 15, aSel = lane >> 4;
    int bRow = (lane & 7) + ((lane >> 4) << 3), bSel = (lane >> 3) & 1;

    #pragma unroll 1
    for (int t = 0; t < 4; t++) {
        int pbase = pblk + t * 64;
        if (t) __syncthreads();

        // U tile (64 rows): lrelu(BN0(A[idx]+D)) split hi/lo
        for (int i = tid; i < 4096; i += 256) {
            int pl = i >> 6, c2 = i & 63;
            const float2* ar = (const float2*)(g_A + sAR[t*64 + pl]);
            const float2* dr = (const float2*)(g_D + (((pbase + pl) >> 5) << 7));
            float2 av = ar[c2], dv = dr[c2];
            int c = c2 << 1;
            float u0 = fmaf(sA[c],     av.x + dv.x, sC[c]);
            float u1 = fmaf(sA[c + 1], av.y + dv.y, sC[c + 1]);
            u0 = (u0 > 0.f) ? u0 : SLOPE * u0;
            u1 = (u1 > 0.f) ? u1 : SLOPE * u1;
            uint32_t hi, lo; hsplit2(u0, u1, hi, lo);
            uint32_t off = sw_pair(pl, c2);
            *(uint32_t*)(sm + L1_UH + off) = hi;
            *(uint32_t*)(sm + L1_UL + off) = lo;
        }
        __syncthreads();

        float acc[8][4];
        #pragma unroll
        for (int nt = 0; nt < 8; nt++)
            #pragma unroll
            for (int q = 0; q < 4; q++) acc[nt][q] = 0.f;

        for (int ks = 0; ks < 8; ks++) {
            uint32_t ah[4], al[4];
            int clA = 2*ks + aSel;
            {
                int r = mr + aRow;
                uint32_t off = sw_chunk(r, clA);
                ldmx4(ah, sb + L1_UH + off);
                ldmx4(al, sb + L1_UL + off);
            }
            int clB = 2*ks + bSel;
            #pragma unroll
            for (int q = 0; q < 4; q++) {
                int n = nr + q*16 + bRow;
                uint32_t bh[4];
                ldmx4(bh, sb + L1_WH + sw_chunk(n, clB));
                mma16816(acc[2*q],     ah, bh);
                mma16816(acc[2*q + 1], ah, bh + 2);
                mma16816(acc[2*q],     al, bh);
                mma16816(acc[2*q + 1], al, bh + 2);
            }
        }

        // ---- register epilogue: y1 -> half2 pairs + channel sums via shuffles ----
        {
            int r = mr + (lane >> 2);
            #pragma unroll
            for (int nt = 0; nt < 8; nt++) {
                int c2 = (nr >> 1) + nt*4 + (lane & 3);
                __half2 h0 = __floats2half2_rn(acc[nt][0], acc[nt][1]);
                __half2 h1 = __floats2half2_rn(acc[nt][2], acc[nt][3]);
                g_y1h[(size_t)(pbase + r)*64 + c2]     = *(uint32_t*)&h0;
                g_y1h[(size_t)(pbase + r + 8)*64 + c2] = *(uint32_t*)&h1;
            }
        }
        #pragma unroll
        for (int nt = 0; nt < 8; nt++) {
            float s0 = acc[nt][0] + acc[nt][2];
            float s1 = acc[nt][1] + acc[nt][3];
            float q0 = acc[nt][0]*acc[nt][0] + acc[nt][2]*acc[nt][2];
            float q1 = acc[nt][1]*acc[nt][1] + acc[nt][3]*acc[nt][3];
            #pragma unroll
            for (int d = 4; d < 32; d <<= 1) {
                s0 += __shfl_xor_sync(0xFFFFFFFF, s0, d);
                s1 += __shfl_xor_sync(0xFFFFFFFF, s1, d);
                q0 += __shfl_xor_sync(0xFFFFFFFF, q0, d);
                q1 += __shfl_xor_sync(0xFFFFFFFF, q1, d);
            }
            if (lane < 4) {
                int c = nr + nt*8 + (lane << 1);
                atomicAdd(&sSum[c], s0);  atomicAdd(&sSum[c + 1], s1);
                atomicAdd(&sSs[c],  q0);  atomicAdd(&sSs[c + 1],  q1);
            }
        }
    }
    __syncthreads();
    if (tid < 128) {
        atomicAdd(&g_s1[tid],       sSum[tid]);
        atomicAdd(&g_s1[128 + tid], sSs[tid]);
    }
}

// ======================= layer 2 =======================
// block: 4 tiles x (64 pts x 128 out-half) x K=128; 256 thr / 8 warps; 3 CTAs/SM
// warp tile 32x32 (warp owns one K-group); grid = 2 * PTOT/256
static const int L2_UH = 4096;                // 16384
static const int L2_UL = L2_UH + 16384;
static const int L2_WH = L2_UL + 16384;       // 32768
static const int SMEM_L2 = L2_WH + 32768;     // 69632

__global__ void __launch_bounds__(256, 3) k_l2(
        const float* __restrict__ gam, const float* __restrict__ bet) {
    extern __shared__ char sm[];
    uint32_t sb = smem_u32(sm);
    float* sA   = (float*)(sm + 0);      // 128
    float* sC   = (float*)(sm + 512);    // 128
    float* sSum = (float*)(sm + 1024);   // 128 (local channel half)
    float* sSs  = (float*)(sm + 1536);   // 128
    int tid = threadIdx.x, wid = tid >> 5, lane = tid & 31;
    int pblk = (blockIdx.x >> 1) * 256;
    int nh   = (blockIdx.x & 1) * 128;   // channel-half offset

    if (tid < 128) {
        const float inv = 1.0f / (float)PTOT;
        float mean = g_s1[tid] * inv;
        float var  = g_s1[128 + tid] * inv - mean * mean;
        float a = gam[tid] * rsqrtf(var + EPSV);
        sA[tid] = a; sC[tid] = bet[tid] - mean * a;
        sSum[tid] = 0.f; sSs[tid] = 0.f;
    }
    __syncthreads();

    // W tile: rows nh..nh+127 of W2
    for (int i = tid; i < 8192; i += 256) {
        int o = i >> 6, c2 = i & 63;
        *(uint32_t*)(sm + L2_WH + sw_pair(o, c2)) = g_W2h2[(nh + o)*64 + c2];
    }

    int mr = (wid & 1) * 32, nr = (wid >> 1) * 32;
    int aRow = lane & 15, aSel = lane >> 4;
    int bRow = (lane & 7) + ((lane >> 4) << 3), bSel = (lane >> 3) & 1;

    #pragma unroll 1
    for (int t = 0; t < 4; t++) {
        int pbase = pblk + t * 64;
        if (t) __syncthreads();

        // U tile: lrelu(BN1(y1)) from half2-packed y1
        for (int i = tid; i < 4096; i += 256) {
            int pl = i >> 6, c2 = i & 63;
            uint32_t yy = g_y1h[(size_t)(pbase + pl)*64 + c2];
            float2 y = __half22float2(*(__half2*)&yy);
            int c = c2 << 1;
            float u0 = fmaf(sA[c],     y.x, sC[c]);
            float u1 = fmaf(sA[c + 1], y.y, sC[c + 1]);
            u0 = (u0 > 0.f) ? u0 : SLOPE * u0;
            u1 = (u1 > 0.f) ? u1 : SLOPE * u1;
            uint32_t hi, lo; hsplit2(u0, u1, hi, lo);
            uint32_t off = sw_pair(pl, c2);
            *(uint32_t*)(sm + L2_UH + off) = hi;
            *(uint32_t*)(sm + L2_UL + off) = lo;
        }
        __syncthreads();

        float acc[2][4][4];
        #pragma unroll
        for (int mt = 0; mt < 2; mt++)
            #pragma unroll
            for (int nt = 0; nt < 4; nt++)
                #pragma unroll
                for (int q = 0; q < 4; q++) acc[mt][nt][q] = 0.f;

        for (int ks = 0; ks < 8; ks++) {
            uint32_t ah[2][4], al[2][4];
            int clA = 2*ks + aSel;
            #pragma unroll
            for (int mt = 0; mt < 2; mt++) {
                int r = mr + mt*16 + aRow;
                uint32_t off = sw_chunk(r, clA);
                ldmx4(ah[mt], sb + L2_UH + off);
                ldmx4(al[mt], sb + L2_UL + off);
            }
            int clB = 2*ks + bSel;
            #pragma unroll
            for (int q = 0; q < 2; q++) {
                int n = nr + q*16 + bRow;
                uint32_t bh[4];
                ldmx4(bh, sb + L2_WH + sw_chunk(n, clB));
                #pragma unroll
                for (int mt = 0; mt < 2; mt++) {
                    mma16816(acc[mt][2*q],     ah[mt], bh);
                    mma16816(acc[mt][2*q + 1], ah[mt], bh + 2);
                    mma16816(acc[mt][2*q],     al[mt], bh);
                    mma16816(acc[mt][2*q + 1], al[mt], bh + 2);
                }
            }
        }

        // ---- register epilogue: warp owns one K-group (32 pts) x 32 ch ----
        int bn = (pbase >> 5) + (wid & 1);
        #pragma unroll
        for (int nt = 0; nt < 4; nt++) {
            float mx0 = fmaxf(fmaxf(acc[0][nt][0], acc[0][nt][2]),
                              fmaxf(acc[1][nt][0], acc[1][nt][2]));
            float mx1 = fmaxf(fmaxf(acc[0][nt][1], acc[0][nt][3]),
                              fmaxf(acc[1][nt][1], acc[1][nt][3]));
            float mn0 = fminf(fminf(acc[0][nt][0], acc[0][nt][2]),
                              fminf(acc[1][nt][0], acc[1][nt][2]));
            float mn1 = fminf(fminf(acc[0][nt][1], acc[0][nt][3]),
                              fminf(acc[1][nt][1], acc[1][nt][3]));
            float s0 = acc[0][nt][0] + acc[0][nt][2] + acc[1][nt][0] + acc[1][nt][2];
            float s1 = acc[0][nt][1] + acc[0][nt][3] + acc[1][nt][1] + acc[1][nt][3];
            float q0 = acc[0][nt][0]*acc[0][nt][0] + acc[0][nt][2]*acc[0][nt][2]
                     + acc[1][nt][0]*acc[1][nt][0] + acc[1][nt][2]*acc[1][nt][2];
            float q1 = acc[0][nt][1]*acc[0][nt][1] + acc[0][nt][3]*acc[0][nt][3]
                     + acc[1][nt][1]*acc[1][nt][1] + acc[1][nt][3]*acc[1][nt][3];
            #pragma unroll
            for (int d = 4; d < 32; d <<= 1) {
                mx0 = fmaxf(mx0, __shfl_xor_sync(0xFFFFFFFF, mx0, d));
                mx1 = fmaxf(mx1, __shfl_xor_sync(0xFFFFFFFF, mx1, d));
                mn0 = fminf(mn0, __shfl_xor_sync(0xFFFFFFFF, mn0, d));
                mn1 = fminf(mn1, __shfl_xor_sync(0xFFFFFFFF, mn1, d));
                s0 += __shfl_xor_sync(0xFFFFFFFF, s0, d);
                s1 += __shfl_xor_sync(0xFFFFFFFF, s1, d);
                q0 += __shfl_xor_sync(0xFFFFFFFF, q0, d);
                q1 += __shfl_xor_sync(0xFFFFFFFF, q1, d);
            }
            if (lane < 4) {
                int cl = nr + nt*8 + (lane << 1);
                int c  = nh + cl;
                *(float2*)&g_mx[bn*256 + c] = make_float2(mx0, mx1);
                *(float2*)&g_mn[bn*256 + c] = make_float2(mn0, mn1);
                atomicAdd(&sSum[cl], s0);  atomicAdd(&sSum[cl + 1], s1);
                atomicAdd(&sSs[cl],  q0);  atomicAdd(&sSs[cl + 1],  q1);
            }
        }
    }
    __syncthreads();
    if (tid < 128) {
        atomicAdd(&g_s2[nh + tid],       sSum[tid]);
        atomicAdd(&g_s2[256 + nh + tid], sSs[tid]);
    }
}

// ---------------- k_out ----------------
static const int SMEM_OUT = 2 * 64 * 257 * 4;
__global__ void __launch_bounds__(256) k_out(float* __restrict__ out,
        const float* __restrict__ gam, const float* __restrict__ bet) {
    extern __shared__ float smf[];
    float* sMx = smf;
    float* sMn = smf + 64*257;
    __shared__ float sA2[256], sC2[256];
    int tid = threadIdx.x;
    {
        const float inv = 1.0f / (float)PTOT;
        float mean = g_s2[tid] * inv;
        float var  = g_s2[256 + tid] * inv - mean * mean;
        float a = gam[tid] * rsqrtf(var + EPSV);
        sA2[tid] = a; sC2[tid] = bet[tid] - mean * a;
    }
    int b  = blockIdx.x >> 5;
    int n0 = (blockIdx.x & 31) * 64;
    for (int i = tid; i < 64*256; i += 256) {
        int nl = i >> 8, o = i & 255;
        int g = (b*NN + n0 + nl)*256 + o;
        sMx[nl*257 + o] = g_mx[g];
        sMn[nl*257 + o] = g_mn[g];
    }
    __syncthreads();
    for (int i = tid; i < 64*256; i += 256) {
        int o = i >> 6, nl = i & 63;
        float a = sA2[o], c = sC2[o];
        float z = (a >= 0.f) ? sMx[nl*257 + o] : sMn[nl*257 + o];
        float y = fmaf(a, z, c);
        out[(b*256 + o)*NN + n0 + nl] = (y > 0.f) ? y : SLOPE * y;
    }
}

// ---------------- launch ----------------
extern "C" void kernel_launch(void* const* d_in, const int* in_sizes, int n_in,
                              void* d_out, int out_size) {
    const float* pos1 = (const float*)d_in[0];
    const float* pos2 = (const float*)d_in[1];
    const float* f1   = (const float*)d_in[2];
    const float* f2   = (const float*)d_in[3];
    const int*   idxp = (const int*)d_in[4];
    const float* W0 = (const float*)d_in[5];
    const float* g0 = (const float*)d_in[6];
    const float* b0 = (const float*)d_in[7];
    const float* W1 = (const float*)d_in[8];
    const float* g1 = (const float*)d_in[9];
    const float* b1 = (const float*)d_in[10];
    const float* W2 = (const float*)d_in[11];
    const float* g2 = (const float*)d_in[12];
    const float* b2 = (const float*)d_in[13];

    cudaFuncSetAttribute(k_prep, cudaFuncAttributeMaxDynamicSharedMemorySize, SMEM_PREP);
    cudaFuncSetAttribute(k_l1,   cudaFuncAttributeMaxDynamicSharedMemorySize, SMEM_L1);
    cudaFuncSetAttribute(k_l2,   cudaFuncAttributeMaxDynamicSharedMemorySize, SMEM_L2);
    cudaFuncSetAttribute(k_out,  cudaFuncAttributeMaxDynamicSharedMemorySize, SMEM_OUT);

    float* outp = (float*)d_out;
    int featOff = out_size - BB*L2C*NN;
    if (featOff < 0) featOff = 0;

    k_zw<<<96, 256>>>(W1, W2);                                       // 0
    k_prep<<<BB*(NN/16), 128, SMEM_PREP>>>(pos1, pos2, f1, f2, W0);  // 1
    k_stats0<<<PTOT/128, 128>>>(idxp);                               // 2
    k_l1<<<PTOT/256, 256, SMEM_L1>>>(idxp, g0, b0);                  // 3 (profiled)
    k_l2<<<2*(PTOT/256), 256, SMEM_L2>>>(g1, b1);                    // 4
    if (featOff > 0)
        cudaMemcpyAsync(d_out, pos1, (size_t)featOff * sizeof(float),
                        cudaMemcpyDeviceToDevice, 0);
    k_out<<<BB*(NN/64), 256, SMEM_OUT>>>(outp + featOff, g2, b2);    // 5
}

// round 9
// speedup vs baseline: 4.5681x; 1.0972x over previous
#include <cuda_runtime.h>
#include <cuda_fp16.h>
#include <cstdint>

#define BB 4
#define NN 2048
#define KK 32
#define L0 128
#define L1C 128
#define L2C 256
#define PTOT (BB*NN*KK)   /* 262144 */
#define EPSV 1e-5f
#define SLOPE 0.01f

// ---------------- scratch ----------------
__device__ float g_A[BB*NN*L0];              // 4 MB
__device__ float g_D[BB*NN*L0];              // 4 MB
__device__ uint32_t g_y1h[(size_t)PTOT*64];  // 67 MB : y1 as half2 pairs [pt][c/2]
__device__ float g_mx[BB*NN*L2C];            // 8 MB
__device__ float g_mn[BB*NN*L2C];            // 8 MB
__device__ float g_s0[2*L0];
__device__ float g_s1[2*L1C];
__device__ float g_s2[2*L2C];
__device__ uint32_t g_W1h2[128*64];          // W1 fp16 half2 packed
__device__ uint32_t g_W2h2[256*64];          // W2 fp16 half2 packed

// ---------------- helpers ----------------
__device__ __forceinline__ uint32_t smem_u32(const void* p) {
    uint32_t a;
    asm("{ .reg .u64 t; cvta.to.shared.u64 t, %1; cvt.u32.u64 %0, t; }" : "=r"(a) : "l"(p));
    return a;
}
__device__ __forceinline__ void ldmx4(uint32_t* r, uint32_t addr) {
    asm volatile("ldmatrix.sync.aligned.m8n8.x4.shared.b16 {%0,%1,%2,%3}, [%4];"
                 : "=r"(r[0]), "=r"(r[1]), "=r"(r[2]), "=r"(r[3]) : "r"(addr));
}
__device__ __forceinline__ void mma16816(float* d, const uint32_t* a, const uint32_t* b) {
    asm volatile(
        "mma.sync.aligned.m16n8k16.row.col.f32.f16.f16.f32 "
        "{%0,%1,%2,%3}, {%4,%5,%6,%7}, {%8,%9}, {%0,%1,%2,%3};"
        : "+f"(d[0]), "+f"(d[1]), "+f"(d[2]), "+f"(d[3])
        : "r"(a[0]), "r"(a[1]), "r"(a[2]), "r"(a[3]), "r"(b[0]), "r"(b[1]));
}
// tile rows are 256B (128 halves); XOR-swizzle 16B chunks within each 128B octant
__device__ __forceinline__ uint32_t sw_pair(int row, int c2) {   // c2 = half2 index 0..63
    return (uint32_t)row*256u + (uint32_t)(((c2 >> 2) ^ (row & 7)) << 4) + (uint32_t)((c2 & 3) << 2);
}
__device__ __forceinline__ uint32_t sw_chunk(int row, int cl) {  // cl = 16B chunk 0..15
    return (uint32_t)row*256u + (uint32_t)(((cl ^ (row & 7)) & 15) << 4);
}

// ---------------- k_zw: zero stats + W1/W2 -> fp16 half2 ----------------
__global__ void k_zw(const float* __restrict__ W1, const float* __restrict__ W2) {
    if (blockIdx.x == 0) {
        for (int j = threadIdx.x; j < 1024; j += 256) {
            if (j < 256)      g_s0[j] = 0.f;
            else if (j < 512) g_s1[j - 256] = 0.f;
            else              g_s2[j - 512] = 0.f;
        }
    }
    int i = blockIdx.x * 256 + threadIdx.x;
    if (i < 8192) {
        float2 w = ((const float2*)W1)[i];
        __half2 h = __floats2half2_rn(w.x, w.y);
        g_W1h2[i] = *(uint32_t*)&h;
    } else if (i < 24576) {
        int j = i - 8192;
        float2 w = ((const float2*)W2)[j];
        __half2 h = __floats2half2_rn(w.x, w.y);
        g_W2h2[j] = *(uint32_t*)&h;
    }
}

// ---------------- k_prep: A/D factorization with smem-staged W0 ----------------
#define SW_PITCH 16900   /* 131*129=16899 rounded up so sI is 16B-aligned */
static const int SMEM_PREP = (SW_PITCH + 131*16) * 4;
__global__ void __launch_bounds__(128) k_prep(
        const float* __restrict__ pos1, const float* __restrict__ pos2,
        const float* __restrict__ f1,   const float* __restrict__ f2,
        const float* __restrict__ W0) {
    extern __shared__ float sp[];
    float* sW = sp;               // [131][129]
    float* sI = sp + SW_PITCH;    // [131][16], 16B-aligned
    int blk = blockIdx.x;
    int b  = blk / (NN/16);
    int j0 = (blk % (NN/16)) * 16;
    int tid = threadIdx.x;

    // ---- pass A ----
    for (int i = tid; i < 131*128; i += 128) {
        int o = i / 131, c = i - o*131;
        sW[c*129 + o] = W0[o*259 + c];
    }
    for (int i = tid; i < 131*16; i += 128) {
        int c = i >> 4, jl = i & 15;
        sI[c*16 + jl] = (c < 3) ? pos2[(b*3 + c)*NN + j0 + jl]
                                : f2[(b*128 + (c-3))*NN + j0 + jl];
    }
    __syncthreads();
    {
        float4 acc[4];
        #pragma unroll
        for (int q = 0; q < 4; q++) acc[q] = make_float4(0.f,0.f,0.f,0.f);
        for (int c = 0; c < 131; c++) {
            float wv = sW[c*129 + tid];
            const float4* r = (const float4*)&sI[c*16];
            #pragma unroll
            for (int q = 0; q < 4; q++) {
                float4 rv = r[q];
                acc[q].x = fmaf(wv, rv.x, acc[q].x);
                acc[q].y = fmaf(wv, rv.y, acc[q].y);
                acc[q].z = fmaf(wv, rv.z, acc[q].z);
                acc[q].w = fmaf(wv, rv.w, acc[q].w);
            }
        }
        const float* af = (const float*)acc;
        #pragma unroll
        for (int pt = 0; pt < 16; pt++)
            g_A[((b*NN + j0 + pt) << 7) + tid] = af[pt];
    }
    __syncthreads();

    // ---- pass D ----
    for (int i = tid; i < 131*128; i += 128) {
        int o = i / 131, c = i - o*131;
        int src = (c < 3) ? c : 128 + c;   // 131 + (c-3)
        sW[c*129 + o] = W0[o*259 + src];
    }
    for (int i = tid; i < 131*16; i += 128) {
        int c = i >> 4, jl = i & 15;
        sI[c*16 + jl] = (c < 3) ? -pos1[(b*3 + c)*NN + j0 + jl]
                                : f1[(b*128 + (c-3))*NN + j0 + jl];
    }
    __syncthreads();
    {
        float4 acc[4];
        #pragma unroll
        for (int q = 0; q < 4; q++) acc[q] = make_float4(0.f,0.f,0.f,0.f);
        for (int c = 0; c < 131; c++) {
            float wv = sW[c*129 + tid];
            const float4* r = (const float4*)&sI[c*16];
            #pragma unroll
            for (int q = 0; q < 4; q++) {
                float4 rv = r[q];
                acc[q].x = fmaf(wv, rv.x, acc[q].x);
                acc[q].y = fmaf(wv, rv.y, acc[q].y);
                acc[q].z = fmaf(wv, rv.z, acc[q].z);
                acc[q].w = fmaf(wv, rv.w, acc[q].w);
            }
        }
        const float* af = (const float*)acc;
        #pragma unroll
        for (int pt = 0; pt < 16; pt++)
            g_D[((b*NN + j0 + pt) << 7) + tid] = af[pt];
    }
}

// ---------------- k_stats0: stats of y0 = A[idx] + D ----------------
__global__ void __launch_bounds__(128) k_stats0(const int* __restrict__ idxp) {
    __shared__ int s_idx[128];
    int tid = threadIdx.x;
    int pbase = blockIdx.x * 128;
    s_idx[tid] = idxp[pbase + tid];
    __syncthreads();
    float s = 0.f, ss = 0.f;
    #pragma unroll 4
    for (int i = 0; i < 128; i++) {
        int p = pbase + i;
        int arow = ((p >> 16) * NN + s_idx[i]) << 7;
        int drow = (p >> 5) << 7;
        float y = g_A[arow + tid] + g_D[drow + tid];
        s += y; ss = fmaf(y, y, ss);
    }
    atomicAdd(&g_s0[tid], s);
    atomicAdd(&g_s0[L0 + tid], ss);
}

// ======================= layer 1 =======================
// block: 4 tiles x (64 pts x 128 out) x K=128; 256 thr / 8 warps; 3 CTAs/SM
// warp tile 16x64; SINGLE-pass fp16: acc = U*W
static const int L1_UH = 4096;                // 64*256B = 16384
static const int L1_WH = L1_UH + 16384;       // 32768
static const int SMEM_L1 = L1_WH + 32768;     // 53248

__global__ void __launch_bounds__(256, 3) k_l1(
        const int* __restrict__ idxp,
        const float* __restrict__ gam, const float* __restrict__ bet) {
    extern __shared__ char sm[];
    uint32_t sb = smem_u32(sm);
    float* sA   = (float*)(sm + 0);      // 128
    float* sC   = (float*)(sm + 512);    // 128
    int*   sAR  = (int*)(sm + 1024);     // 256 ints
    float* sSum = (float*)(sm + 2048);   // 128
    float* sSs  = (float*)(sm + 2560);   // 128
    int tid = threadIdx.x, wid = tid >> 5, lane = tid & 31;
    int pblk = blockIdx.x * 256;

    if (tid < 128) {
        const float inv = 1.0f / (float)PTOT;
        float mean = g_s0[tid] * inv;
        float var  = g_s0[128 + tid] * inv - mean * mean;
        float a = gam[tid] * rsqrtf(var + EPSV);
        sA[tid] = a; sC[tid] = bet[tid] - mean * a;
        sSum[tid] = 0.f; sSs[tid] = 0.f;
    }
    {
        int p = pblk + tid;
        sAR[tid] = ((p >> 16) * NN + idxp[p]) << 7;
    }
    __syncthreads();

    // W tile (128 rows), loaded once
    for (int i = tid; i < 8192; i += 256) {
        int o = i >> 6, c2 = i & 63;
        *(uint32_t*)(sm + L1_WH + sw_pair(o, c2)) = g_W1h2[i];
    }

    int mr = (wid & 3) * 16, nr = (wid >> 2) * 64;
    int aRow = lane & 15, aSel = lane >> 4;
    int bRow = (lane & 7) + ((lane >> 4) << 3), bSel = (lane >> 3) & 1;

    #pragma unroll 1
    for (int t = 0; t < 4; t++) {
        int pbase = pblk + t * 64;
        if (t) __syncthreads();

        // U tile (64 rows): lrelu(BN0(A[idx]+D)) -> fp16
        for (int i = tid; i < 4096; i += 256) {
            int pl = i >> 6, c2 = i & 63;
            const float2* ar = (const float2*)(g_A + sAR[t*64 + pl]);
            const float2* dr = (const float2*)(g_D + (((pbase + pl) >> 5) << 7));
            float2 av = ar[c2], dv = dr[c2];
            int c = c2 << 1;
            float u0 = fmaf(sA[c],     av.x + dv.x, sC[c]);
            float u1 = fmaf(sA[c + 1], av.y + dv.y, sC[c + 1]);
            u0 = (u0 > 0.f) ? u0 : SLOPE * u0;
            u1 = (u1 > 0.f) ? u1 : SLOPE * u1;
            __half2 h = __floats2half2_rn(u0, u1);
            *(uint32_t*)(sm + L1_UH + sw_pair(pl, c2)) = *(uint32_t*)&h;
        }
        __syncthreads();

        float acc[8][4];
        #pragma unroll
        for (int nt = 0; nt < 8; nt++)
            #pragma unroll
            for (int q = 0; q < 4; q++) acc[nt][q] = 0.f;

        for (int ks = 0; ks < 8; ks++) {
            uint32_t ah[4];
            int clA = 2*ks + aSel;
            ldmx4(ah, sb + L1_UH + sw_chunk(mr + aRow, clA));
            int clB = 2*ks + bSel;
            #pragma unroll
            for (int q = 0; q < 4; q++) {
                int n = nr + q*16 + bRow;
                uint32_t bh[4];
                ldmx4(bh, sb + L1_WH + sw_chunk(n, clB));
                mma16816(acc[2*q],     ah, bh);
                mma16816(acc[2*q + 1], ah, bh + 2);
            }
        }

        // ---- register epilogue: y1 -> half2 pairs + channel sums via shuffles ----
        {
            int r = mr + (lane >> 2);
            #pragma unroll
            for (int nt = 0; nt < 8; nt++) {
                int c2 = (nr >> 1) + nt*4 + (lane & 3);
                __half2 h0 = __floats2half2_rn(acc[nt][0], acc[nt][1]);
                __half2 h1 = __floats2half2_rn(acc[nt][2], acc[nt][3]);
                g_y1h[(size_t)(pbase + r)*64 + c2]     = *(uint32_t*)&h0;
                g_y1h[(size_t)(pbase + r + 8)*64 + c2] = *(uint32_t*)&h1;
            }
        }
        #pragma unroll
        for (int nt = 0; nt < 8; nt++) {
            float s0 = acc[nt][0] + acc[nt][2];
            float s1 = acc[nt][1] + acc[nt][3];
            float q0 = acc[nt][0]*acc[nt][0] + acc[nt][2]*acc[nt][2];
            float q1 = acc[nt][1]*acc[nt][1] + acc[nt][3]*acc[nt][3];
            #pragma unroll
            for (int d = 4; d < 32; d <<= 1) {
                s0 += __shfl_xor_sync(0xFFFFFFFF, s0, d);
                s1 += __shfl_xor_sync(0xFFFFFFFF, s1, d);
                q0 += __shfl_xor_sync(0xFFFFFFFF, q0, d);
                q1 += __shfl_xor_sync(0xFFFFFFFF, q1, d);
            }
            if (lane < 4) {
                int c = nr + nt*8 + (lane << 1);
                atomicAdd(&sSum[c], s0);  atomicAdd(&sSum[c + 1], s1);
                atomicAdd(&sSs[c],  q0);  atomicAdd(&sSs[c + 1],  q1);
            }
        }
    }
    __syncthreads();
    if (tid < 128) {
        atomicAdd(&g_s1[tid],       sSum[tid]);
        atomicAdd(&g_s1[128 + tid], sSs[tid]);
    }
}

// ======================= layer 2 =======================
// block: 4 tiles x (64 pts x 128 out-half) x K=128; 256 thr / 8 warps; 3 CTAs/SM
// warp tile 32x32 (warp owns one K-group); SINGLE-pass fp16
static const int L2_UH = 4096;                // 16384
static const int L2_WH = L2_UH + 16384;       // 32768
static const int SMEM_L2 = L2_WH + 32768;     // 53248

__global__ void __launch_bounds__(256, 3) k_l2(
        const float* __restrict__ gam, const float* __restrict__ bet) {
    extern __shared__ char sm[];
    uint32_t sb = smem_u32(sm);
    float* sA   = (float*)(sm + 0);      // 128
    float* sC   = (float*)(sm + 512);    // 128
    float* sSum = (float*)(sm + 1024);   // 128 (local channel half)
    float* sSs  = (float*)(sm + 1536);   // 128
    int tid = threadIdx.x, wid = tid >> 5, lane = tid & 31;
    int pblk = (blockIdx.x >> 1) * 256;
    int nh   = (blockIdx.x & 1) * 128;   // channel-half offset

    if (tid < 128) {
        const float inv = 1.0f / (float)PTOT;
        float mean = g_s1[tid] * inv;
        float var  = g_s1[128 + tid] * inv - mean * mean;
        float a = gam[tid] * rsqrtf(var + EPSV);
        sA[tid] = a; sC[tid] = bet[tid] - mean * a;
        sSum[tid] = 0.f; sSs[tid] = 0.f;
    }
    __syncthreads();

    // W tile: rows nh..nh+127 of W2
    for (int i = tid; i < 8192; i += 256) {
        int o = i >> 6, c2 = i & 63;
        *(uint32_t*)(sm + L2_WH + sw_pair(o, c2)) = g_W2h2[(nh + o)*64 + c2];
    }

    int mr = (wid & 1) * 32, nr = (wid >> 1) * 32;
    int aRow = lane & 15, aSel = lane >> 4;
    int bRow = (lane & 7) + ((lane >> 4) << 3), bSel = (lane >> 3) & 1;

    #pragma unroll 1
    for (int t = 0; t < 4; t++) {
        int pbase = pblk + t * 64;
        if (t) __syncthreads();

        // U tile: lrelu(BN1(y1)) from half2-packed y1 -> fp16
        for (int i = tid; i < 4096; i += 256) {
            int pl = i >> 6, c2 = i & 63;
            uint32_t yy = g_y1h[(size_t)(pbase + pl)*64 + c2];
            float2 y = __half22float2(*(__half2*)&yy);
            int c = c2 << 1;
            float u0 = fmaf(sA[c],     y.x, sC[c]);
            float u1 = fmaf(sA[c + 1], y.y, sC[c + 1]);
            u0 = (u0 > 0.f) ? u0 : SLOPE * u0;
            u1 = (u1 > 0.f) ? u1 : SLOPE * u1;
            __half2 h = __floats2half2_rn(u0, u1);
            *(uint32_t*)(sm + L2_UH + sw_pair(pl, c2)) = *(uint32_t*)&h;
        }
        __syncthreads();

        float acc[2][4][4];
        #pragma unroll
        for (int mt = 0; mt < 2; mt++)
            #pragma unroll
            for (int nt = 0; nt < 4; nt++)
                #pragma unroll
                for (int q = 0; q < 4; q++) acc[mt][nt][q] = 0.f;

        for (int ks = 0; ks < 8; ks++) {
            uint32_t ah[2][4];
            int clA = 2*ks + aSel;
            #pragma unroll
            for (int mt = 0; mt < 2; mt++)
                ldmx4(ah[mt], sb + L2_UH + sw_chunk(mr + mt*16 + aRow, clA));
            int clB = 2*ks + bSel;
            #pragma unroll
            for (int q = 0; q < 2; q++) {
                int n = nr + q*16 + bRow;
                uint32_t bh[4];
                ldmx4(bh, sb + L2_WH + sw_chunk(n, clB));
                #pragma unroll
                for (int mt = 0; mt < 2; mt++) {
                    mma16816(acc[mt][2*q],     ah[mt], bh);
                    mma16816(acc[mt][2*q + 1], ah[mt], bh + 2);
                }
            }
        }

        // ---- register epilogue: warp owns one K-group (32 pts) x 32 ch ----
        int bn = (pbase >> 5) + (wid & 1);
        #pragma unroll
        for (int nt = 0; nt < 4; nt++) {
            float mx0 = fmaxf(fmaxf(acc[0][nt][0], acc[0][nt][2]),
                              fmaxf(acc[1][nt][0], acc[1][nt][2]));
            float mx1 = fmaxf(fmaxf(acc[0][nt][1], acc[0][nt][3]),
                              fmaxf(acc[1][nt][1], acc[1][nt][3]));
            float mn0 = fminf(fminf(acc[0][nt][0], acc[0][nt][2]),
                              fminf(acc[1][nt][0], acc[1][nt][2]));
            float mn1 = fminf(fminf(acc[0][nt][1], acc[0][nt][3]),
                              fminf(acc[1][nt][1], acc[1][nt][3]));
            float s0 = acc[0][nt][0] + acc[0][nt][2] + acc[1][nt][0] + acc[1][nt][2];
            float s1 = acc[0][nt][1] + acc[0][nt][3] + acc[1][nt][1] + acc[1][nt][3];
            float q0 = acc[0][nt][0]*acc[0][nt][0] + acc[0][nt][2]*acc[0][nt][2]
                     + acc[1][nt][0]*acc[1][nt][0] + acc[1][nt][2]*acc[1][nt][2];
            float q1 = acc[0][nt][1]*acc[0][nt][1] + acc[0][nt][3]*acc[0][nt][3]
                     + acc[1][nt][1]*acc[1][nt][1] + acc[1][nt][3]*acc[1][nt][3];
            #pragma unroll
            for (int d = 4; d < 32; d <<= 1) {
                mx0 = fmaxf(mx0, __shfl_xor_sync(0xFFFFFFFF, mx0, d));
                mx1 = fmaxf(mx1, __shfl_xor_sync(0xFFFFFFFF, mx1, d));
                mn0 = fminf(mn0, __shfl_xor_sync(0xFFFFFFFF, mn0, d));
                mn1 = fminf(mn1, __shfl_xor_sync(0xFFFFFFFF, mn1, d));
                s0 += __shfl_xor_sync(0xFFFFFFFF, s0, d);
                s1 += __shfl_xor_sync(0xFFFFFFFF, s1, d);
                q0 += __shfl_xor_sync(0xFFFFFFFF, q0, d);
                q1 += __shfl_xor_sync(0xFFFFFFFF, q1, d);
            }
            if (lane < 4) {
                int cl = nr + nt*8 + (lane << 1);
                int c  = nh + cl;
                *(float2*)&g_mx[bn*256 + c] = make_float2(mx0, mx1);
                *(float2*)&g_mn[bn*256 + c] = make_float2(mn0, mn1);
                atomicAdd(&sSum[cl], s0);  atomicAdd(&sSum[cl + 1], s1);
                atomicAdd(&sSs[cl],  q0);  atomicAdd(&sSs[cl + 1],  q1);
            }
        }
    }
    __syncthreads();
    if (tid < 128) {
        atomicAdd(&g_s2[nh + tid],       sSum[tid]);
        atomicAdd(&g_s2[256 + nh + tid], sSs[tid]);
    }
}

// ---------------- k_out ----------------
static const int SMEM_OUT = 2 * 64 * 257 * 4;
__global__ void __launch_bounds__(256) k_out(float* __restrict__ out,
        const float* __restrict__ gam, const float* __restrict__ bet) {
    extern __shared__ float smf[];
    float* sMx = smf;
    float* sMn = smf + 64*257;
    __shared__ float sA2[256], sC2[256];
    int tid = threadIdx.x;
    {
        const float inv = 1.0f / (float)PTOT;
        float mean = g_s2[tid] * inv;
        float var  = g_s2[256 + tid] * inv - mean * mean;
        float a = gam[tid] * rsqrtf(var + EPSV);
        sA2[tid] = a; sC2[tid] = bet[tid] - mean * a;
    }
    int b  = blockIdx.x >> 5;
    int n0 = (blockIdx.x & 31) * 64;
    for (int i = tid; i < 64*256; i += 256) {
        int nl = i >> 8, o = i & 255;
        int g = (b*NN + n0 + nl)*256 + o;
        sMx[nl*257 + o] = g_mx[g];
        sMn[nl*257 + o] = g_mn[g];
    }
    __syncthreads();
    for (int i = tid; i < 64*256; i += 256) {
        int o = i >> 6, nl = i & 63;
        float a = sA2[o], c = sC2[o];
        float z = (a >= 0.f) ? sMx[nl*257 + o] : sMn[nl*257 + o];
        float y = fmaf(a, z, c);
        out[(b*256 + o)*NN + n0 + nl] = (y > 0.f) ? y : SLOPE * y;
    }
}

// ---------------- launch ----------------
extern "C" void kernel_launch(void* const* d_in, const int* in_sizes, int n_in,
                              void* d_out, int out_size) {
    const float* pos1 = (const float*)d_in[0];
    const float* pos2 = (const float*)d_in[1];
    const float* f1   = (const float*)d_in[2];
    const float* f2   = (const float*)d_in[3];
    const int*   idxp = (const int*)d_in[4];
    const float* W0 = (const float*)d_in[5];
    const float* g0 = (const float*)d_in[6];
    const float* b0 = (const float*)d_in[7];
    const float* W1 = (const float*)d_in[8];
    const float* g1 = (const float*)d_in[9];
    const float* b1 = (const float*)d_in[10];
    const float* W2 = (const float*)d_in[11];
    const float* g2 = (const float*)d_in[12];
    const float* b2 = (const float*)d_in[13];

    cudaFuncSetAttribute(k_prep, cudaFuncAttributeMaxDynamicSharedMemorySize, SMEM_PREP);
    cudaFuncSetAttribute(k_l1,   cudaFuncAttributeMaxDynamicSharedMemorySize, SMEM_L1);
    cudaFuncSetAttribute(k_l2,   cudaFuncAttributeMaxDynamicSharedMemorySize, SMEM_L2);
    cudaFuncSetAttribute(k_out,  cudaFuncAttributeMaxDynamicSharedMemorySize, SMEM_OUT);

    float* outp = (float*)d_out;
    int featOff = out_size - BB*L2C*NN;
    if (featOff < 0) featOff = 0;

    k_zw<<<96, 256>>>(W1, W2);                                       // 0
    k_prep<<<BB*(NN/16), 128, SMEM_PREP>>>(pos1, pos2, f1, f2, W0);  // 1
    k_stats0<<<PTOT/128, 128>>>(idxp);                               // 2
    k_l1<<<PTOT/256, 256, SMEM_L1>>>(idxp, g0, b0);                  // 3 (profiled)
    k_l2<<<2*(PTOT/256), 256, SMEM_L2>>>(g1, b1);                    // 4
    if (featOff > 0)
        cudaMemcpyAsync(d_out, pos1, (size_t)featOff * sizeof(float),
                        cudaMemcpyDeviceToDevice, 0);
    k_out<<<BB*(NN/64), 256, SMEM_OUT>>>(outp + featOff, g2, b2);    // 5
}

// round 10
// speedup vs baseline: 4.9930x; 1.0930x over previous
#include <cuda_runtime.h>
#include <cuda_fp16.h>
#include <cstdint>

#define BB 4
#define NN 2048
#define KK 32
#define L0 128
#define L1C 128
#define L2C 256
#define PTOT (BB*NN*KK)   /* 262144 */
#define EPSV 1e-5f
#define SLOPE 0.01f

// ---------------- scratch ----------------
__device__ __align__(16) float g_A[BB*NN*L0];              // 4 MB
__device__ __align__(16) float g_D[BB*NN*L0];              // 4 MB
__device__ __align__(16) uint32_t g_Ah[BB*NN*64];          // 2 MB : a0*A, half2
__device__ __align__(16) uint32_t g_Dh[BB*NN*64];          // 2 MB : a0*D + c0, half2
__device__ __align__(16) uint32_t g_y1h[(size_t)PTOT*64];  // 67 MB : y1 half2 [pt][c/2]
__device__ float g_mx[BB*NN*L2C];            // 8 MB
__device__ float g_mn[BB*NN*L2C];            // 8 MB
__device__ float g_s0[2*L0];
__device__ float g_s1[2*L1C];
__device__ float g_s2[2*L2C];
__device__ __align__(16) uint32_t g_W1h2[128*64];          // W1 fp16 half2
__device__ __align__(16) uint32_t g_W2h2[256*64];          // W2 fp16 half2

// ---------------- helpers ----------------
__device__ __forceinline__ uint32_t smem_u32(const void* p) {
    uint32_t a;
    asm("{ .reg .u64 t; cvta.to.shared.u64 t, %1; cvt.u32.u64 %0, t; }" : "=r"(a) : "l"(p));
    return a;
}
__device__ __forceinline__ void ldmx4(uint32_t* r, uint32_t addr) {
    asm volatile("ldmatrix.sync.aligned.m8n8.x4.shared.b16 {%0,%1,%2,%3}, [%4];"
                 : "=r"(r[0]), "=r"(r[1]), "=r"(r[2]), "=r"(r[3]) : "r"(addr));
}
__device__ __forceinline__ void mma16816(float* d, const uint32_t* a, const uint32_t* b) {
    asm volatile(
        "mma.sync.aligned.m16n8k16.row.col.f32.f16.f16.f32 "
        "{%0,%1,%2,%3}, {%4,%5,%6,%7}, {%8,%9}, {%0,%1,%2,%3};"
        : "+f"(d[0]), "+f"(d[1]), "+f"(d[2]), "+f"(d[3])
        : "r"(a[0]), "r"(a[1]), "r"(a[2]), "r"(a[3]), "r"(b[0]), "r"(b[1]));
}
// tile rows are 256B (128 halves); XOR-swizzle 16B chunks within each 128B octant
__device__ __forceinline__ uint32_t sw_pair(int row, int c2) {   // c2 = half2 index 0..63
    return (uint32_t)row*256u + (uint32_t)(((c2 >> 2) ^ (row & 7)) << 4) + (uint32_t)((c2 & 3) << 2);
}
__device__ __forceinline__ uint32_t sw_chunk(int row, int cl) {  // cl = 16B chunk 0..15
    return (uint32_t)row*256u + (uint32_t)(((cl ^ (row & 7)) & 15) << 4);
}
__device__ __forceinline__ uint32_t add_lrelu2(uint32_t a, uint32_t d) {
    __half2 s = __hadd2(*(__half2*)&a, *(__half2*)&d);
    __half2 u = __hmax2(s, __hmul2(s, __float2half2_rn(SLOPE)));
    return *(uint32_t*)&u;
}
__device__ __forceinline__ uint32_t bn_lrelu2(uint32_t y, uint32_t a, uint32_t c) {
    __half2 u = __hfma2(*(__half2*)&a, *(__half2*)&y, *(__half2*)&c);
    __half2 r = __hmax2(u, __hmul2(u, __float2half2_rn(SLOPE)));
    return *(uint32_t*)&r;
}

// ---------------- k_prep: A/D factorization + absorbed zero/W-split ----------------
#define SW_PITCH 16900   /* 131*129=16899 rounded up so sI is 16B-aligned */
static const int SMEM_PREP = (SW_PITCH + 131*16) * 4;
__global__ void __launch_bounds__(128) k_prep(
        const float* __restrict__ pos1, const float* __restrict__ pos2,
        const float* __restrict__ f1,   const float* __restrict__ f2,
        const float* __restrict__ W0,
        const float* __restrict__ W1,   const float* __restrict__ W2) {
    extern __shared__ float sp[];
    float* sW = sp;               // [131][129]
    float* sI = sp + SW_PITCH;    // [131][16], 16B-aligned
    int blk = blockIdx.x;
    int b  = blk / (NN/16);
    int j0 = (blk % (NN/16)) * 16;
    int tid = threadIdx.x;

    // ---- absorbed: zero stats + W1/W2 fp16 split (independent side work) ----
    if (blk == 0) {
        for (int j = tid; j < 1024; j += 128) {
            if (j < 256)      g_s0[j] = 0.f;
            else if (j < 512) g_s1[j - 256] = 0.f;
            else              g_s2[j - 512] = 0.f;
        }
    }
    if (blk < 96) {
        for (int t2 = tid; t2 < 256; t2 += 128) {
            int i = blk * 256 + t2;
            if (i < 8192) {
                float2 w = ((const float2*)W1)[i];
                __half2 h = __floats2half2_rn(w.x, w.y);
                g_W1h2[i] = *(uint32_t*)&h;
            } else if (i < 24576) {
                int j = i - 8192;
                float2 w = ((const float2*)W2)[j];
                __half2 h = __floats2half2_rn(w.x, w.y);
                g_W2h2[j] = *(uint32_t*)&h;
            }
        }
    }

    // ---- pass A ----
    for (int i = tid; i < 131*128; i += 128) {
        int o = i / 131, c = i - o*131;
        sW[c*129 + o] = W0[o*259 + c];
    }
    for (int i = tid; i < 131*16; i += 128) {
        int c = i >> 4, jl = i & 15;
        sI[c*16 + jl] = (c < 3) ? pos2[(b*3 + c)*NN + j0 + jl]
                                : f2[(b*128 + (c-3))*NN + j0 + jl];
    }
    __syncthreads();
    {
        float4 acc[4];
        #pragma unroll
        for (int q = 0; q < 4; q++) acc[q] = make_float4(0.f,0.f,0.f,0.f);
        for (int c = 0; c < 131; c++) {
            float wv = sW[c*129 + tid];
            const float4* r = (const float4*)&sI[c*16];
            #pragma unroll
            for (int q = 0; q < 4; q++) {
                float4 rv = r[q];
                acc[q].x = fmaf(wv, rv.x, acc[q].x);
                acc[q].y = fmaf(wv, rv.y, acc[q].y);
                acc[q].z = fmaf(wv, rv.z, acc[q].z);
                acc[q].w = fmaf(wv, rv.w, acc[q].w);
            }
        }
        const float* af = (const float*)acc;
        #pragma unroll
        for (int pt = 0; pt < 16; pt++)
            g_A[((b*NN + j0 + pt) << 7) + tid] = af[pt];
    }
    __syncthreads();

    // ---- pass D ----
    for (int i = tid; i < 131*128; i += 128) {
        int o = i / 131, c = i - o*131;
        int src = (c < 3) ? c : 128 + c;   // 131 + (c-3)
        sW[c*129 + o] = W0[o*259 + src];
    }
    for (int i = tid; i < 131*16; i += 128) {
        int c = i >> 4, jl = i & 15;
        sI[c*16 + jl] = (c < 3) ? -pos1[(b*3 + c)*NN + j0 + jl]
                                : f1[(b*128 + (c-3))*NN + j0 + jl];
    }
    __syncthreads();
    {
        float4 acc[4];
        #pragma unroll
        for (int q = 0; q < 4; q++) acc[q] = make_float4(0.f,0.f,0.f,0.f);
        for (int c = 0; c < 131; c++) {
            float wv = sW[c*129 + tid];
            const float4* r = (const float4*)&sI[c*16];
            #pragma unroll
            for (int q = 0; q < 4; q++) {
                float4 rv = r[q];
                acc[q].x = fmaf(wv, rv.x, acc[q].x);
                acc[q].y = fmaf(wv, rv.y, acc[q].y);
                acc[q].z = fmaf(wv, rv.z, acc[q].z);
                acc[q].w = fmaf(wv, rv.w, acc[q].w);
            }
        }
        const float* af = (const float*)acc;
        #pragma unroll
        for (int pt = 0; pt < 16; pt++)
            g_D[((b*NN + j0 + pt) << 7) + tid] = af[pt];
    }
}

// ---------------- k_stats0: stats of y0 = A[idx] + D ----------------
__global__ void __launch_bounds__(128) k_stats0(const int* __restrict__ idxp) {
    __shared__ int s_idx[128];
    int tid = threadIdx.x;
    int pbase = blockIdx.x * 128;
    s_idx[tid] = idxp[pbase + tid];
    __syncthreads();
    float s = 0.f, ss = 0.f;
    #pragma unroll 4
    for (int i = 0; i < 128; i++) {
        int p = pbase + i;
        int arow = ((p >> 16) * NN + s_idx[i]) << 7;
        int drow = (p >> 5) << 7;
        float y = g_A[arow + tid] + g_D[drow + tid];
        s += y; ss = fmaf(y, y, ss);
    }
    atomicAdd(&g_s0[tid], s);
    atomicAdd(&g_s0[L0 + tid], ss);
}

// ---------------- k_fold: A~ = a0*A (half2), D~ = a0*D + c0 (half2) ----------------
__global__ void __launch_bounds__(256) k_fold(
        const float* __restrict__ gam, const float* __restrict__ bet) {
    __shared__ float sA[128], sC[128];
    int tid = threadIdx.x;
    if (tid < 128) {
        const float inv = 1.0f / (float)PTOT;
        float mean = g_s0[tid] * inv;
        float var  = g_s0[128 + tid] * inv - mean * mean;
        float a = gam[tid] * rsqrtf(var + EPSV);
        sA[tid] = a; sC[tid] = bet[tid] - mean * a;
    }
    __syncthreads();
    int q = blockIdx.x * 256 + tid;     // quad index over BB*NN*16
    int row = q >> 4, ch = q & 15;
    int c = ch << 3;
    const float4* a4 = (const float4*)(g_A + (row << 7) + c);
    const float4* d4 = (const float4*)(g_D + (row << 7) + c);
    float4 av0 = a4[0], av1 = a4[1], dv0 = d4[0], dv1 = d4[1];
    uint4 oa, od;
    {
        __half2 h;
        h = __floats2half2_rn(sA[c+0]*av0.x, sA[c+1]*av0.y); oa.x = *(uint32_t*)&h;
        h = __floats2half2_rn(sA[c+2]*av0.z, sA[c+3]*av0.w); oa.y = *(uint32_t*)&h;
        h = __floats2half2_rn(sA[c+4]*av1.x, sA[c+5]*av1.y); oa.z = *(uint32_t*)&h;
        h = __floats2half2_rn(sA[c+6]*av1.z, sA[c+7]*av1.w); oa.w = *(uint32_t*)&h;
        h = __floats2half2_rn(fmaf(sA[c+0],dv0.x,sC[c+0]), fmaf(sA[c+1],dv0.y,sC[c+1])); od.x = *(uint32_t*)&h;
        h = __floats2half2_rn(fmaf(sA[c+2],dv0.z,sC[c+2]), fmaf(sA[c+3],dv0.w,sC[c+3])); od.y = *(uint32_t*)&h;
        h = __floats2half2_rn(fmaf(sA[c+4],dv1.x,sC[c+4]), fmaf(sA[c+5],dv1.y,sC[c+5])); od.z = *(uint32_t*)&h;
        h = __floats2half2_rn(fmaf(sA[c+6],dv1.z,sC[c+6]), fmaf(sA[c+7],dv1.w,sC[c+7])); od.w = *(uint32_t*)&h;
    }
    *(uint4*)&g_Ah[(row << 6) + (ch << 2)] = oa;
    *(uint4*)&g_Dh[(row << 6) + (ch << 2)] = od;
}

// ======================= layer 1 =======================
// block: 4 tiles x (64 pts x 128 out) x K=128; 256 thr / 8 warps; 3 CTAs/SM
// warp tile 16x64; fill: U = lrelu(A~[idx] + D~) in half2, uint4 vectorized
static const int L1_UH = 4096;                // 64*256B = 16384
static const int L1_WH = L1_UH + 16384;       // 32768
static const int SMEM_L1 = L1_WH + 32768;     // 53248

__global__ void __launch_bounds__(256, 3) k_l1(const int* __restrict__ idxp) {
    extern __shared__ char sm[];
    uint32_t sb = smem_u32(sm);
    int*   sAR  = (int*)(sm);            // 256 ints
    float* sSum = (float*)(sm + 1024);   // 128
    float* sSs  = (float*)(sm + 1536);   // 128
    int tid = threadIdx.x, wid = tid >> 5, lane = tid & 31;
    int pblk = blockIdx.x * 256;

    if (tid < 128) { sSum[tid] = 0.f; sSs[tid] = 0.f; }
    {
        int p = pblk + tid;
        sAR[tid] = ((p >> 16) * NN + idxp[p]) << 6;   // row base in uint32 units
    }
    __syncthreads();

    // W tile (128 rows), loaded once
    for (int i = tid; i < 8192; i += 256) {
        int o = i >> 6, c2 = i & 63;
        *(uint32_t*)(sm + L1_WH + sw_pair(o, c2)) = g_W1h2[i];
    }

    int mr = (wid & 3) * 16, nr = (wid >> 2) * 64;
    int aRow = lane & 15, aSel = lane >> 4;
    int bRow = (lane & 7) + ((lane >> 4) << 3), bSel = (lane >> 3) & 1;
    int fch = tid & 15, fpl = tid >> 4;   // fill coords: chunk (invariant), row base

    #pragma unroll 1
    for (int t = 0; t < 4; t++) {
        int pbase = pblk + t * 64;
        if (t) __syncthreads();

        // fill: 4 iterations, 16B each: 2 LDG.128 + 1 STS.128
        #pragma unroll
        for (int it = 0; it < 4; it++) {
            int pl = fpl + it * 16;
            uint4 av = *(const uint4*)&g_Ah[sAR[t*64 + pl] + (fch << 2)];
            uint4 dv = *(const uint4*)&g_Dh[(((pbase + pl) >> 5) << 6) + (fch << 2)];
            uint4 o;
            o.x = add_lrelu2(av.x, dv.x);
            o.y = add_lrelu2(av.y, dv.y);
            o.z = add_lrelu2(av.z, dv.z);
            o.w = add_lrelu2(av.w, dv.w);
            *(uint4*)(sm + L1_UH + sw_chunk(pl, fch)) = o;
        }
        __syncthreads();

        float acc[8][4];
        #pragma unroll
        for (int nt = 0; nt < 8; nt++)
            #pragma unroll
            for (int q = 0; q < 4; q++) acc[nt][q] = 0.f;

        for (int ks = 0; ks < 8; ks++) {
            uint32_t ah[4];
            int clA = 2*ks + aSel;
            ldmx4(ah, sb + L1_UH + sw_chunk(mr + aRow, clA));
            int clB = 2*ks + bSel;
            #pragma unroll
            for (int q = 0; q < 4; q++) {
                int n = nr + q*16 + bRow;
                uint32_t bh[4];
                ldmx4(bh, sb + L1_WH + sw_chunk(n, clB));
                mma16816(acc[2*q],     ah, bh);
                mma16816(acc[2*q + 1], ah, bh + 2);
            }
        }

        // ---- register epilogue: y1 -> half2 pairs + channel sums via shuffles ----
        {
            int r = mr + (lane >> 2);
            #pragma unroll
            for (int nt = 0; nt < 8; nt++) {
                int c2 = (nr >> 1) + nt*4 + (lane & 3);
                __half2 h0 = __floats2half2_rn(acc[nt][0], acc[nt][1]);
                __half2 h1 = __floats2half2_rn(acc[nt][2], acc[nt][3]);
                g_y1h[(size_t)(pbase + r)*64 + c2]     = *(uint32_t*)&h0;
                g_y1h[(size_t)(pbase + r + 8)*64 + c2] = *(uint32_t*)&h1;
            }
        }
        #pragma unroll
        for (int nt = 0; nt < 8; nt++) {
            float s0 = acc[nt][0] + acc[nt][2];
            float s1 = acc[nt][1] + acc[nt][3];
            float q0 = acc[nt][0]*acc[nt][0] + acc[nt][2]*acc[nt][2];
            float q1 = acc[nt][1]*acc[nt][1] + acc[nt][3]*acc[nt][3];
            #pragma unroll
            for (int d = 4; d < 32; d <<= 1) {
                s0 += __shfl_xor_sync(0xFFFFFFFF, s0, d);
                s1 += __shfl_xor_sync(0xFFFFFFFF, s1, d);
                q0 += __shfl_xor_sync(0xFFFFFFFF, q0, d);
                q1 += __shfl_xor_sync(0xFFFFFFFF, q1, d);
            }
            if (lane < 4) {
                int c = nr + nt*8 + (lane << 1);
                atomicAdd(&sSum[c], s0);  atomicAdd(&sSum[c + 1], s1);
                atomicAdd(&sSs[c],  q0);  atomicAdd(&sSs[c + 1],  q1);
            }
        }
    }
    __syncthreads();
    if (tid < 128) {
        atomicAdd(&g_s1[tid],       sSum[tid]);
        atomicAdd(&g_s1[128 + tid], sSs[tid]);
    }
}

// ======================= layer 2 =======================
// block: 4 tiles x (64 pts x 128 out-half) x K=128; 256 thr / 8 warps; 3 CTAs/SM
// warp tile 32x32; fill: half2 HFMA2 BN + lrelu, uint4 vectorized
static const int L2_UH = 4096;                // 16384
static const int L2_WH = L2_UH + 16384;       // 32768
static const int SMEM_L2 = L2_WH + 32768;     // 53248

__global__ void __launch_bounds__(256, 3) k_l2(
        const float* __restrict__ gam, const float* __restrict__ bet) {
    extern __shared__ char sm[];
    uint32_t sb = smem_u32(sm);
    uint32_t* sAh = (uint32_t*)(sm);     // 64 half2 (a1 pairs)
    uint32_t* sCh = (uint32_t*)(sm + 256);
    float* sSum = (float*)(sm + 512);    // 128
    float* sSs  = (float*)(sm + 1024);   // 128
    int tid = threadIdx.x, wid = tid >> 5, lane = tid & 31;
    int pblk = (blockIdx.x >> 1) * 256;
    int nh   = (blockIdx.x & 1) * 128;   // channel-half offset

    if (tid < 128) { sSum[tid] = 0.f; sSs[tid] = 0.f; }
    if (tid < 64) {
        const float inv = 1.0f / (float)PTOT;
        int ce = tid << 1;
        float m0 = g_s1[ce] * inv;
        float v0 = g_s1[128 + ce] * inv - m0 * m0;
        float a0 = gam[ce] * rsqrtf(v0 + EPSV);
        float c0 = bet[ce] - m0 * a0;
        float m1 = g_s1[ce + 1] * inv;
        float v1 = g_s1[128 + ce + 1] * inv - m1 * m1;
        float a1 = gam[ce + 1] * rsqrtf(v1 + EPSV);
        float c1 = bet[ce + 1] - m1 * a1;
        __half2 ha = __floats2half2_rn(a0, a1);
        __half2 hc = __floats2half2_rn(c0, c1);
        sAh[tid] = *(uint32_t*)&ha;
        sCh[tid] = *(uint32_t*)&hc;
    }
    __syncthreads();

    // W tile: rows nh..nh+127 of W2
    for (int i = tid; i < 8192; i += 256) {
        int o = i >> 6, c2 = i & 63;
        *(uint32_t*)(sm + L2_WH + sw_pair(o, c2)) = g_W2h2[(nh + o)*64 + c2];
    }

    int mr = (wid & 1) * 32, nr = (wid >> 1) * 32;
    int aRow = lane & 15, aSel = lane >> 4;
    int bRow = (lane & 7) + ((lane >> 4) << 3), bSel = (lane >> 3) & 1;
    int fch = tid & 15, fpl = tid >> 4;
    uint4 aq = *(const uint4*)&sAh[fch << 2];   // loop-invariant BN coeffs
    uint4 cq = *(const uint4*)&sCh[fch << 2];

    #pragma unroll 1
    for (int t = 0; t < 4; t++) {
        int pbase = pblk + t * 64;
        if (t) __syncthreads();

        // fill: 4 iterations, 16B each: 1 LDG.128 + 1 STS.128
        #pragma unroll
        for (int it = 0; it < 4; it++) {
            int pl = fpl + it * 16;
            uint4 y = *(const uint4*)&g_y1h[(size_t)(pbase + pl)*64 + (fch << 2)];
            uint4 o;
            o.x = bn_lrelu2(y.x, aq.x, cq.x);
            o.y = bn_lrelu2(y.y, aq.y, cq.y);
            o.z = bn_lrelu2(y.z, aq.z, cq.z);
            o.w = bn_lrelu2(y.w, aq.w, cq.w);
            *(uint4*)(sm + L2_UH + sw_chunk(pl, fch)) = o;
        }
        __syncthreads();

        float acc[2][4][4];
        #pragma unroll
        for (int mt = 0; mt < 2; mt++)
            #pragma unroll
            for (int nt = 0; nt < 4; nt++)
                #pragma unroll
                for (int q = 0; q < 4; q++) acc[mt][nt][q] = 0.f;

        for (int ks = 0; ks < 8; ks++) {
            uint32_t ah[2][4];
            int clA = 2*ks + aSel;
            #pragma unroll
            for (int mt = 0; mt < 2; mt++)
                ldmx4(ah[mt], sb + L2_UH + sw_chunk(mr + mt*16 + aRow, clA));
            int clB = 2*ks + bSel;
            #pragma unroll
            for (int q = 0; q < 2; q++) {
                int n = nr + q*16 + bRow;
                uint32_t bh[4];
                ldmx4(bh, sb + L2_WH + sw_chunk(n, clB));
                #pragma unroll
                for (int mt = 0; mt < 2; mt++) {
                    mma16816(acc[mt][2*q],     ah[mt], bh);
                    mma16816(acc[mt][2*q + 1], ah[mt], bh + 2);
                }
            }
        }

        // ---- register epilogue: warp owns one K-group (32 pts) x 32 ch ----
        int bn = (pbase >> 5) + (wid & 1);
        #pragma unroll
        for (int nt = 0; nt < 4; nt++) {
            float mx0 = fmaxf(fmaxf(acc[0][nt][0], acc[0][nt][2]),
                              fmaxf(acc[1][nt][0], acc[1][nt][2]));
            float mx1 = fmaxf(fmaxf(acc[0][nt][1], acc[0][nt][3]),
                              fmaxf(acc[1][nt][1], acc[1][nt][3]));
            float mn0 = fminf(fminf(acc[0][nt][0], acc[0][nt][2]),
                              fminf(acc[1][nt][0], acc[1][nt][2]));
            float mn1 = fminf(fminf(acc[0][nt][1], acc[0][nt][3]),
                              fminf(acc[1][nt][1], acc[1][nt][3]));
            float s0 = acc[0][nt][0] + acc[0][nt][2] + acc[1][nt][0] + acc[1][nt][2];
            float s1 = acc[0][nt][1] + acc[0][nt][3] + acc[1][nt][1] + acc[1][nt][3];
            float q0 = acc[0][nt][0]*acc[0][nt][0] + acc[0][nt][2]*acc[0][nt][2]
                     + acc[1][nt][0]*acc[1][nt][0] + acc[1][nt][2]*acc[1][nt][2];
            float q1 = acc[0][nt][1]*acc[0][nt][1] + acc[0][nt][3]*acc[0][nt][3]
                     + acc[1][nt][1]*acc[1][nt][1] + acc[1][nt][3]*acc[1][nt][3];
            #pragma unroll
            for (int d = 4; d < 32; d <<= 1) {
                mx0 = fmaxf(mx0, __shfl_xor_sync(0xFFFFFFFF, mx0, d));
                mx1 = fmaxf(mx1, __shfl_xor_sync(0xFFFFFFFF, mx1, d));
                mn0 = fminf(mn0, __shfl_xor_sync(0xFFFFFFFF, mn0, d));
                mn1 = fminf(mn1, __shfl_xor_sync(0xFFFFFFFF, mn1, d));
                s0 += __shfl_xor_sync(0xFFFFFFFF, s0, d);
                s1 += __shfl_xor_sync(0xFFFFFFFF, s1, d);
                q0 += __shfl_xor_sync(0xFFFFFFFF, q0, d);
                q1 += __shfl_xor_sync(0xFFFFFFFF, q1, d);
            }
            if (lane < 4) {
                int cl = nr + nt*8 + (lane << 1);
                int c  = nh + cl;
                *(float2*)&g_mx[bn*256 + c] = make_float2(mx0, mx1);
                *(float2*)&g_mn[bn*256 + c] = make_float2(mn0, mn1);
                atomicAdd(&sSum[cl], s0);  atomicAdd(&sSum[cl + 1], s1);
                atomicAdd(&sSs[cl],  q0);  atomicAdd(&sSs[cl + 1],  q1);
            }
        }
    }
    __syncthreads();
    if (tid < 128) {
        atomicAdd(&g_s2[nh + tid],       sSum[tid]);
        atomicAdd(&g_s2[256 + nh + tid], sSs[tid]);
    }
}

// ---------------- k_out ----------------
static const int SMEM_OUT = 2 * 64 * 257 * 4;
__global__ void __launch_bounds__(256) k_out(float* __restrict__ out,
        const float* __restrict__ gam, const float* __restrict__ bet) {
    extern __shared__ float smf[];
    float* sMx = smf;
    float* sMn = smf + 64*257;
    __shared__ float sA2[256], sC2[256];
    int tid = threadIdx.x;
    {
        const float inv = 1.0f / (float)PTOT;
        float mean = g_s2[tid] * inv;
        float var  = g_s2[256 + tid] * inv - mean * mean;
        float a = gam[tid] * rsqrtf(var + EPSV);
        sA2[tid] = a; sC2[tid] = bet[tid] - mean * a;
    }
    int b  = blockIdx.x >> 5;
    int n0 = (blockIdx.x & 31) * 64;
    for (int i = tid; i < 64*256; i += 256) {
        int nl = i >> 8, o = i & 255;
        int g = (b*NN + n0 + nl)*256 + o;
        sMx[nl*257 + o] = g_mx[g];
        sMn[nl*257 + o] = g_mn[g];
    }
    __syncthreads();
    for (int i = tid; i < 64*256; i += 256) {
        int o = i >> 6, nl = i & 63;
        float a = sA2[o], c = sC2[o];
        float z = (a >= 0.f) ? sMx[nl*257 + o] : sMn[nl*257 + o];
        float y = fmaf(a, z, c);
        out[(b*256 + o)*NN + n0 + nl] = (y > 0.f) ? y : SLOPE * y;
    }
}

// ---------------- launch ----------------
extern "C" void kernel_launch(void* const* d_in, const int* in_sizes, int n_in,
                              void* d_out, int out_size) {
    const float* pos1 = (const float*)d_in[0];
    const float* pos2 = (const float*)d_in[1];
    const float* f1   = (const float*)d_in[2];
    const float* f2   = (const float*)d_in[3];
    const int*   idxp = (const int*)d_in[4];
    const float* W0 = (const float*)d_in[5];
    const float* g0 = (const float*)d_in[6];
    const float* b0 = (const float*)d_in[7];
    const float* W1 = (const float*)d_in[8];
    const float* g1 = (const float*)d_in[9];
    const float* b1 = (const float*)d_in[10];
    const float* W2 = (const float*)d_in[11];
    const float* g2 = (const float*)d_in[12];
    const float* b2 = (const float*)d_in[13];

    cudaFuncSetAttribute(k_prep, cudaFuncAttributeMaxDynamicSharedMemorySize, SMEM_PREP);
    cudaFuncSetAttribute(k_l1,   cudaFuncAttributeMaxDynamicSharedMemorySize, SMEM_L1);
    cudaFuncSetAttribute(k_l2,   cudaFuncAttributeMaxDynamicSharedMemorySize, SMEM_L2);
    cudaFuncSetAttribute(k_out,  cudaFuncAttributeMaxDynamicSharedMemorySize, SMEM_OUT);

    float* outp = (float*)d_out;
    int featOff = out_size - BB*L2C*NN;
    if (featOff < 0) featOff = 0;

    k_prep<<<BB*(NN/16), 128, SMEM_PREP>>>(pos1, pos2, f1, f2, W0, W1, W2); // 0
    k_stats0<<<PTOT/128, 128>>>(idxp);                               // 1
    k_fold<<<512, 256>>>(g0, b0);                                    // 2
    k_l1<<<PTOT/256, 256, SMEM_L1>>>(idxp);                          // 3 (profiled)
    k_l2<<<2*(PTOT/256), 256, SMEM_L2>>>(g1, b1);                    // 4
    if (featOff > 0)
        cudaMemcpyAsync(d_out, pos1, (size_t)featOff * sizeof(float),
                        cudaMemcpyDeviceToDevice, 0);
    k_out<<<BB*(NN/64), 256, SMEM_OUT>>>(outp + featOff, g2, b2);    // 5
}

// round 11
// speedup vs baseline: 5.2719x; 1.0559x over previous
#include <cuda_runtime.h>
#include <cuda_fp16.h>
#include <cstdint>

#define BB 4
#define NN 2048
#define KK 32
#define L0 128
#define L1C 128
#define L2C 256
#define PTOT (BB*NN*KK)   /* 262144 */
#define EPSV 1e-5f
#define SLOPE 0.01f

// ---------------- scratch ----------------
__device__ __align__(16) float g_A[BB*NN*L0];              // 4 MB
__device__ __align__(16) float g_D[BB*NN*L0];              // 4 MB
__device__ __align__(16) uint32_t g_Ah[BB*NN*64];          // 2 MB : a0*A, half2
__device__ __align__(16) uint32_t g_Dh[BB*NN*64];          // 2 MB : a0*D + c0, half2
__device__ __align__(16) char g_y1s[(size_t)4096*16384];   // 67 MB : y1, swizzled 16KB tiles
__device__ float g_mx[BB*NN*L2C];            // 8 MB
__device__ float g_mn[BB*NN*L2C];            // 8 MB
__device__ float g_s0[2*L0];
__device__ float g_s1[2*L1C];
__device__ float g_s2[2*L2C];
__device__ __align__(16) uint32_t g_W1h2[128*64];          // W1 fp16 half2
__device__ __align__(16) uint32_t g_W2h2[256*64];          // W2 fp16 half2

// ---------------- helpers ----------------
__device__ __forceinline__ uint32_t smem_u32(const void* p) {
    uint32_t a;
    asm("{ .reg .u64 t; cvta.to.shared.u64 t, %1; cvt.u32.u64 %0, t; }" : "=r"(a) : "l"(p));
    return a;
}
__device__ __forceinline__ void ldmx4(uint32_t* r, uint32_t addr) {
    asm volatile("ldmatrix.sync.aligned.m8n8.x4.shared.b16 {%0,%1,%2,%3}, [%4];"
                 : "=r"(r[0]), "=r"(r[1]), "=r"(r[2]), "=r"(r[3]) : "r"(addr));
}
__device__ __forceinline__ void mma16816(float* d, const uint32_t* a, const uint32_t* b) {
    asm volatile(
        "mma.sync.aligned.m16n8k16.row.col.f32.f16.f16.f32 "
        "{%0,%1,%2,%3}, {%4,%5,%6,%7}, {%8,%9}, {%0,%1,%2,%3};"
        : "+f"(d[0]), "+f"(d[1]), "+f"(d[2]), "+f"(d[3])
        : "r"(a[0]), "r"(a[1]), "r"(a[2]), "r"(a[3]), "r"(b[0]), "r"(b[1]));
}
__device__ __forceinline__ void cp16(uint32_t dst, const void* src) {
    asm volatile("cp.async.cg.shared.global [%0], [%1], 16;" :: "r"(dst), "l"(src));
}
#define CP_COMMIT() asm volatile("cp.async.commit_group;" ::: "memory")
#define CP_WAIT0()  asm volatile("cp.async.wait_group 0;" ::: "memory")
// tile rows are 256B (128 halves); XOR-swizzle 16B chunks within each 128B octant
__device__ __forceinline__ uint32_t sw_pair(int row, int c2) {   // c2 = half2 index 0..63
    return (uint32_t)row*256u + (uint32_t)(((c2 >> 2) ^ (row & 7)) << 4) + (uint32_t)((c2 & 3) << 2);
}
__device__ __forceinline__ uint32_t sw_chunk(int row, int cl) {  // cl = 16B chunk 0..15
    return (uint32_t)row*256u + (uint32_t)(((cl ^ (row & 7)) & 15) << 4);
}
__device__ __forceinline__ uint32_t add_lrelu2(uint32_t a, uint32_t d) {
    __half2 s = __hadd2(*(__half2*)&a, *(__half2*)&d);
    __half2 u = __hmax2(s, __hmul2(s, __float2half2_rn(SLOPE)));
    return *(uint32_t*)&u;
}
__device__ __forceinline__ uint32_t bn_lrelu2(uint32_t y, uint32_t a, uint32_t c) {
    __half2 u = __hfma2(*(__half2*)&a, *(__half2*)&y, *(__half2*)&c);
    __half2 r = __hmax2(u, __hmul2(u, __float2half2_rn(SLOPE)));
    return *(uint32_t*)&r;
}

// ---------------- k_prep: A/D factorization + absorbed zero/W-split ----------------
#define SW_PITCH 16900   /* 131*129=16899 rounded up so sI is 16B-aligned */
static const int SMEM_PREP = (SW_PITCH + 131*16) * 4;
__global__ void __launch_bounds__(128) k_prep(
        const float* __restrict__ pos1, const float* __restrict__ pos2,
        const float* __restrict__ f1,   const float* __restrict__ f2,
        const float* __restrict__ W0,
        const float* __restrict__ W1,   const float* __restrict__ W2) {
    extern __shared__ float sp[];
    float* sW = sp;               // [131][129]
    float* sI = sp + SW_PITCH;    // [131][16], 16B-aligned
    int blk = blockIdx.x;
    int b  = blk / (NN/16);
    int j0 = (blk % (NN/16)) * 16;
    int tid = threadIdx.x;

    if (blk == 0) {
        for (int j = tid; j < 1024; j += 128) {
            if (j < 256)      g_s0[j] = 0.f;
            else if (j < 512) g_s1[j - 256] = 0.f;
            else              g_s2[j - 512] = 0.f;
        }
    }
    if (blk < 96) {
        for (int t2 = tid; t2 < 256; t2 += 128) {
            int i = blk * 256 + t2;
            if (i < 8192) {
                float2 w = ((const float2*)W1)[i];
                __half2 h = __floats2half2_rn(w.x, w.y);
                g_W1h2[i] = *(uint32_t*)&h;
            } else if (i < 24576) {
                int j = i - 8192;
                float2 w = ((const float2*)W2)[j];
                __half2 h = __floats2half2_rn(w.x, w.y);
                g_W2h2[j] = *(uint32_t*)&h;
            }
        }
    }

    // ---- pass A ----
    for (int i = tid; i < 131*128; i += 128) {
        int o = i / 131, c = i - o*131;
        sW[c*129 + o] = W0[o*259 + c];
    }
    for (int i = tid; i < 131*16; i += 128) {
        int c = i >> 4, jl = i & 15;
        sI[c*16 + jl] = (c < 3) ? pos2[(b*3 + c)*NN + j0 + jl]
                                : f2[(b*128 + (c-3))*NN + j0 + jl];
    }
    __syncthreads();
    {
        float4 acc[4];
        #pragma unroll
        for (int q = 0; q < 4; q++) acc[q] = make_float4(0.f,0.f,0.f,0.f);
        for (int c = 0; c < 131; c++) {
            float wv = sW[c*129 + tid];
            const float4* r = (const float4*)&sI[c*16];
            #pragma unroll
            for (int q = 0; q < 4; q++) {
                float4 rv = r[q];
                acc[q].x = fmaf(wv, rv.x, acc[q].x);
                acc[q].y = fmaf(wv, rv.y, acc[q].y);
                acc[q].z = fmaf(wv, rv.z, acc[q].z);
                acc[q].w = fmaf(wv, rv.w, acc[q].w);
            }
        }
        const float* af = (const float*)acc;
        #pragma unroll
        for (int pt = 0; pt < 16; pt++)
            g_A[((b*NN + j0 + pt) << 7) + tid] = af[pt];
    }
    __syncthreads();

    // ---- pass D ----
    for (int i = tid; i < 131*128; i += 128) {
        int o = i / 131, c = i - o*131;
        int src = (c < 3) ? c : 128 + c;   // 131 + (c-3)
        sW[c*129 + o] = W0[o*259 + src];
    }
    for (int i = tid; i < 131*16; i += 128) {
        int c = i >> 4, jl = i & 15;
        sI[c*16 + jl] = (c < 3) ? -pos1[(b*3 + c)*NN + j0 + jl]
                                : f1[(b*128 + (c-3))*NN + j0 + jl];
    }
    __syncthreads();
    {
        float4 acc[4];
        #pragma unroll
        for (int q = 0; q < 4; q++) acc[q] = make_float4(0.f,0.f,0.f,0.f);
        for (int c = 0; c < 131; c++) {
            float wv = sW[c*129 + tid];
            const float4* r = (const float4*)&sI[c*16];
            #pragma unroll
            for (int q = 0; q < 4; q++) {
                float4 rv = r[q];
                acc[q].x = fmaf(wv, rv.x, acc[q].x);
                acc[q].y = fmaf(wv, rv.y, acc[q].y);
                acc[q].z = fmaf(wv, rv.z, acc[q].z);
                acc[q].w = fmaf(wv, rv.w, acc[q].w);
            }
        }
        const float* af = (const float*)acc;
        #pragma unroll
        for (int pt = 0; pt < 16; pt++)
            g_D[((b*NN + j0 + pt) << 7) + tid] = af[pt];
    }
}

// ---------------- k_stats0: stats of y0 = A[idx] + D ----------------
__global__ void __launch_bounds__(128) k_stats0(const int* __restrict__ idxp) {
    __shared__ int s_idx[128];
    int tid = threadIdx.x;
    int pbase = blockIdx.x * 128;
    s_idx[tid] = idxp[pbase + tid];
    __syncthreads();
    float s = 0.f, ss = 0.f;
    #pragma unroll 4
    for (int i = 0; i < 128; i++) {
        int p = pbase + i;
        int arow = ((p >> 16) * NN + s_idx[i]) << 7;
        int drow = (p >> 5) << 7;
        float y = g_A[arow + tid] + g_D[drow + tid];
        s += y; ss = fmaf(y, y, ss);
    }
    atomicAdd(&g_s0[tid], s);
    atomicAdd(&g_s0[L0 + tid], ss);
}

// ---------------- k_fold: A~ = a0*A (half2), D~ = a0*D + c0 (half2) ----------------
__global__ void __launch_bounds__(256) k_fold(
        const float* __restrict__ gam, const float* __restrict__ bet) {
    __shared__ float sA[128], sC[128];
    int tid = threadIdx.x;
    if (tid < 128) {
        const float inv = 1.0f / (float)PTOT;
        float mean = g_s0[tid] * inv;
        float var  = g_s0[128 + tid] * inv - mean * mean;
        float a = gam[tid] * rsqrtf(var + EPSV);
        sA[tid] = a; sC[tid] = bet[tid] - mean * a;
    }
    __syncthreads();
    int q = blockIdx.x * 256 + tid;
    int row = q >> 4, ch = q & 15;
    int c = ch << 3;
    const float4* a4 = (const float4*)(g_A + (row << 7) + c);
    const float4* d4 = (const float4*)(g_D + (row << 7) + c);
    float4 av0 = a4[0], av1 = a4[1], dv0 = d4[0], dv1 = d4[1];
    uint4 oa, od;
    {
        __half2 h;
        h = __floats2half2_rn(sA[c+0]*av0.x, sA[c+1]*av0.y); oa.x = *(uint32_t*)&h;
        h = __floats2half2_rn(sA[c+2]*av0.z, sA[c+3]*av0.w); oa.y = *(uint32_t*)&h;
        h = __floats2half2_rn(sA[c+4]*av1.x, sA[c+5]*av1.y); oa.z = *(uint32_t*)&h;
        h = __floats2half2_rn(sA[c+6]*av1.z, sA[c+7]*av1.w); oa.w = *(uint32_t*)&h;
        h = __floats2half2_rn(fmaf(sA[c+0],dv0.x,sC[c+0]), fmaf(sA[c+1],dv0.y,sC[c+1])); od.x = *(uint32_t*)&h;
        h = __floats2half2_rn(fmaf(sA[c+2],dv0.z,sC[c+2]), fmaf(sA[c+3],dv0.w,sC[c+3])); od.y = *(uint32_t*)&h;
        h = __floats2half2_rn(fmaf(sA[c+4],dv1.x,sC[c+4]), fmaf(sA[c+5],dv1.y,sC[c+5])); od.z = *(uint32_t*)&h;
        h = __floats2half2_rn(fmaf(sA[c+6],dv1.z,sC[c+6]), fmaf(sA[c+7],dv1.w,sC[c+7])); od.w = *(uint32_t*)&h;
    }
    *(uint4*)&g_Ah[(row << 6) + (ch << 2)] = oa;
    *(uint4*)&g_Dh[(row << 6) + (ch << 2)] = od;
}

// ======================= layer 1 =======================
// block: 4 tiles x (64 pts x 128 out); 256 thr / 8 warps; 3 CTAs/SM
// fill: U = lrelu(A~[idx] + D~) half2 uint4; epilogue: y1 -> swizzled g_y1s tiles
static const int L1_UH = 4096;                // 16384
static const int L1_WH = L1_UH + 16384;       // 32768
static const int SMEM_L1 = L1_WH + 32768;     // 53248

__global__ void __launch_bounds__(256, 3) k_l1(const int* __restrict__ idxp) {
    extern __shared__ char sm[];
    uint32_t sb = smem_u32(sm);
    int*   sAR  = (int*)(sm);            // 256 ints
    float* sSum = (float*)(sm + 1024);   // 128
    float* sSs  = (float*)(sm + 1536);   // 128
    int tid = threadIdx.x, wid = tid >> 5, lane = tid & 31;
    int pblk = blockIdx.x * 256;

    if (tid < 128) { sSum[tid] = 0.f; sSs[tid] = 0.f; }
    {
        int p = pblk + tid;
        sAR[tid] = ((p >> 16) * NN + idxp[p]) << 6;
    }
    __syncthreads();

    for (int i = tid; i < 8192; i += 256) {
        int o = i >> 6, c2 = i & 63;
        *(uint32_t*)(sm + L1_WH + sw_pair(o, c2)) = g_W1h2[i];
    }

    int mr = (wid & 3) * 16, nr = (wid >> 2) * 64;
    int aRow = lane & 15, aSel = lane >> 4;
    int bRow = (lane & 7) + ((lane >> 4) << 3), bSel = (lane >> 3) & 1;
    int fch = tid & 15, fpl = tid >> 4;

    #pragma unroll 1
    for (int t = 0; t < 4; t++) {
        int pbase = pblk + t * 64;
        if (t) __syncthreads();

        #pragma unroll
        for (int it = 0; it < 4; it++) {
            int pl = fpl + it * 16;
            uint4 av = *(const uint4*)&g_Ah[sAR[t*64 + pl] + (fch << 2)];
            uint4 dv = *(const uint4*)&g_Dh[(((pbase + pl) >> 5) << 6) + (fch << 2)];
            uint4 o;
            o.x = add_lrelu2(av.x, dv.x);
            o.y = add_lrelu2(av.y, dv.y);
            o.z = add_lrelu2(av.z, dv.z);
            o.w = add_lrelu2(av.w, dv.w);
            *(uint4*)(sm + L1_UH + sw_chunk(pl, fch)) = o;
        }
        __syncthreads();

        float acc[8][4];
        #pragma unroll
        for (int nt = 0; nt < 8; nt++)
            #pragma unroll
            for (int q = 0; q < 4; q++) acc[nt][q] = 0.f;

        for (int ks = 0; ks < 8; ks++) {
            uint32_t ah[4];
            int clA = 2*ks + aSel;
            ldmx4(ah, sb + L1_UH + sw_chunk(mr + aRow, clA));
            int clB = 2*ks + bSel;
            #pragma unroll
            for (int q = 0; q < 4; q++) {
                int n = nr + q*16 + bRow;
                uint32_t bh[4];
                ldmx4(bh, sb + L1_WH + sw_chunk(n, clB));
                mma16816(acc[2*q],     ah, bh);
                mma16816(acc[2*q + 1], ah, bh + 2);
            }
        }

        // ---- epilogue: y1 -> swizzled tile in g_y1s + channel sums ----
        {
            int r = mr + (lane >> 2);
            char* yb = g_y1s + ((size_t)(pbase >> 6)) * 16384;
            #pragma unroll
            for (int nt = 0; nt < 8; nt++) {
                int c2 = (nr >> 1) + nt*4 + (lane & 3);
                __half2 h0 = __floats2half2_rn(acc[nt][0], acc[nt][1]);
                __half2 h1 = __floats2half2_rn(acc[nt][2], acc[nt][3]);
                *(uint32_t*)(yb + sw_pair(r, c2))     = *(uint32_t*)&h0;
                *(uint32_t*)(yb + sw_pair(r + 8, c2)) = *(uint32_t*)&h1;
            }
        }
        #pragma unroll
        for (int nt = 0; nt < 8; nt++) {
            float s0 = acc[nt][0] + acc[nt][2];
            float s1 = acc[nt][1] + acc[nt][3];
            float q0 = acc[nt][0]*acc[nt][0] + acc[nt][2]*acc[nt][2];
            float q1 = acc[nt][1]*acc[nt][1] + acc[nt][3]*acc[nt][3];
            #pragma unroll
            for (int d = 4; d < 32; d <<= 1) {
                s0 += __shfl_xor_sync(0xFFFFFFFF, s0, d);
                s1 += __shfl_xor_sync(0xFFFFFFFF, s1, d);
                q0 += __shfl_xor_sync(0xFFFFFFFF, q0, d);
                q1 += __shfl_xor_sync(0xFFFFFFFF, q1, d);
            }
            if (lane < 4) {
                int c = nr + nt*8 + (lane << 1);
                atomicAdd(&sSum[c], s0);  atomicAdd(&sSum[c + 1], s1);
                atomicAdd(&sSs[c],  q0);  atomicAdd(&sSs[c + 1],  q1);
            }
        }
    }
    __syncthreads();
    if (tid < 128) {
        atomicAdd(&g_s1[tid],       sSum[tid]);
        atomicAdd(&g_s1[128 + tid], sSs[tid]);
    }
}

// ======================= layer 2 =======================
// block: 4 tiles x (64 pts x 128 out-half); 256 thr / 8 warps; 3 CTAs/SM
// fill: double-buffered cp.async of pre-swizzled y1 tiles; BN1+lrelu on fragments
static const int L2_U0 = 4096;
static const int L2_U1 = L2_U0 + 16384;       // 20480
static const int L2_WH = L2_U1 + 16384;       // 36864
static const int SMEM_L2 = L2_WH + 32768;     // 69632

__global__ void __launch_bounds__(256, 3) k_l2(
        const float* __restrict__ gam, const float* __restrict__ bet) {
    extern __shared__ char sm[];
    uint32_t sb = smem_u32(sm);
    uint2* sAC  = (uint2*)(sm);          // 64 x {a half2, c half2}
    float* sSum = (float*)(sm + 512);    // 128
    float* sSs  = (float*)(sm + 1024);   // 128
    int tid = threadIdx.x, wid = tid >> 5, lane = tid & 31;
    int tb = (blockIdx.x >> 1) * 4;      // tile base (64-pt tiles)
    int nh = (blockIdx.x & 1) * 128;

    if (tid < 128) { sSum[tid] = 0.f; sSs[tid] = 0.f; }
    if (tid < 64) {
        const float inv = 1.0f / (float)PTOT;
        int ce = tid << 1;
        float m0 = g_s1[ce] * inv;
        float v0 = g_s1[128 + ce] * inv - m0 * m0;
        float a0 = gam[ce] * rsqrtf(v0 + EPSV);
        float c0 = bet[ce] - m0 * a0;
        float m1 = g_s1[ce + 1] * inv;
        float v1 = g_s1[128 + ce + 1] * inv - m1 * m1;
        float a1 = gam[ce + 1] * rsqrtf(v1 + EPSV);
        float c1 = bet[ce + 1] - m1 * a1;
        __half2 ha = __floats2half2_rn(a0, a1);
        __half2 hc = __floats2half2_rn(c0, c1);
        sAC[tid] = make_uint2(*(uint32_t*)&ha, *(uint32_t*)&hc);
    }

    // prologue: async-copy tile tb into U0
    {
        uint32_t dst = sb + L2_U0 + tid * 16;
        const char* src = g_y1s + (size_t)tb * 16384 + tid * 16;
        #pragma unroll
        for (int k2 = 0; k2 < 4; k2++) cp16(dst + k2*4096, src + k2*4096);
        CP_COMMIT();
    }
    // W tile: rows nh..nh+127 of W2 (overlaps with async copy)
    for (int i = tid; i < 8192; i += 256) {
        int o = i >> 6, c2 = i & 63;
        *(uint32_t*)(sm + L2_WH + sw_pair(o, c2)) = g_W2h2[(nh + o)*64 + c2];
    }
    __syncthreads();

    int mr = (wid & 1) * 32, nr = (wid >> 1) * 32;
    int aRow = lane & 15, aSel = lane >> 4;
    int bRow = (lane & 7) + ((lane >> 4) << 3), bSel = (lane >> 3) & 1;

    #pragma unroll 1
    for (int t = 0; t < 4; t++) {
        CP_WAIT0();
        __syncthreads();
        if (t < 3) {   // prefetch next tile into the other buffer
            uint32_t dst = sb + (((t + 1) & 1) ? L2_U1 : L2_U0) + tid * 16;
            const char* src = g_y1s + (size_t)(tb + t + 1) * 16384 + tid * 16;
            #pragma unroll
            for (int k2 = 0; k2 < 4; k2++) cp16(dst + k2*4096, src + k2*4096);
            CP_COMMIT();
        }
        uint32_t Ub = sb + ((t & 1) ? L2_U1 : L2_U0);

        float acc[2][4][4];
        #pragma unroll
        for (int mt = 0; mt < 2; mt++)
            #pragma unroll
            for (int nt = 0; nt < 4; nt++)
                #pragma unroll
                for (int q = 0; q < 4; q++) acc[mt][nt][q] = 0.f;

        for (int ks = 0; ks < 8; ks++) {
            uint2 ac0 = sAC[8*ks + (lane & 3)];
            uint2 ac1 = sAC[8*ks + (lane & 3) + 4];
            uint32_t ah[2][4];
            int clA = 2*ks + aSel;
            #pragma unroll
            for (int mt = 0; mt < 2; mt++) {
                ldmx4(ah[mt], Ub + sw_chunk(mr + mt*16 + aRow, clA));
                ah[mt][0] = bn_lrelu2(ah[mt][0], ac0.x, ac0.y);
                ah[mt][1] = bn_lrelu2(ah[mt][1], ac0.x, ac0.y);
                ah[mt][2] = bn_lrelu2(ah[mt][2], ac1.x, ac1.y);
                ah[mt][3] = bn_lrelu2(ah[mt][3], ac1.x, ac1.y);
            }
            int clB = 2*ks + bSel;
            #pragma unroll
            for (int q = 0; q < 2; q++) {
                int n = nr + q*16 + bRow;
                uint32_t bh[4];
                ldmx4(bh, sb + L2_WH + sw_chunk(n, clB));
                #pragma unroll
                for (int mt = 0; mt < 2; mt++) {
                    mma16816(acc[mt][2*q],     ah[mt], bh);
                    mma16816(acc[mt][2*q + 1], ah[mt], bh + 2);
                }
            }
        }

        // ---- register epilogue: warp owns one K-group (32 pts) x 32 ch ----
        int pbase = (tb + t) * 64;
        int bn = (pbase >> 5) + (wid & 1);
        #pragma unroll
        for (int nt = 0; nt < 4; nt++) {
            float mx0 = fmaxf(fmaxf(acc[0][nt][0], acc[0][nt][2]),
                              fmaxf(acc[1][nt][0], acc[1][nt][2]));
            float mx1 = fmaxf(fmaxf(acc[0][nt][1], acc[0][nt][3]),
                              fmaxf(acc[1][nt][1], acc[1][nt][3]));
            float mn0 = fminf(fminf(acc[0][nt][0], acc[0][nt][2]),
                              fminf(acc[1][nt][0], acc[1][nt][2]));
            float mn1 = fminf(fminf(acc[0][nt][1], acc[0][nt][3]),
                              fminf(acc[1][nt][1], acc[1][nt][3]));
            float s0 = acc[0][nt][0] + acc[0][nt][2] + acc[1][nt][0] + acc[1][nt][2];
            float s1 = acc[0][nt][1] + acc[0][nt][3] + acc[1][nt][1] + acc[1][nt][3];
            float q0 = acc[0][nt][0]*acc[0][nt][0] + acc[0][nt][2]*acc[0][nt][2]
                     + acc[1][nt][0]*acc[1][nt][0] + acc[1][nt][2]*acc[1][nt][2];
            float q1 = acc[0][nt][1]*acc[0][nt][1] + acc[0][nt][3]*acc[0][nt][3]
                     + acc[1][nt][1]*acc[1][nt][1] + acc[1][nt][3]*acc[1][nt][3];
            #pragma unroll
            for (int d = 4; d < 32; d <<= 1) {
                mx0 = fmaxf(mx0, __shfl_xor_sync(0xFFFFFFFF, mx0, d));
                mx1 = fmaxf(mx1, __shfl_xor_sync(0xFFFFFFFF, mx1, d));
                mn0 = fminf(mn0, __shfl_xor_sync(0xFFFFFFFF, mn0, d));
                mn1 = fminf(mn1, __shfl_xor_sync(0xFFFFFFFF, mn1, d));
                s0 += __shfl_xor_sync(0xFFFFFFFF, s0, d);
                s1 += __shfl_xor_sync(0xFFFFFFFF, s1, d);
                q0 += __shfl_xor_sync(0xFFFFFFFF, q0, d);
                q1 += __shfl_xor_sync(0xFFFFFFFF, q1, d);
            }
            if (lane < 4) {
                int cl = nr + nt*8 + (lane << 1);
                int c  = nh + cl;
                *(float2*)&g_mx[bn*256 + c] = make_float2(mx0, mx1);
                *(float2*)&g_mn[bn*256 + c] = make_float2(mn0, mn1);
                atomicAdd(&sSum[cl], s0);  atomicAdd(&sSum[cl + 1], s1);
                atomicAdd(&sSs[cl],  q0);  atomicAdd(&sSs[cl + 1],  q1);
            }
        }
    }
    __syncthreads();
    if (tid < 128) {
        atomicAdd(&g_s2[nh + tid],       sSum[tid]);
        atomicAdd(&g_s2[256 + nh + tid], sSs[tid]);
    }
}

// ---------------- k_out ----------------
static const int SMEM_OUT = 2 * 64 * 257 * 4;
__global__ void __launch_bounds__(256) k_out(float* __restrict__ out,
        const float* __restrict__ gam, const float* __restrict__ bet) {
    extern __shared__ float smf[];
    float* sMx = smf;
    float* sMn = smf + 64*257;
    __shared__ float sA2[256], sC2[256];
    int tid = threadIdx.x;
    {
        const float inv = 1.0f / (float)PTOT;
        float mean = g_s2[tid] * inv;
        float var  = g_s2[256 + tid] * inv - mean * mean;
        float a = gam[tid] * rsqrtf(var + EPSV);
        sA2[tid] = a; sC2[tid] = bet[tid] - mean * a;
    }
    int b  = blockIdx.x >> 5;
    int n0 = (blockIdx.x & 31) * 64;
    for (int i = tid; i < 64*256; i += 256) {
        int nl = i >> 8, o = i & 255;
        int g = (b*NN + n0 + nl)*256 + o;
        sMx[nl*257 + o] = g_mx[g];
        sMn[nl*257 + o] = g_mn[g];
    }
    __syncthreads();
    for (int i = tid; i < 64*256; i += 256) {
        int o = i >> 6, nl = i & 63;
        float a = sA2[o], c = sC2[o];
        float z = (a >= 0.f) ? sMx[nl*257 + o] : sMn[nl*257 + o];
        float y = fmaf(a, z, c);
        out[(b*256 + o)*NN + n0 + nl] = (y > 0.f) ? y : SLOPE * y;
    }
}

// ---------------- launch ----------------
extern "C" void kernel_launch(void* const* d_in, const int* in_sizes, int n_in,
                              void* d_out, int out_size) {
    const float* pos1 = (const float*)d_in[0];
    const float* pos2 = (const float*)d_in[1];
    const float* f1   = (const float*)d_in[2];
    const float* f2   = (const float*)d_in[3];
    const int*   idxp = (const int*)d_in[4];
    const float* W0 = (const float*)d_in[5];
    const float* g0 = (const float*)d_in[6];
    const float* b0 = (const float*)d_in[7];
    const float* W1 = (const float*)d_in[8];
    const float* g1 = (const float*)d_in[9];
    const float* b1 = (const float*)d_in[10];
    const float* W2 = (const float*)d_in[11];
    const float* g2 = (const float*)d_in[12];
    const float* b2 = (const float*)d_in[13];

    cudaFuncSetAttribute(k_prep, cudaFuncAttributeMaxDynamicSharedMemorySize, SMEM_PREP);
    cudaFuncSetAttribute(k_l1,   cudaFuncAttributeMaxDynamicSharedMemorySize, SMEM_L1);
    cudaFuncSetAttribute(k_l2,   cudaFuncAttributeMaxDynamicSharedMemorySize, SMEM_L2);
    cudaFuncSetAttribute(k_out,  cudaFuncAttributeMaxDynamicSharedMemorySize, SMEM_OUT);

    float* outp = (float*)d_out;
    int featOff = out_size - BB*L2C*NN;
    if (featOff < 0) featOff = 0;

    k_prep<<<BB*(NN/16), 128, SMEM_PREP>>>(pos1, pos2, f1, f2, W0, W1, W2); // 0
    k_stats0<<<PTOT/128, 128>>>(idxp);                               // 1
    k_fold<<<512, 256>>>(g0, b0);                                    // 2
    k_l1<<<PTOT/256, 256, SMEM_L1>>>(idxp);                          // 3 (profiled)
    k_l2<<<2*(PTOT/256), 256, SMEM_L2>>>(g1, b1);                    // 4
    if (featOff > 0)
        cudaMemcpyAsync(d_out, pos1, (size_t)featOff * sizeof(float),
                        cudaMemcpyDeviceToDevice, 0);
    k_out<<<BB*(NN/64), 256, SMEM_OUT>>>(outp + featOff, g2, b2);    // 5
}